// round 5
// baseline (speedup 1.0000x reference)
#include <cuda_runtime.h>
#include <math.h>

#define NN   50000
#define EE   800000
#define DIN_ 32
#define DL_  128
#define DOUT_ 10
#define GG   256
#define KK   3

// ---------------- scratch (device globals) ----------------
__device__ __align__(16) float g_h  [NN * DL_];
__device__ __align__(16) float g_u  [NN * DL_];
__device__ __align__(16) float g_g  [NN * DL_];
__device__ __align__(16) float g_t  [NN * DL_];
__device__ __align__(16) float g_dec1[NN * 256];
__device__ __align__(16) float g_dinv[NN];
__device__ __align__(16) int   g_deg [NN];
__device__ __align__(16) int   g_off [NN + 1];
__device__ __align__(16) int   g_cur [NN];
__device__ __align__(16) int   g_csr [EE];
__device__ __align__(16) float g_sums[GG * DOUT_];
__device__ __align__(16) float g_cnt [GG];

// ---------------- packed f32x2 helpers ----------------
#define PACKDUP(out, v) \
    asm("mov.b64 %0, {%1, %1};" : "=l"(out) : "r"(__float_as_uint(v)))
#define UNPACK2(lo, hi, in) \
    do { unsigned _ulo, _uhi; \
         asm("mov.b64 {%0, %1}, %2;" : "=r"(_ulo), "=r"(_uhi) : "l"(in)); \
         lo = __uint_as_float(_ulo); hi = __uint_as_float(_uhi); } while (0)
#define FMA2(d, a, b) \
    asm("fma.rn.f32x2 %0, %1, %2, %0;" : "+l"(d) : "l"(a), "l"(b))

#define CP_ASYNC16(dst_u32, src) \
    asm volatile("cp.async.ca.shared.global [%0], [%1], 16;" :: "r"(dst_u32), "l"(src))
#define CP_COMMIT() asm volatile("cp.async.commit_group;")
#define CP_WAIT0()  asm volatile("cp.async.wait_group 0;")

// ---------------- one-time graph preprocessing ----------------
__global__ void count_deg_kernel(const int* __restrict__ dst, int* __restrict__ deg, int E) {
    int i = blockIdx.x * blockDim.x + threadIdx.x;
    if (i < E) atomicAdd(&deg[dst[i]], 1);
}

__global__ void count_nodes_kernel(const int* __restrict__ batch, float* __restrict__ cnt, int M) {
    int i = blockIdx.x * blockDim.x + threadIdx.x;
    if (i < M) atomicAdd(&cnt[batch[i]], 1.0f);
}

// single-block exclusive prefix scan over deg -> off (+cursor copy, +dinv fused)
__global__ __launch_bounds__(1024)
void scan_offsets_kernel(const int* __restrict__ deg, int* __restrict__ off,
                         int* __restrict__ cursor, float* __restrict__ dinv, int M) {
    __shared__ int part[1024];
    int t = threadIdx.x;
    int chunk = (M + 1023) >> 10;
    int base = t * chunk;
    int s = 0;
    for (int i = 0; i < chunk; i++) { int j = base + i; if (j < M) s += deg[j]; }
    part[t] = s;
    __syncthreads();
    for (int d = 1; d < 1024; d <<= 1) {
        int add = (t >= d) ? part[t - d] : 0;
        __syncthreads();
        part[t] += add;
        __syncthreads();
    }
    int excl = part[t] - s;
    int run = excl;
    for (int i = 0; i < chunk; i++) {
        int j = base + i;
        if (j < M) {
            int dj = deg[j];
            off[j] = run; cursor[j] = run; run += dj;
            dinv[j] = rsqrtf((float)dj + 1.0f);
        }
    }
    if (t == 1023) off[M] = part[1023];
}

__global__ void csr_fill_kernel(const int* __restrict__ src, const int* __restrict__ dst,
                                int* __restrict__ cursor, int* __restrict__ csr, int E) {
    int i = blockIdx.x * blockDim.x + threadIdx.x;
    if (i < E) {
        int p = atomicAdd(&cursor[dst[i]], 1);
        csr[p] = src[i];
    }
}

// ---------------- per-hop neighbor gather ----------------
__global__ __launch_bounds__(256)
void gather_kernel(const int* __restrict__ off, const int* __restrict__ csr,
                   const float* __restrict__ u, const float* __restrict__ dinv,
                   const float* __restrict__ bgcn, float* __restrict__ g, int M) {
    int n = (blockIdx.x * blockDim.x + threadIdx.x) >> 5;
    if (n >= M) return;
    int lane = threadIdx.x & 31;
    int e0 = off[n], e1 = off[n + 1];
    int deg = e1 - e0;

    float4 acc = __ldg((const float4*)(u + (size_t)n * DL_ + lane * 4));

    for (int base = 0; base < deg; base += 32) {
        int cnt = min(32, deg - base);
        int idx = 0;
        if (base + lane < deg) idx = __ldg(csr + e0 + base + lane);
        int j = 0;
        for (; j + 8 <= cnt; j += 8) {
            float4 v[8];
#pragma unroll
            for (int q = 0; q < 8; q++) {
                int s = __shfl_sync(0xffffffffu, idx, j + q);
                v[q] = __ldg((const float4*)(u + (size_t)s * DL_ + lane * 4));
            }
#pragma unroll
            for (int q = 0; q < 8; q++) {
                acc.x += v[q].x; acc.y += v[q].y; acc.z += v[q].z; acc.w += v[q].w;
            }
        }
        if (j + 4 <= cnt) {
            float4 v[4];
#pragma unroll
            for (int q = 0; q < 4; q++) {
                int s = __shfl_sync(0xffffffffu, idx, j + q);
                v[q] = __ldg((const float4*)(u + (size_t)s * DL_ + lane * 4));
            }
#pragma unroll
            for (int q = 0; q < 4; q++) {
                acc.x += v[q].x; acc.y += v[q].y; acc.z += v[q].z; acc.w += v[q].w;
            }
            j += 4;
        }
        for (; j < cnt; j++) {
            int s = __shfl_sync(0xffffffffu, idx, j);
            float4 v = __ldg((const float4*)(u + (size_t)s * DL_ + lane * 4));
            acc.x += v.x; acc.y += v.y; acc.z += v.z; acc.w += v.w;
        }
    }

    float dv = dinv[n];
    float4 b = *(const float4*)(bgcn + lane * 4);
    float4 o;
    o.x = fmaf(dv, acc.x, b.x);
    o.y = fmaf(dv, acc.y, b.y);
    o.z = fmaf(dv, acc.z, b.z);
    o.w = fmaf(dv, acc.w, b.w);
    *(float4*)(g + (size_t)n * DL_ + lane * 4) = o;
}

// ---------------- packed-f32x2 SGEMM with pre-packed smem + cp.async B staging ----
// C = act(A[M,K] @ B[K,Nc] + bias) * rowscale
// act: 0=none, 1=sigmoid, 2=relu, 3=softplus(v-5),
//      4=softplus(v-5) -> C (=std), and H = MU + C*EPS (fused reparam)
__global__ __launch_bounds__(128, 5)
void gemm_f32x2(const float* __restrict__ A, const float* __restrict__ B,
                const float* __restrict__ bias, const float* __restrict__ rowscale,
                float* __restrict__ C, int M, int K, int Nc, int act,
                const float* __restrict__ MU, const float* __restrict__ EPS,
                float* __restrict__ H) {
    // As2: A values duplicated into {a,a} pairs.  Bs2: natural float pairs.
    __shared__ unsigned long long As2[2][8][64];
    __shared__ unsigned long long Bs2[2][8][64];
    const int tid  = threadIdx.x;
    const int tx   = tid & 15;
    const int ty   = tid >> 4;
    const int brow = blockIdx.x * 64;
    const int bcol = blockIdx.y * 128;

    const int arow = tid >> 1;          // 0..63
    const int acol = (tid & 1) * 4;     // 0 or 4
    const int bkr  = tid >> 4;          // 0..7
    const int bc   = (tid & 15) * 8;    // float col 0..120

    unsigned long long acc2[8][4];
#pragma unroll
    for (int i = 0; i < 8; i++)
#pragma unroll
        for (int j = 0; j < 4; j++) acc2[i][j] = 0ULL;

    const int nk = K >> 3;
    const int gr = brow + arow;
    const float* Brow = B + (size_t)bkr * Nc + bcol + bc;   // advances by 8*Nc per tile

    unsigned bdst0 = (unsigned)__cvta_generic_to_shared(
        (float*)&Bs2[0][bkr][0] + bc);
    unsigned bdst1 = (unsigned)__cvta_generic_to_shared(
        (float*)&Bs2[1][bkr][0] + bc);

    // preload tile 0
    {
        CP_ASYNC16(bdst0,      Brow);
        CP_ASYNC16(bdst0 + 16, Brow + 4);
        CP_COMMIT();
        float4 av = make_float4(0.f, 0.f, 0.f, 0.f);
        if (gr < M) av = *(const float4*)(A + (size_t)gr * K + acol);
        PACKDUP(As2[0][acol + 0][arow], av.x);
        PACKDUP(As2[0][acol + 1][arow], av.y);
        PACKDUP(As2[0][acol + 2][arow], av.z);
        PACKDUP(As2[0][acol + 3][arow], av.w);
        CP_WAIT0();
    }
    __syncthreads();

    for (int it = 0; it < nk; ++it) {
        const int buf = it & 1;
        const bool more = (it + 1) < nk;
        float4 nav = make_float4(0.f, 0.f, 0.f, 0.f);
        if (more) {
            int k0 = (it + 1) * 8;
            unsigned bdst = (buf ? bdst0 : bdst1);
            const float* bsrc = Brow + (size_t)k0 * Nc;
            CP_ASYNC16(bdst,      bsrc);
            CP_ASYNC16(bdst + 16, bsrc + 4);
            CP_COMMIT();
            if (gr < M) nav = *(const float4*)(A + (size_t)gr * K + k0 + acol);
        }
#pragma unroll
        for (int kk = 0; kk < 8; ++kk) {
            ulonglong2 b01 = *(const ulonglong2*)&Bs2[buf][kk][tx * 4];
            ulonglong2 b23 = *(const ulonglong2*)&Bs2[buf][kk][tx * 4 + 2];
            ulonglong2 a01 = *(const ulonglong2*)&As2[buf][kk][ty * 8];
            ulonglong2 a23 = *(const ulonglong2*)&As2[buf][kk][ty * 8 + 2];
            FMA2(acc2[0][0], a01.x, b01.x); FMA2(acc2[0][1], a01.x, b01.y);
            FMA2(acc2[0][2], a01.x, b23.x); FMA2(acc2[0][3], a01.x, b23.y);
            FMA2(acc2[1][0], a01.y, b01.x); FMA2(acc2[1][1], a01.y, b01.y);
            FMA2(acc2[1][2], a01.y, b23.x); FMA2(acc2[1][3], a01.y, b23.y);
            FMA2(acc2[2][0], a23.x, b01.x); FMA2(acc2[2][1], a23.x, b01.y);
            FMA2(acc2[2][2], a23.x, b23.x); FMA2(acc2[2][3], a23.x, b23.y);
            FMA2(acc2[3][0], a23.y, b01.x); FMA2(acc2[3][1], a23.y, b01.y);
            FMA2(acc2[3][2], a23.y, b23.x); FMA2(acc2[3][3], a23.y, b23.y);
            ulonglong2 a45 = *(const ulonglong2*)&As2[buf][kk][ty * 8 + 4];
            ulonglong2 a67 = *(const ulonglong2*)&As2[buf][kk][ty * 8 + 6];
            FMA2(acc2[4][0], a45.x, b01.x); FMA2(acc2[4][1], a45.x, b01.y);
            FMA2(acc2[4][2], a45.x, b23.x); FMA2(acc2[4][3], a45.x, b23.y);
            FMA2(acc2[5][0], a45.y, b01.x); FMA2(acc2[5][1], a45.y, b01.y);
            FMA2(acc2[5][2], a45.y, b23.x); FMA2(acc2[5][3], a45.y, b23.y);
            FMA2(acc2[6][0], a67.x, b01.x); FMA2(acc2[6][1], a67.x, b01.y);
            FMA2(acc2[6][2], a67.x, b23.x); FMA2(acc2[6][3], a67.x, b23.y);
            FMA2(acc2[7][0], a67.y, b01.x); FMA2(acc2[7][1], a67.y, b01.y);
            FMA2(acc2[7][2], a67.y, b23.x); FMA2(acc2[7][3], a67.y, b23.y);
        }
        if (more) {
            const int nb = buf ^ 1;
            PACKDUP(As2[nb][acol + 0][arow], nav.x);
            PACKDUP(As2[nb][acol + 1][arow], nav.y);
            PACKDUP(As2[nb][acol + 2][arow], nav.z);
            PACKDUP(As2[nb][acol + 3][arow], nav.w);
            CP_WAIT0();
        }
        __syncthreads();
    }

#pragma unroll
    for (int i = 0; i < 8; i++) {
        int row = brow + ty * 8 + i;
        if (row >= M) continue;
        float rs = rowscale ? rowscale[row] : 1.0f;
#pragma unroll
        for (int jp = 0; jp < 4; jp++) {
            float v0, v1;
            UNPACK2(v0, v1, acc2[i][jp]);
            int col = bcol + tx * 8 + jp * 2;
            size_t idx = (size_t)row * Nc + col;
            if (bias) { v0 += bias[col]; v1 += bias[col + 1]; }
            if (act == 1) {
                v0 = __fdividef(1.0f, 1.0f + __expf(-v0));
                v1 = __fdividef(1.0f, 1.0f + __expf(-v1));
            } else if (act == 2) {
                v0 = fmaxf(v0, 0.0f);
                v1 = fmaxf(v1, 0.0f);
            } else if (act >= 3) {
                v0 -= 5.0f; v0 = (v0 > 20.0f) ? v0 : log1pf(expf(v0));
                v1 -= 5.0f; v1 = (v1 > 20.0f) ? v1 : log1pf(expf(v1));
            }
            float2 o; o.x = v0 * rs; o.y = v1 * rs;
            *(float2*)(C + idx) = o;
            if (act == 4) {
                float2 m = *(const float2*)(MU + idx);
                float2 e = *(const float2*)(EPS + idx);
                float2 hh;
                hh.x = fmaf(o.x, e.x, m.x);
                hh.y = fmaf(o.y, e.y, m.y);
                *(float2*)(H + idx) = hh;
            }
        }
    }
}

// ---------------- fused decoder tail ----------------
__global__ __launch_bounds__(128)
void decoder_tail_kernel(const float* __restrict__ din,
                         const float* __restrict__ W2, const float* __restrict__ b2,
                         const float* __restrict__ W3, const float* __restrict__ b3,
                         const float* __restrict__ W4, const float* __restrict__ b4,
                         const float* __restrict__ Wo, const float* __restrict__ bo,
                         const int* __restrict__ batch, float* __restrict__ sums, int M) {
    __shared__ float w2[128 * 64];
    __shared__ float w3[64 * 32];
    __shared__ float w4[32 * 16];
    __shared__ float wo[160];
    __shared__ float xs [4][128];
    __shared__ float t64[4][64];
    __shared__ float t32[4][32];
    __shared__ float t16[4][16];
    for (int i = threadIdx.x; i < 128 * 64; i += 128) w2[i] = W2[i];
    for (int i = threadIdx.x; i < 64 * 32;  i += 128) w3[i] = W3[i];
    for (int i = threadIdx.x; i < 32 * 16;  i += 128) w4[i] = W4[i];
    for (int i = threadIdx.x; i < 160;      i += 128) wo[i] = Wo[i];
    __syncthreads();

    int warp = threadIdx.x >> 5;
    int lane = threadIdx.x & 31;
    int stride = gridDim.x * 4;

    for (int row = blockIdx.x * 4 + warp; row < M; row += stride) {
        *(float4*)&xs[warp][lane * 4] = *(const float4*)(din + (size_t)row * 128 + lane * 4);
        __syncwarp();
        float s0 = b2[lane], s1 = b2[lane + 32];
#pragma unroll 8
        for (int k = 0; k < 128; k++) {
            float xv = xs[warp][k];
            s0 = fmaf(xv, w2[k * 64 + lane],      s0);
            s1 = fmaf(xv, w2[k * 64 + lane + 32], s1);
        }
        t64[warp][lane]      = fmaxf(s0, 0.0f);
        t64[warp][lane + 32] = fmaxf(s1, 0.0f);
        __syncwarp();
        float s = b3[lane];
#pragma unroll 8
        for (int k = 0; k < 64; k++) s = fmaf(t64[warp][k], w3[k * 32 + lane], s);
        t32[warp][lane] = fmaxf(s, 0.0f);
        __syncwarp();
        if (lane < 16) {
            float t = b4[lane];
#pragma unroll
            for (int k = 0; k < 32; k++) t = fmaf(t32[warp][k], w4[k * 16 + lane], t);
            t16[warp][lane] = fmaxf(t, 0.0f);
        }
        __syncwarp();
        if (lane < 10) {
            float t = bo[lane];
#pragma unroll
            for (int k = 0; k < 16; k++) t = fmaf(t16[warp][k], wo[k * 10 + lane], t);
            float yp = __fdividef(1.0f, 1.0f + __expf(-t));
            atomicAdd(&sums[batch[row] * 10 + lane], yp);
        }
        __syncwarp();
    }
}

__global__ void pool_finalize_kernel(const float* __restrict__ sums, const float* __restrict__ cnt,
                                     const float* __restrict__ y,
                                     float* __restrict__ out_pred, float* __restrict__ out_y) {
    int i = blockIdx.x * blockDim.x + threadIdx.x;
    if (i < GG * DOUT_) {
        out_pred[i] = sums[i] / fmaxf(cnt[i / DOUT_], 1.0f);
        out_y[i]    = y[i];
    }
}

// ---------------- launch ----------------
extern "C" void kernel_launch(void* const* d_in, const int* in_sizes, int n_in,
                              void* d_out, int out_size) {
    const float* x     = (const float*)d_in[0];
    const int*   ei    = (const int*)  d_in[1];
    const int*   batch = (const int*)  d_in[2];
    const float* y     = (const float*)d_in[3];
    const float* eps   = (const float*)d_in[4];
    const float* W_in  = (const float*)d_in[5];
    const float* b_in  = (const float*)d_in[6];
    const float* W_gcn = (const float*)d_in[7];
    const float* b_gcn = (const float*)d_in[8];
    const float* W_enc = (const float*)d_in[9];
    const float* b_enc = (const float*)d_in[10];
    const float* W_mu  = (const float*)d_in[11];
    const float* b_mu  = (const float*)d_in[12];
    const float* W_std = (const float*)d_in[13];
    const float* b_std = (const float*)d_in[14];
    const float* Wd0 = (const float*)d_in[15]; const float* bd0 = (const float*)d_in[16];
    const float* Wd1 = (const float*)d_in[17]; const float* bd1 = (const float*)d_in[18];
    const float* Wd2 = (const float*)d_in[19]; const float* bd2 = (const float*)d_in[20];
    const float* Wd3 = (const float*)d_in[21]; const float* bd3 = (const float*)d_in[22];
    const float* Wd4 = (const float*)d_in[23]; const float* bd4 = (const float*)d_in[24];
    const float* Wo  = (const float*)d_in[25]; const float* bo  = (const float*)d_in[26];

    float *h, *u, *gbuf, *tbuf, *dec1, *dinv, *sums, *cnt;
    int *deg, *off, *cur, *csr;
    cudaGetSymbolAddress((void**)&h,    g_h);
    cudaGetSymbolAddress((void**)&u,    g_u);
    cudaGetSymbolAddress((void**)&gbuf, g_g);
    cudaGetSymbolAddress((void**)&tbuf, g_t);
    cudaGetSymbolAddress((void**)&dec1, g_dec1);
    cudaGetSymbolAddress((void**)&dinv, g_dinv);
    cudaGetSymbolAddress((void**)&deg,  g_deg);
    cudaGetSymbolAddress((void**)&off,  g_off);
    cudaGetSymbolAddress((void**)&cur,  g_cur);
    cudaGetSymbolAddress((void**)&csr,  g_csr);
    cudaGetSymbolAddress((void**)&sums, g_sums);
    cudaGetSymbolAddress((void**)&cnt,  g_cnt);

    float* out      = (float*)d_out;
    float* out_pred = out;
    float* out_mu   = out + GG * DOUT_;
    float* out_std  = out + GG * DOUT_ + (size_t)NN * DL_;
    float* out_y    = out + GG * DOUT_ + (size_t)2 * NN * DL_;

    const int* src = ei;
    const int* dst = ei + EE;

    // graph preprocessing (ordered so the fixed ncu capture slot lands on a
    // K=128 GEMM or the gather, not a prep kernel)
    cudaMemsetAsync(deg, 0, NN * sizeof(int));
    count_deg_kernel   <<<(EE + 255) / 256, 256>>>(dst, deg, EE);
    scan_offsets_kernel<<<1, 1024>>>(deg, off, cur, dinv, NN);
    csr_fill_kernel    <<<(EE + 255) / 256, 256>>>(src, dst, cur, csr, EE);

    dim3 g64((NN + 63) / 64, 1);
    gemm_f32x2<<<g64, 128>>>(x, W_in, b_in, nullptr, h, NN, DIN_, DL_, 1,
                             nullptr, nullptr, nullptr);

    for (int it = 0; it < KK; it++) {
        gemm_f32x2<<<g64, 128>>>(h, W_gcn, nullptr, dinv, u, NN, DL_, DL_, 0,
                                 nullptr, nullptr, nullptr);
        gather_kernel<<<(NN * 32 + 255) / 256, 256>>>(off, csr, u, dinv, b_gcn, gbuf, NN);

        const float* curp = gbuf;
        float* nxt = tbuf;
        for (int j = 0; j < 5; j++) {
            gemm_f32x2<<<g64, 128>>>(curp, W_enc + (size_t)j * DL_ * DL_, b_enc + j * DL_,
                                     nullptr, nxt, NN, DL_, DL_, 1,
                                     nullptr, nullptr, nullptr);
            float* tmp = (float*)curp; curp = nxt; nxt = tmp;
        }
        gemm_f32x2<<<g64, 128>>>(curp, W_mu,  b_mu,  nullptr, out_mu,  NN, DL_, DL_, 0,
                                 nullptr, nullptr, nullptr);
        gemm_f32x2<<<g64, 128>>>(curp, W_std, b_std, nullptr, out_std, NN, DL_, DL_, 4,
                                 out_mu, eps + (size_t)it * NN * DL_, h);
    }

    // decoder
    dim3 gd0((NN + 63) / 64, 2);
    gemm_f32x2<<<gd0, 128>>>(h, Wd0, bd0, nullptr, dec1, NN, DL_, 256, 2,
                             nullptr, nullptr, nullptr);
    gemm_f32x2<<<g64, 128>>>(dec1, Wd1, bd1, nullptr, u, NN, 256, DL_, 2,
                             nullptr, nullptr, nullptr);

    // pooling prep placed late (independent of the hop pipeline)
    cudaMemsetAsync(sums, 0, GG * DOUT_ * sizeof(float));
    cudaMemsetAsync(cnt,  0, GG * sizeof(float));
    count_nodes_kernel<<<(NN + 255) / 256, 256>>>(batch, cnt, NN);
    decoder_tail_kernel<<<592, 128>>>(u, Wd2, bd2, Wd3, bd3, Wd4, bd4, Wo, bo,
                                      batch, sums, NN);
    pool_finalize_kernel<<<(GG * DOUT_ + 255) / 256, 256>>>(sums, cnt, y, out_pred, out_y);

    (void)in_sizes; (void)n_in; (void)out_size;
}

// round 7
// speedup vs baseline: 1.7900x; 1.7900x over previous
#include <cuda_runtime.h>
#include <cuda_bf16.h>
#include <math.h>

#define NN   50000
#define EE   800000
#define DIN_ 32
#define DL_  128
#define DOUT_ 10
#define GG   256
#define KK   3

// ---------------- scratch (device globals) ----------------
__device__ __align__(16) float g_h  [NN * DL_];
__device__ __align__(16) float g_u  [NN * DL_];
__device__ __align__(16) float g_g  [NN * DL_];
__device__ __align__(16) float g_t  [NN * DL_];
__device__ __align__(16) float g_dec1[NN * 256];
__device__ __align__(16) float g_dinv[NN];
__device__ __align__(16) int   g_deg [NN];
__device__ __align__(16) int   g_off [NN + 1];
__device__ __align__(16) int   g_cur [NN];
__device__ __align__(16) int   g_csr [EE];
__device__ __align__(16) float g_sums[GG * DOUT_];
__device__ __align__(16) float g_cnt [GG];
// split-bf16 weight blobs (184320 elems total)
__device__ __align__(16) unsigned short g_wh[184320];
__device__ __align__(16) unsigned short g_wl[184320];

// ---------------- asm helpers ----------------
__device__ __forceinline__ unsigned smem_u32(const void* p) {
    unsigned a;
    asm("{ .reg .u64 t; cvta.to.shared.u64 t, %1; cvt.u32.u64 %0, t; }" : "=r"(a) : "l"(p));
    return a;
}
#define CP_ASYNC16(dst_u32, src) \
    asm volatile("cp.async.ca.shared.global [%0], [%1], 16;" :: "r"(dst_u32), "l"(src))
#define CP_COMMIT() asm volatile("cp.async.commit_group;")
#define CP_WAIT0()  asm volatile("cp.async.wait_group 0;")
#define LDSM_X4(r0, r1, r2, r3, addr) \
    asm volatile("ldmatrix.sync.aligned.m8n8.x4.shared.b16 {%0,%1,%2,%3}, [%4];" \
                 : "=r"(r0), "=r"(r1), "=r"(r2), "=r"(r3) : "r"(addr))
#define LDSM_X2T(r0, r1, addr) \
    asm volatile("ldmatrix.sync.aligned.m8n8.x2.trans.shared.b16 {%0,%1}, [%2];" \
                 : "=r"(r0), "=r"(r1) : "r"(addr))
#define MMA16816(c, a0, a1, a2, a3, b0, b1) \
    asm volatile("mma.sync.aligned.m16n8k16.row.col.f32.bf16.bf16.f32 " \
                 "{%0,%1,%2,%3}, {%4,%5,%6,%7}, {%8,%9}, {%0,%1,%2,%3};" \
                 : "+f"((c)[0]), "+f"((c)[1]), "+f"((c)[2]), "+f"((c)[3]) \
                 : "r"(a0), "r"(a1), "r"(a2), "r"(a3), "r"(b0), "r"(b1))

// smem geometry for gemm_mma
#define A_STRIDE 80      // bytes per A row (40 bf16, padded for bank-free ldmatrix)
#define B_STRIDE 272     // bytes per B row (136 bf16)
#define OFF_ALO  10240   // 128*80
#define OFF_BHI  20480
#define OFF_BLO  29184   // 20480 + 32*272
#define ABUF     37888   // per double-buffer stage
#define SMEM_GEMM (2 * ABUF)

// ---------------- one-time graph preprocessing ----------------
__global__ void count_deg_kernel(const int* __restrict__ dst, int* __restrict__ deg, int E) {
    int i = blockIdx.x * blockDim.x + threadIdx.x;
    if (i < E) atomicAdd(&deg[dst[i]], 1);
}

__global__ void count_nodes_kernel(const int* __restrict__ batch, float* __restrict__ cnt, int M) {
    int i = blockIdx.x * blockDim.x + threadIdx.x;
    if (i < M) atomicAdd(&cnt[batch[i]], 1.0f);
}

__global__ __launch_bounds__(1024)
void scan_offsets_kernel(const int* __restrict__ deg, int* __restrict__ off,
                         int* __restrict__ cursor, float* __restrict__ dinv, int M) {
    __shared__ int part[1024];
    int t = threadIdx.x;
    int chunk = (M + 1023) >> 10;
    int base = t * chunk;
    int s = 0;
    for (int i = 0; i < chunk; i++) { int j = base + i; if (j < M) s += deg[j]; }
    part[t] = s;
    __syncthreads();
    for (int d = 1; d < 1024; d <<= 1) {
        int add = (t >= d) ? part[t - d] : 0;
        __syncthreads();
        part[t] += add;
        __syncthreads();
    }
    int run = part[t] - s;
    for (int i = 0; i < chunk; i++) {
        int j = base + i;
        if (j < M) {
            int dj = deg[j];
            off[j] = run; cursor[j] = run; run += dj;
            dinv[j] = rsqrtf((float)dj + 1.0f);
        }
    }
    if (t == 1023) off[M] = part[1023];
}

__global__ void csr_fill_kernel(const int* __restrict__ src, const int* __restrict__ dst,
                                int* __restrict__ cursor, int* __restrict__ csr, int E) {
    int i = blockIdx.x * blockDim.x + threadIdx.x;
    if (i < E) {
        int p = atomicAdd(&cursor[dst[i]], 1);
        csr[p] = src[i];
    }
}

// ---------------- weight split prep: fp32 [K][N] -> bf16 hi/lo blobs (same layout) ----------------
struct WJob { const float* W; int elems; int off; };
struct WJobs { WJob j[11]; };

__global__ void wsplit_kernel(WJobs jobs, unsigned short* __restrict__ wh,
                              unsigned short* __restrict__ wl) {
    WJob jb = jobs.j[blockIdx.y];
    for (int i = blockIdx.x * blockDim.x + threadIdx.x; i < jb.elems;
         i += gridDim.x * blockDim.x) {
        float w = jb.W[i];
        __nv_bfloat16 hb = __float2bfloat16(w);
        __nv_bfloat16 lb = __float2bfloat16(w - __bfloat162float(hb));
        wh[jb.off + i] = __bfloat16_as_ushort(hb);
        wl[jb.off + i] = __bfloat16_as_ushort(lb);
    }
}

// ---------------- per-hop neighbor gather ----------------
__global__ __launch_bounds__(256)
void gather_kernel(const int* __restrict__ off, const int* __restrict__ csr,
                   const float* __restrict__ u, const float* __restrict__ dinv,
                   const float* __restrict__ bgcn, float* __restrict__ g, int M) {
    int n = (blockIdx.x * blockDim.x + threadIdx.x) >> 5;
    if (n >= M) return;
    int lane = threadIdx.x & 31;
    int e0 = off[n], e1 = off[n + 1];
    int deg = e1 - e0;

    float4 acc = __ldg((const float4*)(u + (size_t)n * DL_ + lane * 4));

    for (int base = 0; base < deg; base += 32) {
        int cnt = min(32, deg - base);
        int idx = 0;
        if (base + lane < deg) idx = __ldg(csr + e0 + base + lane);
        int j = 0;
        for (; j + 8 <= cnt; j += 8) {
            float4 v[8];
#pragma unroll
            for (int q = 0; q < 8; q++) {
                int s = __shfl_sync(0xffffffffu, idx, j + q);
                v[q] = __ldg((const float4*)(u + (size_t)s * DL_ + lane * 4));
            }
#pragma unroll
            for (int q = 0; q < 8; q++) {
                acc.x += v[q].x; acc.y += v[q].y; acc.z += v[q].z; acc.w += v[q].w;
            }
        }
        for (; j < cnt; j++) {
            int s = __shfl_sync(0xffffffffu, idx, j);
            float4 v = __ldg((const float4*)(u + (size_t)s * DL_ + lane * 4));
            acc.x += v.x; acc.y += v.y; acc.z += v.z; acc.w += v.w;
        }
    }

    float dv = dinv[n];
    float4 b = *(const float4*)(bgcn + lane * 4);
    float4 o;
    o.x = fmaf(dv, acc.x, b.x);
    o.y = fmaf(dv, acc.y, b.y);
    o.z = fmaf(dv, acc.z, b.z);
    o.w = fmaf(dv, acc.w, b.w);
    *(float4*)(g + (size_t)n * DL_ + lane * 4) = o;
}

// ---------------- split-bf16 tensor-core GEMM (mma.sync m16n8k16) ----------------
// CTA: 128 rows x 128 cols. 8 warps in 2x4; warp tile 64x32; BK=32, double-buffered.
// C = act(A[M,K] @ W + bias) * rowscale; W given as bf16 hi/lo [K][ldb] row-major.
// act: 0 none, 1 sigmoid, 2 relu, 4 softplus(v-5)->C and H = MU + C*EPS
__global__ __launch_bounds__(256)
void gemm_mma(const float* __restrict__ A,
              const __nv_bfloat16* __restrict__ Bh, const __nv_bfloat16* __restrict__ Bl,
              const float* __restrict__ bias, const float* __restrict__ rowscale,
              float* __restrict__ C, int M, int K, int ldb, int Ncs, int col0, int act,
              const float* __restrict__ MU, const float* __restrict__ EPS,
              float* __restrict__ H) {
    extern __shared__ __align__(16) char smem[];
    const unsigned sb = smem_u32(smem);
    const int tid  = threadIdx.x;
    const int wid  = tid >> 5;
    const int lane = tid & 31;
    const int brow = blockIdx.x * 128;

    const int warp_m = (wid >> 2) * 64;
    const int warp_n = (wid & 3) * 32;
    const int arow   = (lane & 7) + ((lane >> 3) & 1) * 8;  // ldmatrix x4 row
    const int akq    = (lane >> 4);                         // k half (0/1)
    const int lane16 = lane & 15;

    float acc[4][4][4];
#pragma unroll
    for (int i = 0; i < 4; i++)
#pragma unroll
        for (int j = 0; j < 4; j++)
#pragma unroll
            for (int q = 0; q < 4; q++) acc[i][j][q] = 0.0f;

    const int nkt = K >> 5;   // K/32 tiles
    const int sr  = tid >> 1;         // staging row 0..127
    const int skh = (tid & 1) * 16;   // staging k half

    // ---- staging lambdas (macro-style) ----
#define STAGE_B(bufi, kt) do { \
    unsigned dbase = sb + (bufi) * ABUF; \
    _Pragma("unroll") \
    for (int s2 = 0; s2 < 2; s2++) { \
        int idx = tid + s2 * 256; \
        int rowb = idx >> 4, cc = idx & 15; \
        const char* sh = (const char*)(Bh + (size_t)((kt) * 32 + rowb) * ldb) + cc * 16; \
        const char* sl = (const char*)(Bl + (size_t)((kt) * 32 + rowb) * ldb) + cc * 16; \
        CP_ASYNC16(dbase + OFF_BHI + rowb * B_STRIDE + cc * 16, sh); \
        CP_ASYNC16(dbase + OFF_BLO + rowb * B_STRIDE + cc * 16, sl); \
    } \
    CP_COMMIT(); \
} while (0)

#define STAGE_A(bufi, kt) do { \
    char* dh = smem + (bufi) * ABUF; \
    char* dl = smem + (bufi) * ABUF + OFF_ALO; \
    const float* Ar = A + (size_t)(brow + sr) * K + (kt) * 32 + skh; \
    bool okr = (brow + sr) < M; \
    _Pragma("unroll") \
    for (int i4 = 0; i4 < 4; i4++) { \
        float4 v = okr ? *(const float4*)(Ar + i4 * 4) : make_float4(0.f, 0.f, 0.f, 0.f); \
        __nv_bfloat16 h0 = __float2bfloat16(v.x), h1 = __float2bfloat16(v.y); \
        __nv_bfloat16 h2 = __float2bfloat16(v.z), h3 = __float2bfloat16(v.w); \
        __nv_bfloat16 l0 = __float2bfloat16(v.x - __bfloat162float(h0)); \
        __nv_bfloat16 l1 = __float2bfloat16(v.y - __bfloat162float(h1)); \
        __nv_bfloat16 l2 = __float2bfloat16(v.z - __bfloat162float(h2)); \
        __nv_bfloat16 l3 = __float2bfloat16(v.w - __bfloat162float(h3)); \
        unsigned hA = (unsigned)__bfloat16_as_ushort(h0) | ((unsigned)__bfloat16_as_ushort(h1) << 16); \
        unsigned hB = (unsigned)__bfloat16_as_ushort(h2) | ((unsigned)__bfloat16_as_ushort(h3) << 16); \
        unsigned lA = (unsigned)__bfloat16_as_ushort(l0) | ((unsigned)__bfloat16_as_ushort(l1) << 16); \
        unsigned lB = (unsigned)__bfloat16_as_ushort(l2) | ((unsigned)__bfloat16_as_ushort(l3) << 16); \
        *(uint2*)(dh + sr * A_STRIDE + (skh + i4 * 4) * 2) = make_uint2(hA, hB); \
        *(uint2*)(dl + sr * A_STRIDE + (skh + i4 * 4) * 2) = make_uint2(lA, lB); \
    } \
} while (0)

    STAGE_B(0, 0);
    STAGE_A(0, 0);
    CP_WAIT0();
    __syncthreads();

    for (int kt = 0; kt < nkt; kt++) {
        const int buf = kt & 1;
        const bool more = (kt + 1) < nkt;
        if (more) {
            STAGE_B(buf ^ 1, kt + 1);
            STAGE_A(buf ^ 1, kt + 1);
        }
        const unsigned sba = sb + buf * ABUF;
#pragma unroll
        for (int ks = 0; ks < 2; ks++) {
            unsigned aoff = sba + (warp_m + arow) * A_STRIDE + (ks * 16 + akq * 8) * 2;
            unsigned boff = sba + OFF_BHI + (ks * 16 + lane16) * B_STRIDE + warp_n * 2;
            unsigned Ah[4][4], Bhf[4][2];
#pragma unroll
            for (int tm = 0; tm < 4; tm++)
                LDSM_X4(Ah[tm][0], Ah[tm][1], Ah[tm][2], Ah[tm][3], aoff + tm * 16 * A_STRIDE);
#pragma unroll
            for (int tn = 0; tn < 4; tn++)
                LDSM_X2T(Bhf[tn][0], Bhf[tn][1], boff + tn * 16);
#pragma unroll
            for (int tm = 0; tm < 4; tm++)
#pragma unroll
                for (int tn = 0; tn < 4; tn++)
                    MMA16816(acc[tm][tn], Ah[tm][0], Ah[tm][1], Ah[tm][2], Ah[tm][3],
                             Bhf[tn][0], Bhf[tn][1]);
            // Ah x Blo
            unsigned Blf[4][2];
            unsigned bloff = sba + OFF_BLO + (ks * 16 + lane16) * B_STRIDE + warp_n * 2;
#pragma unroll
            for (int tn = 0; tn < 4; tn++)
                LDSM_X2T(Blf[tn][0], Blf[tn][1], bloff + tn * 16);
#pragma unroll
            for (int tm = 0; tm < 4; tm++)
#pragma unroll
                for (int tn = 0; tn < 4; tn++)
                    MMA16816(acc[tm][tn], Ah[tm][0], Ah[tm][1], Ah[tm][2], Ah[tm][3],
                             Blf[tn][0], Blf[tn][1]);
            // Alo x Bh
            unsigned Alf[4][4];
            unsigned aloff = sba + OFF_ALO + (warp_m + arow) * A_STRIDE + (ks * 16 + akq * 8) * 2;
#pragma unroll
            for (int tm = 0; tm < 4; tm++)
                LDSM_X4(Alf[tm][0], Alf[tm][1], Alf[tm][2], Alf[tm][3], aloff + tm * 16 * A_STRIDE);
#pragma unroll
            for (int tm = 0; tm < 4; tm++)
#pragma unroll
                for (int tn = 0; tn < 4; tn++)
                    MMA16816(acc[tm][tn], Alf[tm][0], Alf[tm][1], Alf[tm][2], Alf[tm][3],
                             Bhf[tn][0], Bhf[tn][1]);
        }
        if (more) CP_WAIT0();
        __syncthreads();
    }

    // ---- epilogue: fragments -> bias/act/rowscale -> global ----
#pragma unroll
    for (int tm = 0; tm < 4; tm++) {
        int r0 = brow + warp_m + tm * 16 + (lane >> 2);
        int r1 = r0 + 8;
        float rs0 = 1.0f, rs1 = 1.0f;
        if (rowscale) {
            if (r0 < M) rs0 = __ldg(rowscale + r0);
            if (r1 < M) rs1 = __ldg(rowscale + r1);
        }
#pragma unroll
        for (int tn = 0; tn < 4; tn++) {
            int gcol = col0 + warp_n + tn * 8 + (lane & 3) * 2;
            float bb0 = 0.f, bb1 = 0.f;
            if (bias) { bb0 = __ldg(bias + gcol); bb1 = __ldg(bias + gcol + 1); }
#pragma unroll
            for (int half = 0; half < 2; half++) {
                int r = half ? r1 : r0;
                if (r >= M) continue;
                float rs = half ? rs1 : rs0;
                float v0 = acc[tm][tn][half * 2 + 0] + bb0;
                float v1 = acc[tm][tn][half * 2 + 1] + bb1;
                if (act == 1) {
                    v0 = __fdividef(1.0f, 1.0f + __expf(-v0));
                    v1 = __fdividef(1.0f, 1.0f + __expf(-v1));
                } else if (act == 2) {
                    v0 = fmaxf(v0, 0.0f);
                    v1 = fmaxf(v1, 0.0f);
                } else if (act == 4) {
                    v0 -= 5.0f; v0 = (v0 > 20.0f) ? v0 : log1pf(expf(v0));
                    v1 -= 5.0f; v1 = (v1 > 20.0f) ? v1 : log1pf(expf(v1));
                }
                v0 *= rs; v1 *= rs;
                size_t idx = (size_t)r * Ncs + gcol;
                float2 o; o.x = v0; o.y = v1;
                *(float2*)(C + idx) = o;
                if (act == 4) {
                    float2 m = *(const float2*)(MU + idx);
                    float2 e = *(const float2*)(EPS + idx);
                    float2 hh;
                    hh.x = fmaf(v0, e.x, m.x);
                    hh.y = fmaf(v1, e.y, m.y);
                    *(float2*)(H + idx) = hh;
                }
            }
        }
    }
}

// ---------------- fused decoder tail ----------------
__global__ __launch_bounds__(128)
void decoder_tail_kernel(const float* __restrict__ din,
                         const float* __restrict__ W2, const float* __restrict__ b2,
                         const float* __restrict__ W3, const float* __restrict__ b3,
                         const float* __restrict__ W4, const float* __restrict__ b4,
                         const float* __restrict__ Wo, const float* __restrict__ bo,
                         const int* __restrict__ batch, float* __restrict__ sums, int M) {
    __shared__ float w2[128 * 64];
    __shared__ float w3[64 * 32];
    __shared__ float w4[32 * 16];
    __shared__ float wo[160];
    __shared__ float xs [4][128];
    __shared__ float t64[4][64];
    __shared__ float t32[4][32];
    __shared__ float t16[4][16];
    for (int i = threadIdx.x; i < 128 * 64; i += 128) w2[i] = W2[i];
    for (int i = threadIdx.x; i < 64 * 32;  i += 128) w3[i] = W3[i];
    for (int i = threadIdx.x; i < 32 * 16;  i += 128) w4[i] = W4[i];
    for (int i = threadIdx.x; i < 160;      i += 128) wo[i] = Wo[i];
    __syncthreads();

    int warp = threadIdx.x >> 5;
    int lane = threadIdx.x & 31;
    int stride = gridDim.x * 4;

    for (int row = blockIdx.x * 4 + warp; row < M; row += stride) {
        *(float4*)&xs[warp][lane * 4] = *(const float4*)(din + (size_t)row * 128 + lane * 4);
        __syncwarp();
        float s0 = b2[lane], s1 = b2[lane + 32];
#pragma unroll 8
        for (int k = 0; k < 128; k++) {
            float xv = xs[warp][k];
            s0 = fmaf(xv, w2[k * 64 + lane],      s0);
            s1 = fmaf(xv, w2[k * 64 + lane + 32], s1);
        }
        t64[warp][lane]      = fmaxf(s0, 0.0f);
        t64[warp][lane + 32] = fmaxf(s1, 0.0f);
        __syncwarp();
        float s = b3[lane];
#pragma unroll 8
        for (int k = 0; k < 64; k++) s = fmaf(t64[warp][k], w3[k * 32 + lane], s);
        t32[warp][lane] = fmaxf(s, 0.0f);
        __syncwarp();
        if (lane < 16) {
            float t = b4[lane];
#pragma unroll
            for (int k = 0; k < 32; k++) t = fmaf(t32[warp][k], w4[k * 16 + lane], t);
            t16[warp][lane] = fmaxf(t, 0.0f);
        }
        __syncwarp();
        if (lane < 10) {
            float t = bo[lane];
#pragma unroll
            for (int k = 0; k < 16; k++) t = fmaf(t16[warp][k], wo[k * 10 + lane], t);
            float yp = __fdividef(1.0f, 1.0f + __expf(-t));
            atomicAdd(&sums[batch[row] * 10 + lane], yp);
        }
        __syncwarp();
    }
}

__global__ void pool_finalize_kernel(const float* __restrict__ sums, const float* __restrict__ cnt,
                                     const float* __restrict__ y,
                                     float* __restrict__ out_pred, float* __restrict__ out_y) {
    int i = blockIdx.x * blockDim.x + threadIdx.x;
    if (i < GG * DOUT_) {
        out_pred[i] = sums[i] / fmaxf(cnt[i / DOUT_], 1.0f);
        out_y[i]    = y[i];
    }
}

// ---------------- launch ----------------
extern "C" void kernel_launch(void* const* d_in, const int* in_sizes, int n_in,
                              void* d_out, int out_size) {
    const float* x     = (const float*)d_in[0];
    const int*   ei    = (const int*)  d_in[1];
    const int*   batch = (const int*)  d_in[2];
    const float* y     = (const float*)d_in[3];
    const float* eps   = (const float*)d_in[4];
    const float* W_in  = (const float*)d_in[5];
    const float* b_in  = (const float*)d_in[6];
    const float* W_gcn = (const float*)d_in[7];
    const float* b_gcn = (const float*)d_in[8];
    const float* W_enc = (const float*)d_in[9];
    const float* b_enc = (const float*)d_in[10];
    const float* W_mu  = (const float*)d_in[11];
    const float* b_mu  = (const float*)d_in[12];
    const float* W_std = (const float*)d_in[13];
    const float* b_std = (const float*)d_in[14];
    const float* Wd0 = (const float*)d_in[15]; const float* bd0 = (const float*)d_in[16];
    const float* Wd1 = (const float*)d_in[17]; const float* bd1 = (const float*)d_in[18];
    const float* Wd2 = (const float*)d_in[19]; const float* bd2 = (const float*)d_in[20];
    const float* Wd3 = (const float*)d_in[21]; const float* bd3 = (const float*)d_in[22];
    const float* Wd4 = (const float*)d_in[23]; const float* bd4 = (const float*)d_in[24];
    const float* Wo  = (const float*)d_in[25]; const float* bo  = (const float*)d_in[26];

    float *h, *u, *gbuf, *tbuf, *dec1, *dinv, *sums, *cnt;
    int *deg, *off, *cur, *csr;
    unsigned short *wh, *wl;
    cudaGetSymbolAddress((void**)&h,    g_h);
    cudaGetSymbolAddress((void**)&u,    g_u);
    cudaGetSymbolAddress((void**)&gbuf, g_g);
    cudaGetSymbolAddress((void**)&tbuf, g_t);
    cudaGetSymbolAddress((void**)&dec1, g_dec1);
    cudaGetSymbolAddress((void**)&dinv, g_dinv);
    cudaGetSymbolAddress((void**)&deg,  g_deg);
    cudaGetSymbolAddress((void**)&off,  g_off);
    cudaGetSymbolAddress((void**)&cur,  g_cur);
    cudaGetSymbolAddress((void**)&csr,  g_csr);
    cudaGetSymbolAddress((void**)&sums, g_sums);
    cudaGetSymbolAddress((void**)&cnt,  g_cnt);
    cudaGetSymbolAddress((void**)&wh,   g_wh);
    cudaGetSymbolAddress((void**)&wl,   g_wl);

    float* out      = (float*)d_out;
    float* out_pred = out;
    float* out_mu   = out + GG * DOUT_;
    float* out_std  = out + GG * DOUT_ + (size_t)NN * DL_;
    float* out_y    = out + GG * DOUT_ + (size_t)2 * NN * DL_;

    const int* src = ei;
    const int* dst = ei + EE;

    cudaFuncSetAttribute(gemm_mma, cudaFuncAttributeMaxDynamicSharedMemorySize, SMEM_GEMM);

    // weight split blobs: 0 in,1 gcn,2-6 enc,7 mu,8 std,9 Wd0,10 Wd1
    WJobs jobs;
    int O[11];
    {
        int o = 0;
        auto set = [&](int i, const float* W, int elems) {
            jobs.j[i].W = W; jobs.j[i].elems = elems; jobs.j[i].off = o; O[i] = o; o += elems;
        };
        set(0, W_in, 32 * 128);
        set(1, W_gcn, 128 * 128);
        for (int j = 0; j < 5; j++) set(2 + j, W_enc + (size_t)j * DL_ * DL_, 128 * 128);
        set(7, W_mu, 128 * 128);
        set(8, W_std, 128 * 128);
        set(9, Wd0, 128 * 256);
        set(10, Wd1, 256 * 128);
    }
    wsplit_kernel<<<dim3(32, 11), 256>>>(jobs, wh, wl);

    // graph preprocessing
    cudaMemsetAsync(deg, 0, NN * sizeof(int));
    count_deg_kernel   <<<(EE + 255) / 256, 256>>>(dst, deg, EE);
    scan_offsets_kernel<<<1, 1024>>>(deg, off, cur, dinv, NN);
    csr_fill_kernel    <<<(EE + 255) / 256, 256>>>(src, dst, cur, csr, EE);

    const int GRID = (NN + 127) / 128;   // 391
    const __nv_bfloat16* WH = (const __nv_bfloat16*)wh;
    const __nv_bfloat16* WL = (const __nv_bfloat16*)wl;

    // input layer: h = sigmoid(x @ W_in + b_in)
    gemm_mma<<<GRID, 256, SMEM_GEMM>>>(x, WH + O[0], WL + O[0], b_in, nullptr,
                                       h, NN, 32, 128, 128, 0, 1, nullptr, nullptr, nullptr);

    for (int it = 0; it < KK; it++) {
        // u = (h @ W_gcn) * dinv[row]
        gemm_mma<<<GRID, 256, SMEM_GEMM>>>(h, WH + O[1], WL + O[1], nullptr, dinv,
                                           u, NN, 128, 128, 128, 0, 0, nullptr, nullptr, nullptr);
        gather_kernel<<<(NN * 32 + 255) / 256, 256>>>(off, csr, u, dinv, b_gcn, gbuf, NN);

        const float* curp = gbuf;
        float* nxt = tbuf;
        for (int j = 0; j < 5; j++) {
            gemm_mma<<<GRID, 256, SMEM_GEMM>>>(curp, WH + O[2 + j], WL + O[2 + j],
                                               b_enc + j * DL_, nullptr,
                                               nxt, NN, 128, 128, 128, 0, 1,
                                               nullptr, nullptr, nullptr);
            float* tmp = (float*)curp; curp = nxt; nxt = tmp;
        }
        gemm_mma<<<GRID, 256, SMEM_GEMM>>>(curp, WH + O[7], WL + O[7], b_mu, nullptr,
                                           out_mu, NN, 128, 128, 128, 0, 0,
                                           nullptr, nullptr, nullptr);
        gemm_mma<<<GRID, 256, SMEM_GEMM>>>(curp, WH + O[8], WL + O[8], b_std, nullptr,
                                           out_std, NN, 128, 128, 128, 0, 4,
                                           out_mu, eps + (size_t)it * NN * DL_, h);
    }

    // decoder: 128 -> 256 (two col-tiles of Wd0) -> 128 -> tail
    gemm_mma<<<GRID, 256, SMEM_GEMM>>>(h, WH + O[9], WL + O[9], bd0, nullptr,
                                       dec1, NN, 128, 256, 256, 0, 2, nullptr, nullptr, nullptr);
    gemm_mma<<<GRID, 256, SMEM_GEMM>>>(h, WH + O[9] + 128, WL + O[9] + 128, bd0, nullptr,
                                       dec1, NN, 128, 256, 256, 128, 2, nullptr, nullptr, nullptr);
    gemm_mma<<<GRID, 256, SMEM_GEMM>>>(dec1, WH + O[10], WL + O[10], bd1, nullptr,
                                       u, NN, 256, 128, 128, 0, 2, nullptr, nullptr, nullptr);

    cudaMemsetAsync(sums, 0, GG * DOUT_ * sizeof(float));
    cudaMemsetAsync(cnt,  0, GG * sizeof(float));
    count_nodes_kernel<<<(NN + 255) / 256, 256>>>(batch, cnt, NN);
    decoder_tail_kernel<<<592, 128>>>(u, Wd2, bd2, Wd3, bd3, Wd4, bd4, Wo, bo,
                                      batch, sums, NN);
    pool_finalize_kernel<<<(GG * DOUT_ + 255) / 256, 256>>>(sums, cnt, y, out_pred, out_y);

    (void)in_sizes; (void)n_in; (void)out_size;
}

// round 8
// speedup vs baseline: 2.2942x; 1.2817x over previous
#include <cuda_runtime.h>
#include <cuda_bf16.h>
#include <math.h>

#define NN   50000
#define EE   800000
#define DIN_ 32
#define DL_  128
#define DOUT_ 10
#define GG   256
#define KK   3

// ---------------- scratch (device globals) ----------------
__device__ __align__(16) float g_h  [NN * DL_];
__device__ __align__(16) float g_u  [NN * DL_];
__device__ __align__(16) float g_g  [NN * DL_];
__device__ __align__(16) float g_dec1[NN * 256];
__device__ __align__(16) float g_dinv[NN];
__device__ __align__(16) int   g_deg [NN];
__device__ __align__(16) int   g_off [NN + 1];
__device__ __align__(16) int   g_cur [NN];
__device__ __align__(16) int   g_csr [EE];
__device__ __align__(16) float g_sums[GG * DOUT_];
__device__ __align__(16) float g_cnt [GG];
__device__ __align__(16) unsigned short g_wh[184320];
__device__ __align__(16) unsigned short g_wl[184320];

// ---------------- asm helpers ----------------
__device__ __forceinline__ unsigned smem_u32(const void* p) {
    unsigned a;
    asm("{ .reg .u64 t; cvta.to.shared.u64 t, %1; cvt.u32.u64 %0, t; }" : "=r"(a) : "l"(p));
    return a;
}
#define CP_ASYNC16(dst_u32, src) \
    asm volatile("cp.async.ca.shared.global [%0], [%1], 16;" :: "r"(dst_u32), "l"(src))
#define CP_COMMIT() asm volatile("cp.async.commit_group;")
#define CP_WAIT0()  asm volatile("cp.async.wait_group 0;")
#define LDSM_X4(r0, r1, r2, r3, addr) \
    asm volatile("ldmatrix.sync.aligned.m8n8.x4.shared.b16 {%0,%1,%2,%3}, [%4];" \
                 : "=r"(r0), "=r"(r1), "=r"(r2), "=r"(r3) : "r"(addr))
#define LDSM_X2T(r0, r1, addr) \
    asm volatile("ldmatrix.sync.aligned.m8n8.x2.trans.shared.b16 {%0,%1}, [%2];" \
                 : "=r"(r0), "=r"(r1) : "r"(addr))
#define MMA16816(c, a0, a1, a2, a3, b0, b1) \
    asm volatile("mma.sync.aligned.m16n8k16.row.col.f32.bf16.bf16.f32 " \
                 "{%0,%1,%2,%3}, {%4,%5,%6,%7}, {%8,%9}, {%0,%1,%2,%3};" \
                 : "+f"((c)[0]), "+f"((c)[1]), "+f"((c)[2]), "+f"((c)[3]) \
                 : "r"(a0), "r"(a1), "r"(a2), "r"(a3), "r"(b0), "r"(b1))

__device__ __forceinline__ unsigned bfpack(float a, float b) {
    return (unsigned)__bfloat16_as_ushort(__float2bfloat16(a)) |
           ((unsigned)__bfloat16_as_ushort(__float2bfloat16(b)) << 16);
}
__device__ __forceinline__ void bfsplit2(float v0, float v1, unsigned& hi, unsigned& lo) {
    __nv_bfloat16 h0 = __float2bfloat16(v0), h1 = __float2bfloat16(v1);
    float r0 = v0 - __bfloat162float(h0), r1 = v1 - __bfloat162float(h1);
    hi = (unsigned)__bfloat16_as_ushort(h0) | ((unsigned)__bfloat16_as_ushort(h1) << 16);
    lo = (unsigned)__bfloat16_as_ushort(__float2bfloat16(r0)) |
         ((unsigned)__bfloat16_as_ushort(__float2bfloat16(r1)) << 16);
}

// ================= mega kernel smem geometry =================
#define AST    272                 // bytes per 128-col bf16 row (+pad)
#define MS_AH  0
#define MS_AL  34816
#define MS_W0  69632               // hi at +0, lo at +34816
#define MS_W1  139264
#define MS_MU  139264              // fp32 mu reuses W1 region (stride 528B)
#define MEGA_SMEM 208896

// old gemm geometry (decoder)
#define A_STRIDE 80
#define B_STRIDE 272
#define OFF_ALO  10240
#define OFF_BHI  20480
#define OFF_BLO  29184
#define ABUF     37888
#define SMEM_GEMM (2 * ABUF)

// ---------------- preprocessing ----------------
__global__ void count_deg_kernel(const int* __restrict__ dst, int* __restrict__ deg, int E) {
    int i = blockIdx.x * blockDim.x + threadIdx.x;
    if (i < E) atomicAdd(&deg[dst[i]], 1);
}
__global__ void count_nodes_kernel(const int* __restrict__ batch, float* __restrict__ cnt, int M) {
    int i = blockIdx.x * blockDim.x + threadIdx.x;
    if (i < M) atomicAdd(&cnt[batch[i]], 1.0f);
}
__global__ __launch_bounds__(1024)
void scan_offsets_kernel(const int* __restrict__ deg, int* __restrict__ off,
                         int* __restrict__ cursor, float* __restrict__ dinv, int M) {
    __shared__ int part[1024];
    int t = threadIdx.x;
    int chunk = (M + 1023) >> 10;
    int base = t * chunk;
    int s = 0;
    for (int i = 0; i < chunk; i++) { int j = base + i; if (j < M) s += deg[j]; }
    part[t] = s;
    __syncthreads();
    for (int d = 1; d < 1024; d <<= 1) {
        int add = (t >= d) ? part[t - d] : 0;
        __syncthreads();
        part[t] += add;
        __syncthreads();
    }
    int run = part[t] - s;
    for (int i = 0; i < chunk; i++) {
        int j = base + i;
        if (j < M) {
            int dj = deg[j];
            off[j] = run; cursor[j] = run; run += dj;
            dinv[j] = rsqrtf((float)dj + 1.0f);
        }
    }
    if (t == 1023) off[M] = part[1023];
}
__global__ void csr_fill_kernel(const int* __restrict__ src, const int* __restrict__ dst,
                                int* __restrict__ cursor, int* __restrict__ csr, int E) {
    int i = blockIdx.x * blockDim.x + threadIdx.x;
    if (i < E) {
        int p = atomicAdd(&cursor[dst[i]], 1);
        csr[p] = src[i];
    }
}

// ---------------- weight split ----------------
struct WJob { const float* W; int elems; int off; };
struct WJobs { WJob j[11]; };
__global__ void wsplit_kernel(WJobs jobs, unsigned short* __restrict__ wh,
                              unsigned short* __restrict__ wl) {
    WJob jb = jobs.j[blockIdx.y];
    for (int i = blockIdx.x * blockDim.x + threadIdx.x; i < jb.elems;
         i += gridDim.x * blockDim.x) {
        float w = jb.W[i];
        __nv_bfloat16 hb = __float2bfloat16(w);
        __nv_bfloat16 lb = __float2bfloat16(w - __bfloat162float(hb));
        wh[jb.off + i] = __bfloat16_as_ushort(hb);
        wl[jb.off + i] = __bfloat16_as_ushort(lb);
    }
}

// ---------------- gather ----------------
__global__ __launch_bounds__(256)
void gather_kernel(const int* __restrict__ off, const int* __restrict__ csr,
                   const float* __restrict__ u, const float* __restrict__ dinv,
                   const float* __restrict__ bgcn, float* __restrict__ g, int M) {
    int n = (blockIdx.x * blockDim.x + threadIdx.x) >> 5;
    if (n >= M) return;
    int lane = threadIdx.x & 31;
    int e0 = off[n], e1 = off[n + 1];
    int deg = e1 - e0;
    float4 acc = __ldg((const float4*)(u + (size_t)n * DL_ + lane * 4));
    for (int base = 0; base < deg; base += 32) {
        int cnt = min(32, deg - base);
        int idx = 0;
        if (base + lane < deg) idx = __ldg(csr + e0 + base + lane);
        int j = 0;
        for (; j + 8 <= cnt; j += 8) {
            float4 v[8];
#pragma unroll
            for (int q = 0; q < 8; q++) {
                int s = __shfl_sync(0xffffffffu, idx, j + q);
                v[q] = __ldg((const float4*)(u + (size_t)s * DL_ + lane * 4));
            }
#pragma unroll
            for (int q = 0; q < 8; q++) {
                acc.x += v[q].x; acc.y += v[q].y; acc.z += v[q].z; acc.w += v[q].w;
            }
        }
        for (; j < cnt; j++) {
            int s = __shfl_sync(0xffffffffu, idx, j);
            float4 v = __ldg((const float4*)(u + (size_t)s * DL_ + lane * 4));
            acc.x += v.x; acc.y += v.y; acc.z += v.z; acc.w += v.w;
        }
    }
    float dv = dinv[n];
    float4 b = *(const float4*)(bgcn + lane * 4);
    float4 o;
    o.x = fmaf(dv, acc.x, b.x);
    o.y = fmaf(dv, acc.y, b.y);
    o.z = fmaf(dv, acc.z, b.z);
    o.w = fmaf(dv, acc.w, b.w);
    *(float4*)(g + (size_t)n * DL_ + lane * 4) = o;
}

// ================= mega kernel pieces =================
__device__ __forceinline__ void stage_w128(unsigned sb, int woff,
                                           const __nv_bfloat16* Wh, const __nv_bfloat16* Wl,
                                           int nrows, int tid) {
    int chunks = nrows * 16;
    for (int idx = tid; idx < chunks; idx += 256) {
        int rowb = idx >> 4, cc = idx & 15;
        CP_ASYNC16(sb + woff + rowb * AST + cc * 16, (const char*)(Wh + rowb * 128) + cc * 16);
        CP_ASYNC16(sb + woff + 34816 + rowb * AST + cc * 16,
                   (const char*)(Wl + rowb * 128) + cc * 16);
    }
    CP_COMMIT();
}

// acc = A(smem hi/lo) @ W(smem hi/lo), 3 split products, K = nks*16
__device__ __forceinline__ void layer_mma(unsigned sb, int woff,
                                          int warp_m, int warp_n, int lane,
                                          int nks, float acc[4][4][4]) {
#pragma unroll
    for (int i = 0; i < 4; i++)
#pragma unroll
        for (int j = 0; j < 4; j++)
#pragma unroll
            for (int q = 0; q < 4; q++) acc[i][j][q] = 0.0f;
    const int arow = (lane & 7) + ((lane >> 3) & 1) * 8;
    const int akq  = lane >> 4;
    const int lane16 = lane & 15;
    for (int ks = 0; ks < nks; ks++) {
        unsigned aoff = sb + MS_AH + (warp_m + arow) * AST + (ks * 16 + akq * 8) * 2;
        unsigned boff = sb + woff + (ks * 16 + lane16) * AST + warp_n * 2;
        unsigned Ah[4][4], Bhf[4][2];
#pragma unroll
        for (int tm = 0; tm < 4; tm++)
            LDSM_X4(Ah[tm][0], Ah[tm][1], Ah[tm][2], Ah[tm][3], aoff + tm * 16 * AST);
#pragma unroll
        for (int tn = 0; tn < 4; tn++)
            LDSM_X2T(Bhf[tn][0], Bhf[tn][1], boff + tn * 16);
#pragma unroll
        for (int tm = 0; tm < 4; tm++)
#pragma unroll
            for (int tn = 0; tn < 4; tn++)
                MMA16816(acc[tm][tn], Ah[tm][0], Ah[tm][1], Ah[tm][2], Ah[tm][3],
                         Bhf[tn][0], Bhf[tn][1]);
        unsigned Blf[4][2];
        unsigned bloff = boff + 34816;
#pragma unroll
        for (int tn = 0; tn < 4; tn++)
            LDSM_X2T(Blf[tn][0], Blf[tn][1], bloff + tn * 16);
#pragma unroll
        for (int tm = 0; tm < 4; tm++)
#pragma unroll
            for (int tn = 0; tn < 4; tn++)
                MMA16816(acc[tm][tn], Ah[tm][0], Ah[tm][1], Ah[tm][2], Ah[tm][3],
                         Blf[tn][0], Blf[tn][1]);
        unsigned Alf[4][4];
        unsigned aloff = aoff + (MS_AL - MS_AH);
#pragma unroll
        for (int tm = 0; tm < 4; tm++)
            LDSM_X4(Alf[tm][0], Alf[tm][1], Alf[tm][2], Alf[tm][3], aloff + tm * 16 * AST);
#pragma unroll
        for (int tm = 0; tm < 4; tm++)
#pragma unroll
            for (int tn = 0; tn < 4; tn++)
                MMA16816(acc[tm][tn], Alf[tm][0], Alf[tm][1], Alf[tm][2], Alf[tm][3],
                         Bhf[tn][0], Bhf[tn][1]);
    }
}

// sigmoid + split-store fragments back into the resident A tile
__device__ __forceinline__ void store_act_sig(char* smem, float acc[4][4][4],
                                              const float* __restrict__ bias,
                                              int warp_m, int warp_n, int lane) {
#pragma unroll
    for (int tn = 0; tn < 4; tn++) {
        int c = warp_n + tn * 8 + (lane & 3) * 2;
        float b0 = __ldg(bias + c), b1 = __ldg(bias + c + 1);
#pragma unroll
        for (int tm = 0; tm < 4; tm++)
#pragma unroll
            for (int half = 0; half < 2; half++) {
                int r = warp_m + tm * 16 + (lane >> 2) + half * 8;
                float v0 = acc[tm][tn][half * 2]     + b0;
                float v1 = acc[tm][tn][half * 2 + 1] + b1;
                v0 = __fdividef(1.0f, 1.0f + __expf(-v0));
                v1 = __fdividef(1.0f, 1.0f + __expf(-v1));
                unsigned hi, lo;
                bfsplit2(v0, v1, hi, lo);
                *(unsigned*)(smem + MS_AH + r * AST + c * 2) = hi;
                *(unsigned*)(smem + MS_AL + r * AST + c * 2) = lo;
            }
    }
}

// mega: mode 0 = input (x -> h -> u); 1 = hop (g -> ... -> u); 2 = last hop (g -> mu,std,h)
__global__ __launch_bounds__(256)
void mega_kernel(int mode, const float* __restrict__ Ain,
                 const __nv_bfloat16* __restrict__ WH, const __nv_bfloat16* __restrict__ WL,
                 int o_first, const float* __restrict__ b_first,
                 int o_gcn, int o_enc0, const float* __restrict__ b_enc,
                 int o_mu, const float* __restrict__ b_mu,
                 int o_std, const float* __restrict__ b_std,
                 const float* __restrict__ dinv, const float* __restrict__ eps_it,
                 float* __restrict__ u_out, float* __restrict__ mu_out,
                 float* __restrict__ std_out, float* __restrict__ h_out, int M) {
    extern __shared__ __align__(16) char smem[];
    const unsigned sb = smem_u32(smem);
    const int tid  = threadIdx.x;
    const int wid  = tid >> 5;
    const int lane = tid & 31;
    const int brow = blockIdx.x * 128;
    const int warp_m = (wid >> 2) * 64;
    const int warp_n = (wid & 3) * 32;

    // ---- stage initial A (fp32 global -> bf16 hi/lo smem) ----
    {
        const int K0 = (mode == 0) ? DIN_ : DL_;
        const int halfK = K0 >> 1;
        int row = tid >> 1;
        int c0 = (tid & 1) * halfK;
        bool ok = (brow + row) < M;
        const float* Ar = Ain + (size_t)(brow + row) * K0 + c0;
        for (int i4 = 0; i4 < (halfK >> 2); i4++) {
            float4 v = ok ? *(const float4*)(Ar + i4 * 4) : make_float4(0.f, 0.f, 0.f, 0.f);
            unsigned h01, l01, h23, l23;
            bfsplit2(v.x, v.y, h01, l01);
            bfsplit2(v.z, v.w, h23, l23);
            int c = c0 + i4 * 4;
            *(uint2*)(smem + MS_AH + row * AST + c * 2) = make_uint2(h01, h23);
            *(uint2*)(smem + MS_AL + row * AST + c * 2) = make_uint2(l01, l23);
        }
    }
    stage_w128(sb, MS_W0, WH + ((mode == 0) ? o_first : o_enc0),
               WL + ((mode == 0) ? o_first : o_enc0), (mode == 0) ? 32 : 128, tid);
    CP_WAIT0();
    __syncthreads();

    float acc[4][4][4];

    if (mode == 0) {
        // l0: W_in (K=32), sigmoid -> A; stage gcn meanwhile
        stage_w128(sb, MS_W1, WH + o_gcn, WL + o_gcn, 128, tid);
        layer_mma(sb, MS_W0, warp_m, warp_n, lane, 2, acc);
        __syncthreads();
        store_act_sig(smem, acc, b_first, warp_m, warp_n, lane);
        CP_WAIT0();
        __syncthreads();
        // l1: gcn -> u (rowscale dinv)
        layer_mma(sb, MS_W1, warp_m, warp_n, lane, 8, acc);
#pragma unroll
        for (int tm = 0; tm < 4; tm++)
#pragma unroll
            for (int half = 0; half < 2; half++) {
                int r = brow + warp_m + tm * 16 + (lane >> 2) + half * 8;
                if (r >= M) continue;
                float rs = __ldg(dinv + r);
#pragma unroll
                for (int tn = 0; tn < 4; tn++) {
                    int c = warp_n + tn * 8 + (lane & 3) * 2;
                    float2 o;
                    o.x = acc[tm][tn][half * 2]     * rs;
                    o.y = acc[tm][tn][half * 2 + 1] * rs;
                    *(float2*)(u_out + (size_t)r * DL_ + c) = o;
                }
            }
        return;
    }

    // ---- hop: enc x5 ----
    for (int j = 0; j < 5; j++) {
        int cb = (j & 1) ? MS_W1 : MS_W0;
        int nb = (j & 1) ? MS_W0 : MS_W1;
        int nxt = (j < 4) ? (o_enc0 + (j + 1) * 16384) : o_mu;
        stage_w128(sb, nb, WH + nxt, WL + nxt, 128, tid);
        layer_mma(sb, cb, warp_m, warp_n, lane, 8, acc);
        __syncthreads();
        store_act_sig(smem, acc, b_enc + j * DL_, warp_m, warp_n, lane);
        CP_WAIT0();
        __syncthreads();
    }
    // ---- mu (W in W1); stage W_std -> W0 ----
    stage_w128(sb, MS_W0, WH + o_std, WL + o_std, 128, tid);
    layer_mma(sb, MS_W1, warp_m, warp_n, lane, 8, acc);
    __syncthreads();   // all warps done reading W_mu (W1)
    // park mu as fp32 in W1 region; write out if last hop
#pragma unroll
    for (int tn = 0; tn < 4; tn++) {
        int c = warp_n + tn * 8 + (lane & 3) * 2;
        float b0 = __ldg(b_mu + c), b1 = __ldg(b_mu + c + 1);
#pragma unroll
        for (int tm = 0; tm < 4; tm++)
#pragma unroll
            for (int half = 0; half < 2; half++) {
                int r = warp_m + tm * 16 + (lane >> 2) + half * 8;
                float2 v;
                v.x = acc[tm][tn][half * 2]     + b0;
                v.y = acc[tm][tn][half * 2 + 1] + b1;
                *(float2*)(smem + MS_MU + r * 528 + c * 4) = v;
                if (mode == 2 && (brow + r) < M)
                    *(float2*)(mu_out + (size_t)(brow + r) * DL_ + c) = v;
            }
    }
    CP_WAIT0();
    __syncthreads();
    // ---- std (W in W0) ----
    layer_mma(sb, MS_W0, warp_m, warp_n, lane, 8, acc);
    __syncthreads();   // done reading A5 + W_std
    if (mode == 1)     // overlap gcn weight staging with the h computation
        stage_w128(sb, MS_W0, WH + o_gcn, WL + o_gcn, 128, tid);
    // h = mu + softplus(std)*eps -> resident A; write std/h if last hop
#pragma unroll
    for (int tn = 0; tn < 4; tn++) {
        int c = warp_n + tn * 8 + (lane & 3) * 2;
        float b0 = __ldg(b_std + c), b1 = __ldg(b_std + c + 1);
#pragma unroll
        for (int tm = 0; tm < 4; tm++)
#pragma unroll
            for (int half = 0; half < 2; half++) {
                int r = warp_m + tm * 16 + (lane >> 2) + half * 8;
                int gr = brow + r;
                float s0 = acc[tm][tn][half * 2]     + b0 - 5.0f;
                float s1 = acc[tm][tn][half * 2 + 1] + b1 - 5.0f;
                s0 = (s0 > 20.0f) ? s0 : log1pf(expf(s0));
                s1 = (s1 > 20.0f) ? s1 : log1pf(expf(s1));
                float2 m = *(const float2*)(smem + MS_MU + r * 528 + c * 4);
                float2 e = make_float2(0.f, 0.f);
                if (gr < M) e = *(const float2*)(eps_it + (size_t)gr * DL_ + c);
                float h0 = fmaf(s0, e.x, m.x);
                float h1 = fmaf(s1, e.y, m.y);
                if (mode == 2 && gr < M) {
                    float2 so; so.x = s0; so.y = s1;
                    *(float2*)(std_out + (size_t)gr * DL_ + c) = so;
                    float2 ho; ho.x = h0; ho.y = h1;
                    *(float2*)(h_out + (size_t)gr * DL_ + c) = ho;
                }
                unsigned hi, lo;
                bfsplit2(h0, h1, hi, lo);
                *(unsigned*)(smem + MS_AH + r * AST + c * 2) = hi;
                *(unsigned*)(smem + MS_AL + r * AST + c * 2) = lo;
            }
    }
    if (mode == 2) return;
    CP_WAIT0();
    __syncthreads();
    // ---- gcn: u = h @ W_gcn * dinv ----
    layer_mma(sb, MS_W0, warp_m, warp_n, lane, 8, acc);
#pragma unroll
    for (int tm = 0; tm < 4; tm++)
#pragma unroll
        for (int half = 0; half < 2; half++) {
            int r = brow + warp_m + tm * 16 + (lane >> 2) + half * 8;
            if (r >= M) continue;
            float rs = __ldg(dinv + r);
#pragma unroll
            for (int tn = 0; tn < 4; tn++) {
                int c = warp_n + tn * 8 + (lane & 3) * 2;
                float2 o;
                o.x = acc[tm][tn][half * 2]     * rs;
                o.y = acc[tm][tn][half * 2 + 1] * rs;
                *(float2*)(u_out + (size_t)r * DL_ + c) = o;
            }
        }
}

// ---------------- decoder GEMM (unchanged proven kernel) ----------------
__global__ __launch_bounds__(256)
void gemm_mma(const float* __restrict__ A,
              const __nv_bfloat16* __restrict__ Bh, const __nv_bfloat16* __restrict__ Bl,
              const float* __restrict__ bias, float* __restrict__ C,
              int M, int K, int ldb, int Ncs, int col0) {
    extern __shared__ __align__(16) char smem[];
    const unsigned sb = smem_u32(smem);
    const int tid  = threadIdx.x;
    const int wid  = tid >> 5;
    const int lane = tid & 31;
    const int brow = blockIdx.x * 128;
    const int warp_m = (wid >> 2) * 64;
    const int warp_n = (wid & 3) * 32;
    const int arow   = (lane & 7) + ((lane >> 3) & 1) * 8;
    const int akq    = (lane >> 4);
    const int lane16 = lane & 15;

    float acc[4][4][4];
#pragma unroll
    for (int i = 0; i < 4; i++)
#pragma unroll
        for (int j = 0; j < 4; j++)
#pragma unroll
            for (int q = 0; q < 4; q++) acc[i][j][q] = 0.0f;

    const int nkt = K >> 5;
    const int sr  = tid >> 1;
    const int skh = (tid & 1) * 16;

#define STAGE_BD(bufi, kt) do { \
    unsigned dbase = sb + (bufi) * ABUF; \
    _Pragma("unroll") \
    for (int s2 = 0; s2 < 2; s2++) { \
        int idx = tid + s2 * 256; \
        int rowb = idx >> 4, cc = idx & 15; \
        const char* sh = (const char*)(Bh + (size_t)((kt) * 32 + rowb) * ldb) + cc * 16; \
        const char* sl = (const char*)(Bl + (size_t)((kt) * 32 + rowb) * ldb) + cc * 16; \
        CP_ASYNC16(dbase + OFF_BHI + rowb * B_STRIDE + cc * 16, sh); \
        CP_ASYNC16(dbase + OFF_BLO + rowb * B_STRIDE + cc * 16, sl); \
    } \
    CP_COMMIT(); \
} while (0)

#define STAGE_AD(bufi, kt) do { \
    char* dh = smem + (bufi) * ABUF; \
    char* dl = smem + (bufi) * ABUF + OFF_ALO; \
    const float* Ar = A + (size_t)(brow + sr) * K + (kt) * 32 + skh; \
    bool okr = (brow + sr) < M; \
    _Pragma("unroll") \
    for (int i4 = 0; i4 < 4; i4++) { \
        float4 v = okr ? *(const float4*)(Ar + i4 * 4) : make_float4(0.f, 0.f, 0.f, 0.f); \
        unsigned hA, lA, hB, lB; \
        bfsplit2(v.x, v.y, hA, lA); \
        bfsplit2(v.z, v.w, hB, lB); \
        *(uint2*)(dh + sr * A_STRIDE + (skh + i4 * 4) * 2) = make_uint2(hA, hB); \
        *(uint2*)(dl + sr * A_STRIDE + (skh + i4 * 4) * 2) = make_uint2(lA, lB); \
    } \
} while (0)

    STAGE_BD(0, 0);
    STAGE_AD(0, 0);
    CP_WAIT0();
    __syncthreads();

    for (int kt = 0; kt < nkt; kt++) {
        const int buf = kt & 1;
        const bool more = (kt + 1) < nkt;
        if (more) {
            STAGE_BD(buf ^ 1, kt + 1);
            STAGE_AD(buf ^ 1, kt + 1);
        }
        const unsigned sba = sb + buf * ABUF;
#pragma unroll
        for (int ks = 0; ks < 2; ks++) {
            unsigned aoff = sba + (warp_m + arow) * A_STRIDE + (ks * 16 + akq * 8) * 2;
            unsigned boff = sba + OFF_BHI + (ks * 16 + lane16) * B_STRIDE + warp_n * 2;
            unsigned Ah[4][4], Bhf[4][2];
#pragma unroll
            for (int tm = 0; tm < 4; tm++)
                LDSM_X4(Ah[tm][0], Ah[tm][1], Ah[tm][2], Ah[tm][3], aoff + tm * 16 * A_STRIDE);
#pragma unroll
            for (int tn = 0; tn < 4; tn++)
                LDSM_X2T(Bhf[tn][0], Bhf[tn][1], boff + tn * 16);
#pragma unroll
            for (int tm = 0; tm < 4; tm++)
#pragma unroll
                for (int tn = 0; tn < 4; tn++)
                    MMA16816(acc[tm][tn], Ah[tm][0], Ah[tm][1], Ah[tm][2], Ah[tm][3],
                             Bhf[tn][0], Bhf[tn][1]);
            unsigned Blf[4][2];
            unsigned bloff = sba + OFF_BLO + (ks * 16 + lane16) * B_STRIDE + warp_n * 2;
#pragma unroll
            for (int tn = 0; tn < 4; tn++)
                LDSM_X2T(Blf[tn][0], Blf[tn][1], bloff + tn * 16);
#pragma unroll
            for (int tm = 0; tm < 4; tm++)
#pragma unroll
                for (int tn = 0; tn < 4; tn++)
                    MMA16816(acc[tm][tn], Ah[tm][0], Ah[tm][1], Ah[tm][2], Ah[tm][3],
                             Blf[tn][0], Blf[tn][1]);
            unsigned Alf[4][4];
            unsigned aloff = sba + OFF_ALO + (warp_m + arow) * A_STRIDE + (ks * 16 + akq * 8) * 2;
#pragma unroll
            for (int tm = 0; tm < 4; tm++)
                LDSM_X4(Alf[tm][0], Alf[tm][1], Alf[tm][2], Alf[tm][3], aloff + tm * 16 * A_STRIDE);
#pragma unroll
            for (int tm = 0; tm < 4; tm++)
#pragma unroll
                for (int tn = 0; tn < 4; tn++)
                    MMA16816(acc[tm][tn], Alf[tm][0], Alf[tm][1], Alf[tm][2], Alf[tm][3],
                             Bhf[tn][0], Bhf[tn][1]);
        }
        if (more) CP_WAIT0();
        __syncthreads();
    }

#pragma unroll
    for (int tm = 0; tm < 4; tm++) {
#pragma unroll
        for (int tn = 0; tn < 4; tn++) {
            int gcol = col0 + warp_n + tn * 8 + (lane & 3) * 2;
            float bb0 = __ldg(bias + gcol), bb1 = __ldg(bias + gcol + 1);
#pragma unroll
            for (int half = 0; half < 2; half++) {
                int r = brow + warp_m + tm * 16 + (lane >> 2) + half * 8;
                if (r >= M) continue;
                float v0 = fmaxf(acc[tm][tn][half * 2 + 0] + bb0, 0.0f);
                float v1 = fmaxf(acc[tm][tn][half * 2 + 1] + bb1, 0.0f);
                float2 o; o.x = v0; o.y = v1;
                *(float2*)(C + (size_t)r * Ncs + gcol) = o;
            }
        }
    }
}

// ---------------- fused decoder tail ----------------
__global__ __launch_bounds__(128)
void decoder_tail_kernel(const float* __restrict__ din,
                         const float* __restrict__ W2, const float* __restrict__ b2,
                         const float* __restrict__ W3, const float* __restrict__ b3,
                         const float* __restrict__ W4, const float* __restrict__ b4,
                         const float* __restrict__ Wo, const float* __restrict__ bo,
                         const int* __restrict__ batch, float* __restrict__ sums, int M) {
    __shared__ float w2[128 * 64];
    __shared__ float w3[64 * 32];
    __shared__ float w4[32 * 16];
    __shared__ float wo[160];
    __shared__ float xs [4][128];
    __shared__ float t64[4][64];
    __shared__ float t32[4][32];
    __shared__ float t16[4][16];
    for (int i = threadIdx.x; i < 128 * 64; i += 128) w2[i] = W2[i];
    for (int i = threadIdx.x; i < 64 * 32;  i += 128) w3[i] = W3[i];
    for (int i = threadIdx.x; i < 32 * 16;  i += 128) w4[i] = W4[i];
    for (int i = threadIdx.x; i < 160;      i += 128) wo[i] = Wo[i];
    __syncthreads();
    int warp = threadIdx.x >> 5;
    int lane = threadIdx.x & 31;
    int stride = gridDim.x * 4;
    for (int row = blockIdx.x * 4 + warp; row < M; row += stride) {
        *(float4*)&xs[warp][lane * 4] = *(const float4*)(din + (size_t)row * 128 + lane * 4);
        __syncwarp();
        float s0 = b2[lane], s1 = b2[lane + 32];
#pragma unroll 8
        for (int k = 0; k < 128; k++) {
            float xv = xs[warp][k];
            s0 = fmaf(xv, w2[k * 64 + lane],      s0);
            s1 = fmaf(xv, w2[k * 64 + lane + 32], s1);
        }
        t64[warp][lane]      = fmaxf(s0, 0.0f);
        t64[warp][lane + 32] = fmaxf(s1, 0.0f);
        __syncwarp();
        float s = b3[lane];
#pragma unroll 8
        for (int k = 0; k < 64; k++) s = fmaf(t64[warp][k], w3[k * 32 + lane], s);
        t32[warp][lane] = fmaxf(s, 0.0f);
        __syncwarp();
        if (lane < 16) {
            float t = b4[lane];
#pragma unroll
            for (int k = 0; k < 32; k++) t = fmaf(t32[warp][k], w4[k * 16 + lane], t);
            t16[warp][lane] = fmaxf(t, 0.0f);
        }
        __syncwarp();
        if (lane < 10) {
            float t = bo[lane];
#pragma unroll
            for (int k = 0; k < 16; k++) t = fmaf(t16[warp][k], wo[k * 10 + lane], t);
            float yp = __fdividef(1.0f, 1.0f + __expf(-t));
            atomicAdd(&sums[batch[row] * 10 + lane], yp);
        }
        __syncwarp();
    }
}

__global__ void pool_finalize_kernel(const float* __restrict__ sums, const float* __restrict__ cnt,
                                     const float* __restrict__ y,
                                     float* __restrict__ out_pred, float* __restrict__ out_y) {
    int i = blockIdx.x * blockDim.x + threadIdx.x;
    if (i < GG * DOUT_) {
        out_pred[i] = sums[i] / fmaxf(cnt[i / DOUT_], 1.0f);
        out_y[i]    = y[i];
    }
}

// ---------------- launch ----------------
extern "C" void kernel_launch(void* const* d_in, const int* in_sizes, int n_in,
                              void* d_out, int out_size) {
    const float* x     = (const float*)d_in[0];
    const int*   ei    = (const int*)  d_in[1];
    const int*   batch = (const int*)  d_in[2];
    const float* y     = (const float*)d_in[3];
    const float* eps   = (const float*)d_in[4];
    const float* W_in  = (const float*)d_in[5];
    const float* b_in  = (const float*)d_in[6];
    const float* W_gcn = (const float*)d_in[7];
    const float* b_gcn = (const float*)d_in[8];
    const float* W_enc = (const float*)d_in[9];
    const float* b_enc = (const float*)d_in[10];
    const float* W_mu  = (const float*)d_in[11];
    const float* b_mu  = (const float*)d_in[12];
    const float* W_std = (const float*)d_in[13];
    const float* b_std = (const float*)d_in[14];
    const float* Wd0 = (const float*)d_in[15]; const float* bd0 = (const float*)d_in[16];
    const float* Wd1 = (const float*)d_in[17]; const float* bd1 = (const float*)d_in[18];
    const float* Wd2 = (const float*)d_in[19]; const float* bd2 = (const float*)d_in[20];
    const float* Wd3 = (const float*)d_in[21]; const float* bd3 = (const float*)d_in[22];
    const float* Wd4 = (const float*)d_in[23]; const float* bd4 = (const float*)d_in[24];
    const float* Wo  = (const float*)d_in[25]; const float* bo  = (const float*)d_in[26];

    float *h, *u, *gbuf, *dec1, *dinv, *sums, *cnt;
    int *deg, *off, *cur, *csr;
    unsigned short *wh, *wl;
    cudaGetSymbolAddress((void**)&h,    g_h);
    cudaGetSymbolAddress((void**)&u,    g_u);
    cudaGetSymbolAddress((void**)&gbuf, g_g);
    cudaGetSymbolAddress((void**)&dec1, g_dec1);
    cudaGetSymbolAddress((void**)&dinv, g_dinv);
    cudaGetSymbolAddress((void**)&deg,  g_deg);
    cudaGetSymbolAddress((void**)&off,  g_off);
    cudaGetSymbolAddress((void**)&cur,  g_cur);
    cudaGetSymbolAddress((void**)&csr,  g_csr);
    cudaGetSymbolAddress((void**)&sums, g_sums);
    cudaGetSymbolAddress((void**)&cnt,  g_cnt);
    cudaGetSymbolAddress((void**)&wh,   g_wh);
    cudaGetSymbolAddress((void**)&wl,   g_wl);

    float* out      = (float*)d_out;
    float* out_pred = out;
    float* out_mu   = out + GG * DOUT_;
    float* out_std  = out + GG * DOUT_ + (size_t)NN * DL_;
    float* out_y    = out + GG * DOUT_ + (size_t)2 * NN * DL_;

    const int* src = ei;
    const int* dst = ei + EE;

    cudaFuncSetAttribute(mega_kernel, cudaFuncAttributeMaxDynamicSharedMemorySize, MEGA_SMEM);
    cudaFuncSetAttribute(gemm_mma,   cudaFuncAttributeMaxDynamicSharedMemorySize, SMEM_GEMM);

    // weight split blobs: 0 in,1 gcn,2-6 enc,7 mu,8 std,9 Wd0,10 Wd1
    WJobs jobs;
    int O[11];
    {
        int o = 0;
        auto set = [&](int i, const float* W, int elems) {
            jobs.j[i].W = W; jobs.j[i].elems = elems; jobs.j[i].off = o; O[i] = o; o += elems;
        };
        set(0, W_in, 32 * 128);
        set(1, W_gcn, 128 * 128);
        for (int j = 0; j < 5; j++) set(2 + j, W_enc + (size_t)j * DL_ * DL_, 128 * 128);
        set(7, W_mu, 128 * 128);
        set(8, W_std, 128 * 128);
        set(9, Wd0, 128 * 256);
        set(10, Wd1, 256 * 128);
    }
    wsplit_kernel<<<dim3(32, 11), 256>>>(jobs, wh, wl);

    cudaMemsetAsync(deg, 0, NN * sizeof(int));
    count_deg_kernel   <<<(EE + 255) / 256, 256>>>(dst, deg, EE);
    scan_offsets_kernel<<<1, 1024>>>(deg, off, cur, dinv, NN);
    csr_fill_kernel    <<<(EE + 255) / 256, 256>>>(src, dst, cur, csr, EE);

    const int GRID = (NN + 127) / 128;
    const __nv_bfloat16* WH = (const __nv_bfloat16*)wh;
    const __nv_bfloat16* WL = (const __nv_bfloat16*)wl;

    // input: x -> h -> u
    mega_kernel<<<GRID, 256, MEGA_SMEM>>>(0, x, WH, WL, O[0], b_in, O[1], O[2], b_enc,
                                          O[7], b_mu, O[8], b_std, dinv, nullptr,
                                          u, nullptr, nullptr, nullptr, NN);
    for (int it = 0; it < KK; it++) {
        gather_kernel<<<(NN * 32 + 255) / 256, 256>>>(off, csr, u, dinv, b_gcn, gbuf, NN);
        int mode = (it == KK - 1) ? 2 : 1;
        mega_kernel<<<GRID, 256, MEGA_SMEM>>>(mode, gbuf, WH, WL, O[0], b_in, O[1], O[2], b_enc,
                                              O[7], b_mu, O[8], b_std, dinv,
                                              eps + (size_t)it * NN * DL_,
                                              u, out_mu, out_std, h, NN);
    }

    // decoder: h -> 256 (two col-tiles) -> 128 -> tail
    gemm_mma<<<GRID, 256, SMEM_GEMM>>>(h, WH + O[9], WL + O[9], bd0, dec1, NN, 128, 256, 256, 0);
    gemm_mma<<<GRID, 256, SMEM_GEMM>>>(h, WH + O[9] + 128, WL + O[9] + 128, bd0, dec1,
                                       NN, 128, 256, 256, 128);
    gemm_mma<<<GRID, 256, SMEM_GEMM>>>(dec1, WH + O[10], WL + O[10], bd1, u, NN, 256, 128, 128, 0);

    cudaMemsetAsync(sums, 0, GG * DOUT_ * sizeof(float));
    cudaMemsetAsync(cnt,  0, GG * sizeof(float));
    count_nodes_kernel<<<(NN + 255) / 256, 256>>>(batch, cnt, NN);
    decoder_tail_kernel<<<592, 128>>>(u, Wd2, bd2, Wd3, bd3, Wd4, bd4, Wo, bo,
                                      batch, sums, NN);
    pool_finalize_kernel<<<(GG * DOUT_ + 255) / 256, 256>>>(sums, cnt, y, out_pred, out_y);

    (void)in_sizes; (void)n_in; (void)out_size;
}

// round 9
// speedup vs baseline: 2.4245x; 1.0568x over previous
#include <cuda_runtime.h>
#include <cuda_bf16.h>
#include <math.h>

#define NN   50000
#define EE   800000
#define DIN_ 32
#define DL_  128
#define DOUT_ 10
#define GG   256
#define KK   3

// ---------------- scratch (device globals) ----------------
__device__ __align__(16) float g_h  [NN * DL_];
__device__ __align__(16) float g_u  [NN * DL_];
__device__ __align__(16) float g_g  [NN * DL_];
__device__ __align__(16) float g_dec1[NN * 256];
__device__ __align__(16) float g_dinv[NN];
__device__ __align__(16) int   g_deg [NN];
__device__ __align__(16) int   g_off [NN + 1];
__device__ __align__(16) int   g_cur [NN];
__device__ __align__(16) int   g_csr [EE];
__device__ __align__(16) float g_sums[GG * DOUT_];
__device__ __align__(16) float g_cnt [GG];
__device__ __align__(16) unsigned short g_wh[184320];
__device__ __align__(16) unsigned short g_wl[184320];

// ---------------- asm helpers ----------------
__device__ __forceinline__ unsigned smem_u32(const void* p) {
    unsigned a;
    asm("{ .reg .u64 t; cvta.to.shared.u64 t, %1; cvt.u32.u64 %0, t; }" : "=r"(a) : "l"(p));
    return a;
}
#define CP_ASYNC16(dst_u32, src) \
    asm volatile("cp.async.ca.shared.global [%0], [%1], 16;" :: "r"(dst_u32), "l"(src))
#define CP_COMMIT() asm volatile("cp.async.commit_group;")
#define CP_WAIT0()  asm volatile("cp.async.wait_group 0;")
#define LDSM_X4(r0, r1, r2, r3, addr) \
    asm volatile("ldmatrix.sync.aligned.m8n8.x4.shared.b16 {%0,%1,%2,%3}, [%4];" \
                 : "=r"(r0), "=r"(r1), "=r"(r2), "=r"(r3) : "r"(addr))
#define LDSM_X2T(r0, r1, addr) \
    asm volatile("ldmatrix.sync.aligned.m8n8.x2.trans.shared.b16 {%0,%1}, [%2];" \
                 : "=r"(r0), "=r"(r1) : "r"(addr))
#define MMA16816(c, a0, a1, a2, a3, b0, b1) \
    asm volatile("mma.sync.aligned.m16n8k16.row.col.f32.bf16.bf16.f32 " \
                 "{%0,%1,%2,%3}, {%4,%5,%6,%7}, {%8,%9}, {%0,%1,%2,%3};" \
                 : "+f"((c)[0]), "+f"((c)[1]), "+f"((c)[2]), "+f"((c)[3]) \
                 : "r"(a0), "r"(a1), "r"(a2), "r"(a3), "r"(b0), "r"(b1))

__device__ __forceinline__ void bfsplit2(float v0, float v1, unsigned& hi, unsigned& lo) {
    __nv_bfloat16 h0 = __float2bfloat16(v0), h1 = __float2bfloat16(v1);
    float r0 = v0 - __bfloat162float(h0), r1 = v1 - __bfloat162float(h1);
    hi = (unsigned)__bfloat16_as_ushort(h0) | ((unsigned)__bfloat16_as_ushort(h1) << 16);
    lo = (unsigned)__bfloat16_as_ushort(__float2bfloat16(r0)) |
         ((unsigned)__bfloat16_as_ushort(__float2bfloat16(r1)) << 16);
}

// ================= mega kernel smem geometry =================
#define AST    272
#define MS_AH  0
#define MS_AL  34816
#define MS_W0  69632
#define MS_W1  139264
#define MS_MU  139264
#define MEGA_SMEM 208896

// decoder gemm geometry
#define A_STRIDE 80
#define B_STRIDE 272
#define OFF_ALO  10240
#define OFF_BHI  20480
#define OFF_BLO  29184
#define ABUF     37888
#define SMEM_GEMM (2 * ABUF)

// ---------------- preprocessing ----------------
__global__ void count_deg_kernel(const int* __restrict__ dst, int* __restrict__ deg, int E) {
    int i = blockIdx.x * blockDim.x + threadIdx.x;
    if (i < E) atomicAdd(&deg[dst[i]], 1);
}
__global__ void count_nodes_kernel(const int* __restrict__ batch, float* __restrict__ cnt, int M) {
    int i = blockIdx.x * blockDim.x + threadIdx.x;
    if (i < M) atomicAdd(&cnt[batch[i]], 1.0f);
}
__global__ __launch_bounds__(1024)
void scan_offsets_kernel(const int* __restrict__ deg, int* __restrict__ off,
                         int* __restrict__ cursor, float* __restrict__ dinv, int M) {
    __shared__ int part[1024];
    int t = threadIdx.x;
    int chunk = (M + 1023) >> 10;
    int base = t * chunk;
    int s = 0;
    for (int i = 0; i < chunk; i++) { int j = base + i; if (j < M) s += deg[j]; }
    part[t] = s;
    __syncthreads();
    for (int d = 1; d < 1024; d <<= 1) {
        int add = (t >= d) ? part[t - d] : 0;
        __syncthreads();
        part[t] += add;
        __syncthreads();
    }
    int run = part[t] - s;
    for (int i = 0; i < chunk; i++) {
        int j = base + i;
        if (j < M) {
            int dj = deg[j];
            off[j] = run; cursor[j] = run; run += dj;
            dinv[j] = rsqrtf((float)dj + 1.0f);
        }
    }
    if (t == 1023) off[M] = part[1023];
}
__global__ void csr_fill_kernel(const int* __restrict__ src, const int* __restrict__ dst,
                                int* __restrict__ cursor, int* __restrict__ csr, int E) {
    int i = blockIdx.x * blockDim.x + threadIdx.x;
    if (i < E) {
        int p = atomicAdd(&cursor[dst[i]], 1);
        csr[p] = src[i];
    }
}

// ---------------- weight split ----------------
struct WJob { const float* W; int elems; int off; };
struct WJobs { WJob j[11]; };
__global__ void wsplit_kernel(WJobs jobs, unsigned short* __restrict__ wh,
                              unsigned short* __restrict__ wl) {
    WJob jb = jobs.j[blockIdx.y];
    for (int i = blockIdx.x * blockDim.x + threadIdx.x; i < jb.elems;
         i += gridDim.x * blockDim.x) {
        float w = jb.W[i];
        __nv_bfloat16 hb = __float2bfloat16(w);
        __nv_bfloat16 lb = __float2bfloat16(w - __bfloat162float(hb));
        wh[jb.off + i] = __bfloat16_as_ushort(hb);
        wl[jb.off + i] = __bfloat16_as_ushort(lb);
    }
}

// ---------------- gather ----------------
__global__ __launch_bounds__(256)
void gather_kernel(const int* __restrict__ off, const int* __restrict__ csr,
                   const float* __restrict__ u, const float* __restrict__ dinv,
                   const float* __restrict__ bgcn, float* __restrict__ g, int M) {
    int n = (blockIdx.x * blockDim.x + threadIdx.x) >> 5;
    if (n >= M) return;
    int lane = threadIdx.x & 31;
    int e0 = off[n], e1 = off[n + 1];
    int deg = e1 - e0;
    float4 acc = __ldg((const float4*)(u + (size_t)n * DL_ + lane * 4));
    for (int base = 0; base < deg; base += 32) {
        int cnt = min(32, deg - base);
        int idx = 0;
        if (base + lane < deg) idx = __ldg(csr + e0 + base + lane);
        int j = 0;
        for (; j + 8 <= cnt; j += 8) {
            float4 v[8];
#pragma unroll
            for (int q = 0; q < 8; q++) {
                int s = __shfl_sync(0xffffffffu, idx, j + q);
                v[q] = __ldg((const float4*)(u + (size_t)s * DL_ + lane * 4));
            }
#pragma unroll
            for (int q = 0; q < 8; q++) {
                acc.x += v[q].x; acc.y += v[q].y; acc.z += v[q].z; acc.w += v[q].w;
            }
        }
        for (; j < cnt; j++) {
            int s = __shfl_sync(0xffffffffu, idx, j);
            float4 v = __ldg((const float4*)(u + (size_t)s * DL_ + lane * 4));
            acc.x += v.x; acc.y += v.y; acc.z += v.z; acc.w += v.w;
        }
    }
    float dv = dinv[n];
    float4 b = *(const float4*)(bgcn + lane * 4);
    float4 o;
    o.x = fmaf(dv, acc.x, b.x);
    o.y = fmaf(dv, acc.y, b.y);
    o.z = fmaf(dv, acc.z, b.z);
    o.w = fmaf(dv, acc.w, b.w);
    *(float4*)(g + (size_t)n * DL_ + lane * 4) = o;
}

// ================= mega kernel pieces (512 threads, 16 warps, warp tile 32x32) =================
__device__ __forceinline__ void stage_w128(unsigned sb, int woff,
                                           const __nv_bfloat16* Wh, const __nv_bfloat16* Wl,
                                           int nrows, int tid) {
    int chunks = nrows * 16;
    for (int idx = tid; idx < chunks; idx += 512) {
        int rowb = idx >> 4, cc = idx & 15;
        CP_ASYNC16(sb + woff + rowb * AST + cc * 16, (const char*)(Wh + rowb * 128) + cc * 16);
        CP_ASYNC16(sb + woff + 34816 + rowb * AST + cc * 16,
                   (const char*)(Wl + rowb * 128) + cc * 16);
    }
    CP_COMMIT();
}

__device__ __forceinline__ void layer_mma(unsigned sb, int woff,
                                          int warp_m, int warp_n, int lane,
                                          int nks, float acc[2][4][4]) {
#pragma unroll
    for (int i = 0; i < 2; i++)
#pragma unroll
        for (int j = 0; j < 4; j++)
#pragma unroll
            for (int q = 0; q < 4; q++) acc[i][j][q] = 0.0f;
    const int arow = (lane & 7) + ((lane >> 3) & 1) * 8;
    const int akq  = lane >> 4;
    const int lane16 = lane & 15;
    for (int ks = 0; ks < nks; ks++) {
        unsigned aoff = sb + MS_AH + (warp_m + arow) * AST + (ks * 16 + akq * 8) * 2;
        unsigned boff = sb + woff + (ks * 16 + lane16) * AST + warp_n * 2;
        unsigned Ah[2][4], Bhf[4][2];
#pragma unroll
        for (int tm = 0; tm < 2; tm++)
            LDSM_X4(Ah[tm][0], Ah[tm][1], Ah[tm][2], Ah[tm][3], aoff + tm * 16 * AST);
#pragma unroll
        for (int tn = 0; tn < 4; tn++)
            LDSM_X2T(Bhf[tn][0], Bhf[tn][1], boff + tn * 16);
#pragma unroll
        for (int tm = 0; tm < 2; tm++)
#pragma unroll
            for (int tn = 0; tn < 4; tn++)
                MMA16816(acc[tm][tn], Ah[tm][0], Ah[tm][1], Ah[tm][2], Ah[tm][3],
                         Bhf[tn][0], Bhf[tn][1]);
        unsigned Blf[4][2];
        unsigned bloff = boff + 34816;
#pragma unroll
        for (int tn = 0; tn < 4; tn++)
            LDSM_X2T(Blf[tn][0], Blf[tn][1], bloff + tn * 16);
#pragma unroll
        for (int tm = 0; tm < 2; tm++)
#pragma unroll
            for (int tn = 0; tn < 4; tn++)
                MMA16816(acc[tm][tn], Ah[tm][0], Ah[tm][1], Ah[tm][2], Ah[tm][3],
                         Blf[tn][0], Blf[tn][1]);
        unsigned Alf[2][4];
        unsigned aloff = aoff + (MS_AL - MS_AH);
#pragma unroll
        for (int tm = 0; tm < 2; tm++)
            LDSM_X4(Alf[tm][0], Alf[tm][1], Alf[tm][2], Alf[tm][3], aloff + tm * 16 * AST);
#pragma unroll
        for (int tm = 0; tm < 2; tm++)
#pragma unroll
            for (int tn = 0; tn < 4; tn++)
                MMA16816(acc[tm][tn], Alf[tm][0], Alf[tm][1], Alf[tm][2], Alf[tm][3],
                         Bhf[tn][0], Bhf[tn][1]);
    }
}

__device__ __forceinline__ void store_act_sig(char* smem, float acc[2][4][4],
                                              const float* __restrict__ bias,
                                              int warp_m, int warp_n, int lane) {
#pragma unroll
    for (int tn = 0; tn < 4; tn++) {
        int c = warp_n + tn * 8 + (lane & 3) * 2;
        float b0 = __ldg(bias + c), b1 = __ldg(bias + c + 1);
#pragma unroll
        for (int tm = 0; tm < 2; tm++)
#pragma unroll
            for (int half = 0; half < 2; half++) {
                int r = warp_m + tm * 16 + (lane >> 2) + half * 8;
                float v0 = acc[tm][tn][half * 2]     + b0;
                float v1 = acc[tm][tn][half * 2 + 1] + b1;
                v0 = __fdividef(1.0f, 1.0f + __expf(-v0));
                v1 = __fdividef(1.0f, 1.0f + __expf(-v1));
                unsigned hi, lo;
                bfsplit2(v0, v1, hi, lo);
                *(unsigned*)(smem + MS_AH + r * AST + c * 2) = hi;
                *(unsigned*)(smem + MS_AL + r * AST + c * 2) = lo;
            }
    }
}

// mode 0 = input (x -> h -> u); 1 = hop (g -> ... -> u); 2 = last hop (g -> mu,std,h)
__global__ __launch_bounds__(512)
void mega_kernel(int mode, const float* __restrict__ Ain,
                 const __nv_bfloat16* __restrict__ WH, const __nv_bfloat16* __restrict__ WL,
                 int o_first, const float* __restrict__ b_first,
                 int o_gcn, int o_enc0, const float* __restrict__ b_enc,
                 int o_mu, const float* __restrict__ b_mu,
                 int o_std, const float* __restrict__ b_std,
                 const float* __restrict__ dinv, const float* __restrict__ eps_it,
                 float* __restrict__ u_out, float* __restrict__ mu_out,
                 float* __restrict__ std_out, float* __restrict__ h_out, int M) {
    extern __shared__ __align__(16) char smem[];
    const unsigned sb = smem_u32(smem);
    const int tid  = threadIdx.x;
    const int wid  = tid >> 5;
    const int lane = tid & 31;
    const int brow = blockIdx.x * 128;
    const int warp_m = (wid >> 2) * 32;
    const int warp_n = (wid & 3) * 32;

    // ---- stage initial A (fp32 global -> bf16 hi/lo smem) ----
    {
        const int K0 = (mode == 0) ? DIN_ : DL_;
        const int qK = K0 >> 2;
        int row = tid >> 2;
        int c0 = (tid & 3) * qK;
        bool ok = (brow + row) < M;
        const float* Ar = Ain + (size_t)(brow + row) * K0 + c0;
        for (int i4 = 0; i4 < (qK >> 2); i4++) {
            float4 v = ok ? *(const float4*)(Ar + i4 * 4) : make_float4(0.f, 0.f, 0.f, 0.f);
            unsigned h01, l01, h23, l23;
            bfsplit2(v.x, v.y, h01, l01);
            bfsplit2(v.z, v.w, h23, l23);
            int c = c0 + i4 * 4;
            *(uint2*)(smem + MS_AH + row * AST + c * 2) = make_uint2(h01, h23);
            *(uint2*)(smem + MS_AL + row * AST + c * 2) = make_uint2(l01, l23);
        }
    }
    stage_w128(sb, MS_W0, WH + ((mode == 0) ? o_first : o_enc0),
               WL + ((mode == 0) ? o_first : o_enc0), (mode == 0) ? 32 : 128, tid);
    CP_WAIT0();
    __syncthreads();

    float acc[2][4][4];

    if (mode == 0) {
        stage_w128(sb, MS_W1, WH + o_gcn, WL + o_gcn, 128, tid);
        layer_mma(sb, MS_W0, warp_m, warp_n, lane, 2, acc);
        __syncthreads();
        store_act_sig(smem, acc, b_first, warp_m, warp_n, lane);
        CP_WAIT0();
        __syncthreads();
        layer_mma(sb, MS_W1, warp_m, warp_n, lane, 8, acc);
#pragma unroll
        for (int tm = 0; tm < 2; tm++)
#pragma unroll
            for (int half = 0; half < 2; half++) {
                int r = brow + warp_m + tm * 16 + (lane >> 2) + half * 8;
                if (r >= M) continue;
                float rs = __ldg(dinv + r);
#pragma unroll
                for (int tn = 0; tn < 4; tn++) {
                    int c = warp_n + tn * 8 + (lane & 3) * 2;
                    float2 o;
                    o.x = acc[tm][tn][half * 2]     * rs;
                    o.y = acc[tm][tn][half * 2 + 1] * rs;
                    *(float2*)(u_out + (size_t)r * DL_ + c) = o;
                }
            }
        return;
    }

    // ---- hop: enc x5 ----
    for (int j = 0; j < 5; j++) {
        int cb = (j & 1) ? MS_W1 : MS_W0;
        int nb = (j & 1) ? MS_W0 : MS_W1;
        int nxt = (j < 4) ? (o_enc0 + (j + 1) * 16384) : o_mu;
        stage_w128(sb, nb, WH + nxt, WL + nxt, 128, tid);
        layer_mma(sb, cb, warp_m, warp_n, lane, 8, acc);
        __syncthreads();
        store_act_sig(smem, acc, b_enc + j * DL_, warp_m, warp_n, lane);
        CP_WAIT0();
        __syncthreads();
    }
    // ---- mu (W in W1); stage W_std -> W0 ----
    stage_w128(sb, MS_W0, WH + o_std, WL + o_std, 128, tid);
    layer_mma(sb, MS_W1, warp_m, warp_n, lane, 8, acc);
    __syncthreads();
#pragma unroll
    for (int tn = 0; tn < 4; tn++) {
        int c = warp_n + tn * 8 + (lane & 3) * 2;
        float b0 = __ldg(b_mu + c), b1 = __ldg(b_mu + c + 1);
#pragma unroll
        for (int tm = 0; tm < 2; tm++)
#pragma unroll
            for (int half = 0; half < 2; half++) {
                int r = warp_m + tm * 16 + (lane >> 2) + half * 8;
                float2 v;
                v.x = acc[tm][tn][half * 2]     + b0;
                v.y = acc[tm][tn][half * 2 + 1] + b1;
                *(float2*)(smem + MS_MU + r * 528 + c * 4) = v;
                if (mode == 2 && (brow + r) < M)
                    *(float2*)(mu_out + (size_t)(brow + r) * DL_ + c) = v;
            }
    }
    CP_WAIT0();
    __syncthreads();
    // ---- std (W in W0) ----
    layer_mma(sb, MS_W0, warp_m, warp_n, lane, 8, acc);
    __syncthreads();
    if (mode == 1)
        stage_w128(sb, MS_W0, WH + o_gcn, WL + o_gcn, 128, tid);
#pragma unroll
    for (int tn = 0; tn < 4; tn++) {
        int c = warp_n + tn * 8 + (lane & 3) * 2;
        float b0 = __ldg(b_std + c), b1 = __ldg(b_std + c + 1);
#pragma unroll
        for (int tm = 0; tm < 2; tm++)
#pragma unroll
            for (int half = 0; half < 2; half++) {
                int r = warp_m + tm * 16 + (lane >> 2) + half * 8;
                int gr = brow + r;
                float s0 = acc[tm][tn][half * 2]     + b0 - 5.0f;
                float s1 = acc[tm][tn][half * 2 + 1] + b1 - 5.0f;
                s0 = (s0 > 20.0f) ? s0 : log1pf(expf(s0));
                s1 = (s1 > 20.0f) ? s1 : log1pf(expf(s1));
                float2 m = *(const float2*)(smem + MS_MU + r * 528 + c * 4);
                float2 e = make_float2(0.f, 0.f);
                if (gr < M) e = *(const float2*)(eps_it + (size_t)gr * DL_ + c);
                float h0 = fmaf(s0, e.x, m.x);
                float h1 = fmaf(s1, e.y, m.y);
                if (mode == 2 && gr < M) {
                    float2 so; so.x = s0; so.y = s1;
                    *(float2*)(std_out + (size_t)gr * DL_ + c) = so;
                    float2 ho; ho.x = h0; ho.y = h1;
                    *(float2*)(h_out + (size_t)gr * DL_ + c) = ho;
                }
                unsigned hi, lo;
                bfsplit2(h0, h1, hi, lo);
                *(unsigned*)(smem + MS_AH + r * AST + c * 2) = hi;
                *(unsigned*)(smem + MS_AL + r * AST + c * 2) = lo;
            }
    }
    if (mode == 2) return;
    CP_WAIT0();
    __syncthreads();
    // ---- gcn: u = h @ W_gcn * dinv ----
    layer_mma(sb, MS_W0, warp_m, warp_n, lane, 8, acc);
#pragma unroll
    for (int tm = 0; tm < 2; tm++)
#pragma unroll
        for (int half = 0; half < 2; half++) {
            int r = brow + warp_m + tm * 16 + (lane >> 2) + half * 8;
            if (r >= M) continue;
            float rs = __ldg(dinv + r);
#pragma unroll
            for (int tn = 0; tn < 4; tn++) {
                int c = warp_n + tn * 8 + (lane & 3) * 2;
                float2 o;
                o.x = acc[tm][tn][half * 2]     * rs;
                o.y = acc[tm][tn][half * 2 + 1] * rs;
                *(float2*)(u_out + (size_t)r * DL_ + c) = o;
            }
        }
}

// ---------------- decoder GEMM (proven, unchanged) ----------------
__global__ __launch_bounds__(256)
void gemm_mma(const float* __restrict__ A,
              const __nv_bfloat16* __restrict__ Bh, const __nv_bfloat16* __restrict__ Bl,
              const float* __restrict__ bias, float* __restrict__ C,
              int M, int K, int ldb, int Ncs, int col0) {
    extern __shared__ __align__(16) char smem[];
    const unsigned sb = smem_u32(smem);
    const int tid  = threadIdx.x;
    const int wid  = tid >> 5;
    const int lane = tid & 31;
    const int brow = blockIdx.x * 128;
    const int warp_m = (wid >> 2) * 64;
    const int warp_n = (wid & 3) * 32;
    const int arow   = (lane & 7) + ((lane >> 3) & 1) * 8;
    const int akq    = (lane >> 4);
    const int lane16 = lane & 15;

    float acc[4][4][4];
#pragma unroll
    for (int i = 0; i < 4; i++)
#pragma unroll
        for (int j = 0; j < 4; j++)
#pragma unroll
            for (int q = 0; q < 4; q++) acc[i][j][q] = 0.0f;

    const int nkt = K >> 5;
    const int sr  = tid >> 1;
    const int skh = (tid & 1) * 16;

#define STAGE_BD(bufi, kt) do { \
    unsigned dbase = sb + (bufi) * ABUF; \
    _Pragma("unroll") \
    for (int s2 = 0; s2 < 2; s2++) { \
        int idx = tid + s2 * 256; \
        int rowb = idx >> 4, cc = idx & 15; \
        const char* sh = (const char*)(Bh + (size_t)((kt) * 32 + rowb) * ldb) + cc * 16; \
        const char* sl = (const char*)(Bl + (size_t)((kt) * 32 + rowb) * ldb) + cc * 16; \
        CP_ASYNC16(dbase + OFF_BHI + rowb * B_STRIDE + cc * 16, sh); \
        CP_ASYNC16(dbase + OFF_BLO + rowb * B_STRIDE + cc * 16, sl); \
    } \
    CP_COMMIT(); \
} while (0)

#define STAGE_AD(bufi, kt) do { \
    char* dh = smem + (bufi) * ABUF; \
    char* dl = smem + (bufi) * ABUF + OFF_ALO; \
    const float* Ar = A + (size_t)(brow + sr) * K + (kt) * 32 + skh; \
    bool okr = (brow + sr) < M; \
    _Pragma("unroll") \
    for (int i4 = 0; i4 < 4; i4++) { \
        float4 v = okr ? *(const float4*)(Ar + i4 * 4) : make_float4(0.f, 0.f, 0.f, 0.f); \
        unsigned hA, lA, hB, lB; \
        bfsplit2(v.x, v.y, hA, lA); \
        bfsplit2(v.z, v.w, hB, lB); \
        *(uint2*)(dh + sr * A_STRIDE + (skh + i4 * 4) * 2) = make_uint2(hA, hB); \
        *(uint2*)(dl + sr * A_STRIDE + (skh + i4 * 4) * 2) = make_uint2(lA, lB); \
    } \
} while (0)

    STAGE_BD(0, 0);
    STAGE_AD(0, 0);
    CP_WAIT0();
    __syncthreads();

    for (int kt = 0; kt < nkt; kt++) {
        const int buf = kt & 1;
        const bool more = (kt + 1) < nkt;
        if (more) {
            STAGE_BD(buf ^ 1, kt + 1);
            STAGE_AD(buf ^ 1, kt + 1);
        }
        const unsigned sba = sb + buf * ABUF;
#pragma unroll
        for (int ks = 0; ks < 2; ks++) {
            unsigned aoff = sba + (warp_m + arow) * A_STRIDE + (ks * 16 + akq * 8) * 2;
            unsigned boff = sba + OFF_BHI + (ks * 16 + lane16) * B_STRIDE + warp_n * 2;
            unsigned Ah[4][4], Bhf[4][2];
#pragma unroll
            for (int tm = 0; tm < 4; tm++)
                LDSM_X4(Ah[tm][0], Ah[tm][1], Ah[tm][2], Ah[tm][3], aoff + tm * 16 * A_STRIDE);
#pragma unroll
            for (int tn = 0; tn < 4; tn++)
                LDSM_X2T(Bhf[tn][0], Bhf[tn][1], boff + tn * 16);
#pragma unroll
            for (int tm = 0; tm < 4; tm++)
#pragma unroll
                for (int tn = 0; tn < 4; tn++)
                    MMA16816(acc[tm][tn], Ah[tm][0], Ah[tm][1], Ah[tm][2], Ah[tm][3],
                             Bhf[tn][0], Bhf[tn][1]);
            unsigned Blf[4][2];
            unsigned bloff = sba + OFF_BLO + (ks * 16 + lane16) * B_STRIDE + warp_n * 2;
#pragma unroll
            for (int tn = 0; tn < 4; tn++)
                LDSM_X2T(Blf[tn][0], Blf[tn][1], bloff + tn * 16);
#pragma unroll
            for (int tm = 0; tm < 4; tm++)
#pragma unroll
                for (int tn = 0; tn < 4; tn++)
                    MMA16816(acc[tm][tn], Ah[tm][0], Ah[tm][1], Ah[tm][2], Ah[tm][3],
                             Blf[tn][0], Blf[tn][1]);
            unsigned Alf[4][4];
            unsigned aloff = sba + OFF_ALO + (warp_m + arow) * A_STRIDE + (ks * 16 + akq * 8) * 2;
#pragma unroll
            for (int tm = 0; tm < 4; tm++)
                LDSM_X4(Alf[tm][0], Alf[tm][1], Alf[tm][2], Alf[tm][3], aloff + tm * 16 * A_STRIDE);
#pragma unroll
            for (int tm = 0; tm < 4; tm++)
#pragma unroll
                for (int tn = 0; tn < 4; tn++)
                    MMA16816(acc[tm][tn], Alf[tm][0], Alf[tm][1], Alf[tm][2], Alf[tm][3],
                             Bhf[tn][0], Bhf[tn][1]);
        }
        if (more) CP_WAIT0();
        __syncthreads();
    }

#pragma unroll
    for (int tm = 0; tm < 4; tm++) {
#pragma unroll
        for (int tn = 0; tn < 4; tn++) {
            int gcol = col0 + warp_n + tn * 8 + (lane & 3) * 2;
            float bb0 = __ldg(bias + gcol), bb1 = __ldg(bias + gcol + 1);
#pragma unroll
            for (int half = 0; half < 2; half++) {
                int r = brow + warp_m + tm * 16 + (lane >> 2) + half * 8;
                if (r >= M) continue;
                float v0 = fmaxf(acc[tm][tn][half * 2 + 0] + bb0, 0.0f);
                float v1 = fmaxf(acc[tm][tn][half * 2 + 1] + bb1, 0.0f);
                float2 o; o.x = v0; o.y = v1;
                *(float2*)(C + (size_t)r * Ncs + gcol) = o;
            }
        }
    }
}

// ---------------- fused decoder tail ----------------
__global__ __launch_bounds__(128)
void decoder_tail_kernel(const float* __restrict__ din,
                         const float* __restrict__ W2, const float* __restrict__ b2,
                         const float* __restrict__ W3, const float* __restrict__ b3,
                         const float* __restrict__ W4, const float* __restrict__ b4,
                         const float* __restrict__ Wo, const float* __restrict__ bo,
                         const int* __restrict__ batch, float* __restrict__ sums, int M) {
    __shared__ float w2[128 * 64];
    __shared__ float w3[64 * 32];
    __shared__ float w4[32 * 16];
    __shared__ float wo[160];
    __shared__ float xs [4][128];
    __shared__ float t64[4][64];
    __shared__ float t32[4][32];
    __shared__ float t16[4][16];
    for (int i = threadIdx.x; i < 128 * 64; i += 128) w2[i] = W2[i];
    for (int i = threadIdx.x; i < 64 * 32;  i += 128) w3[i] = W3[i];
    for (int i = threadIdx.x; i < 32 * 16;  i += 128) w4[i] = W4[i];
    for (int i = threadIdx.x; i < 160;      i += 128) wo[i] = Wo[i];
    __syncthreads();
    int warp = threadIdx.x >> 5;
    int lane = threadIdx.x & 31;
    int stride = gridDim.x * 4;
    for (int row = blockIdx.x * 4 + warp; row < M; row += stride) {
        *(float4*)&xs[warp][lane * 4] = *(const float4*)(din + (size_t)row * 128 + lane * 4);
        __syncwarp();
        float s0 = b2[lane], s1 = b2[lane + 32];
#pragma unroll 8
        for (int k = 0; k < 128; k++) {
            float xv = xs[warp][k];
            s0 = fmaf(xv, w2[k * 64 + lane],      s0);
            s1 = fmaf(xv, w2[k * 64 + lane + 32], s1);
        }
        t64[warp][lane]      = fmaxf(s0, 0.0f);
        t64[warp][lane + 32] = fmaxf(s1, 0.0f);
        __syncwarp();
        float s = b3[lane];
#pragma unroll 8
        for (int k = 0; k < 64; k++) s = fmaf(t64[warp][k], w3[k * 32 + lane], s);
        t32[warp][lane] = fmaxf(s, 0.0f);
        __syncwarp();
        if (lane < 16) {
            float t = b4[lane];
#pragma unroll
            for (int k = 0; k < 32; k++) t = fmaf(t32[warp][k], w4[k * 16 + lane], t);
            t16[warp][lane] = fmaxf(t, 0.0f);
        }
        __syncwarp();
        if (lane < 10) {
            float t = bo[lane];
#pragma unroll
            for (int k = 0; k < 16; k++) t = fmaf(t16[warp][k], wo[k * 10 + lane], t);
            float yp = __fdividef(1.0f, 1.0f + __expf(-t));
            atomicAdd(&sums[batch[row] * 10 + lane], yp);
        }
        __syncwarp();
    }
}

__global__ void pool_finalize_kernel(const float* __restrict__ sums, const float* __restrict__ cnt,
                                     const float* __restrict__ y,
                                     float* __restrict__ out_pred, float* __restrict__ out_y) {
    int i = blockIdx.x * blockDim.x + threadIdx.x;
    if (i < GG * DOUT_) {
        out_pred[i] = sums[i] / fmaxf(cnt[i / DOUT_], 1.0f);
        out_y[i]    = y[i];
    }
}

// ---------------- launch ----------------
extern "C" void kernel_launch(void* const* d_in, const int* in_sizes, int n_in,
                              void* d_out, int out_size) {
    const float* x     = (const float*)d_in[0];
    const int*   ei    = (const int*)  d_in[1];
    const int*   batch = (const int*)  d_in[2];
    const float* y     = (const float*)d_in[3];
    const float* eps   = (const float*)d_in[4];
    const float* W_in  = (const float*)d_in[5];
    const float* b_in  = (const float*)d_in[6];
    const float* W_gcn = (const float*)d_in[7];
    const float* b_gcn = (const float*)d_in[8];
    const float* W_enc = (const float*)d_in[9];
    const float* b_enc = (const float*)d_in[10];
    const float* W_mu  = (const float*)d_in[11];
    const float* b_mu  = (const float*)d_in[12];
    const float* W_std = (const float*)d_in[13];
    const float* b_std = (const float*)d_in[14];
    const float* Wd0 = (const float*)d_in[15]; const float* bd0 = (const float*)d_in[16];
    const float* Wd1 = (const float*)d_in[17]; const float* bd1 = (const float*)d_in[18];
    const float* Wd2 = (const float*)d_in[19]; const float* bd2 = (const float*)d_in[20];
    const float* Wd3 = (const float*)d_in[21]; const float* bd3 = (const float*)d_in[22];
    const float* Wd4 = (const float*)d_in[23]; const float* bd4 = (const float*)d_in[24];
    const float* Wo  = (const float*)d_in[25]; const float* bo  = (const float*)d_in[26];

    float *h, *u, *gbuf, *dec1, *dinv, *sums, *cnt;
    int *deg, *off, *cur, *csr;
    unsigned short *wh, *wl;
    cudaGetSymbolAddress((void**)&h,    g_h);
    cudaGetSymbolAddress((void**)&u,    g_u);
    cudaGetSymbolAddress((void**)&gbuf, g_g);
    cudaGetSymbolAddress((void**)&dec1, g_dec1);
    cudaGetSymbolAddress((void**)&dinv, g_dinv);
    cudaGetSymbolAddress((void**)&deg,  g_deg);
    cudaGetSymbolAddress((void**)&off,  g_off);
    cudaGetSymbolAddress((void**)&cur,  g_cur);
    cudaGetSymbolAddress((void**)&csr,  g_csr);
    cudaGetSymbolAddress((void**)&sums, g_sums);
    cudaGetSymbolAddress((void**)&cnt,  g_cnt);
    cudaGetSymbolAddress((void**)&wh,   g_wh);
    cudaGetSymbolAddress((void**)&wl,   g_wl);

    float* out      = (float*)d_out;
    float* out_pred = out;
    float* out_mu   = out + GG * DOUT_;
    float* out_std  = out + GG * DOUT_ + (size_t)NN * DL_;
    float* out_y    = out + GG * DOUT_ + (size_t)2 * NN * DL_;

    const int* src = ei;
    const int* dst = ei + EE;

    cudaFuncSetAttribute(mega_kernel, cudaFuncAttributeMaxDynamicSharedMemorySize, MEGA_SMEM);
    cudaFuncSetAttribute(gemm_mma,   cudaFuncAttributeMaxDynamicSharedMemorySize, SMEM_GEMM);

    WJobs jobs;
    int O[11];
    {
        int o = 0;
        auto set = [&](int i, const float* W, int elems) {
            jobs.j[i].W = W; jobs.j[i].elems = elems; jobs.j[i].off = o; O[i] = o; o += elems;
        };
        set(0, W_in, 32 * 128);
        set(1, W_gcn, 128 * 128);
        for (int j = 0; j < 5; j++) set(2 + j, W_enc + (size_t)j * DL_ * DL_, 128 * 128);
        set(7, W_mu, 128 * 128);
        set(8, W_std, 128 * 128);
        set(9, Wd0, 128 * 256);
        set(10, Wd1, 256 * 128);
    }
    const int GRID = (NN + 127) / 128;
    const __nv_bfloat16* WH = (const __nv_bfloat16*)wh;
    const __nv_bfloat16* WL = (const __nv_bfloat16*)wl;

    // order chosen so mega0 is the 5th kernel launch (ncu -s 5 capture slot)
    wsplit_kernel<<<dim3(32, 11), 256>>>(jobs, wh, wl);
    cudaMemsetAsync(deg, 0, NN * sizeof(int));
    count_deg_kernel   <<<(EE + 255) / 256, 256>>>(dst, deg, EE);
    scan_offsets_kernel<<<1, 1024>>>(deg, off, cur, dinv, NN);
    // input: x -> h -> u   (needs wsplit + dinv only)
    mega_kernel<<<GRID, 512, MEGA_SMEM>>>(0, x, WH, WL, O[0], b_in, O[1], O[2], b_enc,
                                          O[7], b_mu, O[8], b_std, dinv, nullptr,
                                          u, nullptr, nullptr, nullptr, NN);
    csr_fill_kernel    <<<(EE + 255) / 256, 256>>>(src, dst, cur, csr, EE);

    for (int it = 0; it < KK; it++) {
        gather_kernel<<<(NN * 32 + 255) / 256, 256>>>(off, csr, u, dinv, b_gcn, gbuf, NN);
        int mode = (it == KK - 1) ? 2 : 1;
        mega_kernel<<<GRID, 512, MEGA_SMEM>>>(mode, gbuf, WH, WL, O[0], b_in, O[1], O[2], b_enc,
                                              O[7], b_mu, O[8], b_std, dinv,
                                              eps + (size_t)it * NN * DL_,
                                              u, out_mu, out_std, h, NN);
    }

    gemm_mma<<<GRID, 256, SMEM_GEMM>>>(h, WH + O[9], WL + O[9], bd0, dec1, NN, 128, 256, 256, 0);
    gemm_mma<<<GRID, 256, SMEM_GEMM>>>(h, WH + O[9] + 128, WL + O[9] + 128, bd0, dec1,
                                       NN, 128, 256, 256, 128);
    gemm_mma<<<GRID, 256, SMEM_GEMM>>>(dec1, WH + O[10], WL + O[10], bd1, u, NN, 256, 128, 128, 0);

    cudaMemsetAsync(sums, 0, GG * DOUT_ * sizeof(float));
    cudaMemsetAsync(cnt,  0, GG * sizeof(float));
    count_nodes_kernel<<<(NN + 255) / 256, 256>>>(batch, cnt, NN);
    decoder_tail_kernel<<<592, 128>>>(u, Wd2, bd2, Wd3, bd3, Wd4, bd4, Wo, bo,
                                      batch, sums, NN);
    pool_finalize_kernel<<<(GG * DOUT_ + 255) / 256, 256>>>(sums, cnt, y, out_pred, out_y);

    (void)in_sizes; (void)n_in; (void)out_size;
}

// round 10
// speedup vs baseline: 2.9051x; 1.1982x over previous
#include <cuda_runtime.h>
#include <cuda_bf16.h>
#include <cuda_fp16.h>
#include <math.h>

#define NN   50000
#define EE   800000
#define DIN_ 32
#define DL_  128
#define DOUT_ 10
#define GG   256
#define KK   3

// ---------------- scratch (device globals) ----------------
__device__ __align__(16) float g_h  [NN * DL_];
__device__ __align__(16) float g_u  [NN * DL_];
__device__ __align__(16) float g_g  [NN * DL_];
__device__ __align__(16) float g_dec1[NN * 256];
__device__ __align__(16) float g_dinv[NN];
__device__ __align__(16) int   g_deg [NN];
__device__ __align__(16) int   g_off [NN + 1];
__device__ __align__(16) int   g_cur [NN];
__device__ __align__(16) int   g_csr [EE];
__device__ __align__(16) float g_sums[GG * DOUT_];
__device__ __align__(16) float g_cnt [GG];
__device__ __align__(16) unsigned short g_wh[184320];
__device__ __align__(16) unsigned short g_wl[184320];

// ---------------- asm helpers ----------------
__device__ __forceinline__ unsigned smem_u32(const void* p) {
    unsigned a;
    asm("{ .reg .u64 t; cvta.to.shared.u64 t, %1; cvt.u32.u64 %0, t; }" : "=r"(a) : "l"(p));
    return a;
}
#define CP_ASYNC16(dst_u32, src) \
    asm volatile("cp.async.ca.shared.global [%0], [%1], 16;" :: "r"(dst_u32), "l"(src))
#define CP_COMMIT() asm volatile("cp.async.commit_group;")
#define CP_WAIT0()  asm volatile("cp.async.wait_group 0;")
#define LDSM_X4(r0, r1, r2, r3, addr) \
    asm volatile("ldmatrix.sync.aligned.m8n8.x4.shared.b16 {%0,%1,%2,%3}, [%4];" \
                 : "=r"(r0), "=r"(r1), "=r"(r2), "=r"(r3) : "r"(addr))
#define LDSM_X2T(r0, r1, addr) \
    asm volatile("ldmatrix.sync.aligned.m8n8.x2.trans.shared.b16 {%0,%1}, [%2];" \
                 : "=r"(r0), "=r"(r1) : "r"(addr))
#define MMAF16(c, a0, a1, a2, a3, b0, b1) \
    asm volatile("mma.sync.aligned.m16n8k16.row.col.f32.f16.f16.f32 " \
                 "{%0,%1,%2,%3}, {%4,%5,%6,%7}, {%8,%9}, {%0,%1,%2,%3};" \
                 : "+f"((c)[0]), "+f"((c)[1]), "+f"((c)[2]), "+f"((c)[3]) \
                 : "r"(a0), "r"(a1), "r"(a2), "r"(a3), "r"(b0), "r"(b1))

__device__ __forceinline__ unsigned hpack2(float a, float b) {
    __half2 h = __floats2half2_rn(a, b);
    return *(unsigned*)&h;
}

// ================= mega kernel smem geometry (A fp16 hi only; W fp16 hi+lo) ==
#define AST    272
#define MS_AH  0
#define MS_W0  34816
#define MS_W1  104448
#define MS_MU  104448              // fp32 mu parks in W1 region (stride 528)
#define WLO    34816               // lo offset inside a W region
#define MEGA_SMEM 174080

// decoder gemm geometry
#define A_STRIDE 80
#define B_STRIDE 272
#define OFF_BHI  10240
#define OFF_BLO  18944
#define ABUF     27648
#define SMEM_GEMM (2 * ABUF)

// ---------------- preprocessing ----------------
__global__ void count_deg_kernel(const int* __restrict__ dst, int* __restrict__ deg, int E) {
    int i = blockIdx.x * blockDim.x + threadIdx.x;
    if (i < E) atomicAdd(&deg[dst[i]], 1);
}
__global__ void count_nodes_kernel(const int* __restrict__ batch, float* __restrict__ cnt, int M) {
    int i = blockIdx.x * blockDim.x + threadIdx.x;
    if (i < M) atomicAdd(&cnt[batch[i]], 1.0f);
}
__global__ __launch_bounds__(1024)
void scan_offsets_kernel(const int* __restrict__ deg, int* __restrict__ off,
                         int* __restrict__ cursor, float* __restrict__ dinv, int M) {
    __shared__ int part[1024];
    int t = threadIdx.x;
    int chunk = (M + 1023) >> 10;
    int base = t * chunk;
    int s = 0;
    for (int i = 0; i < chunk; i++) { int j = base + i; if (j < M) s += deg[j]; }
    part[t] = s;
    __syncthreads();
    for (int d = 1; d < 1024; d <<= 1) {
        int add = (t >= d) ? part[t - d] : 0;
        __syncthreads();
        part[t] += add;
        __syncthreads();
    }
    int run = part[t] - s;
    for (int i = 0; i < chunk; i++) {
        int j = base + i;
        if (j < M) {
            int dj = deg[j];
            off[j] = run; cursor[j] = run; run += dj;
            dinv[j] = rsqrtf((float)dj + 1.0f);
        }
    }
    if (t == 1023) off[M] = part[1023];
}
__global__ void csr_fill_kernel(const int* __restrict__ src, const int* __restrict__ dst,
                                int* __restrict__ cursor, int* __restrict__ csr, int E) {
    int i = blockIdx.x * blockDim.x + threadIdx.x;
    if (i < E) {
        int p = atomicAdd(&cursor[dst[i]], 1);
        csr[p] = src[i];
    }
}

// ---------------- weight split (fp16 hi/lo) ----------------
struct WJob { const float* W; int elems; int off; };
struct WJobs { WJob j[11]; };
__global__ void wsplit_kernel(WJobs jobs, unsigned short* __restrict__ wh,
                              unsigned short* __restrict__ wl) {
    WJob jb = jobs.j[blockIdx.y];
    for (int i = blockIdx.x * blockDim.x + threadIdx.x; i < jb.elems;
         i += gridDim.x * blockDim.x) {
        float w = jb.W[i];
        __half hb = __float2half_rn(w);
        __half lb = __float2half_rn(w - __half2float(hb));
        wh[jb.off + i] = __half_as_ushort(hb);
        wl[jb.off + i] = __half_as_ushort(lb);
    }
}

// ---------------- gather ----------------
__global__ __launch_bounds__(256)
void gather_kernel(const int* __restrict__ off, const int* __restrict__ csr,
                   const float* __restrict__ u, const float* __restrict__ dinv,
                   const float* __restrict__ bgcn, float* __restrict__ g, int M) {
    int n = (blockIdx.x * blockDim.x + threadIdx.x) >> 5;
    if (n >= M) return;
    int lane = threadIdx.x & 31;
    int e0 = off[n], e1 = off[n + 1];
    int deg = e1 - e0;
    float4 acc = __ldg((const float4*)(u + (size_t)n * DL_ + lane * 4));
    for (int base = 0; base < deg; base += 32) {
        int cnt = min(32, deg - base);
        int idx = 0;
        if (base + lane < deg) idx = __ldg(csr + e0 + base + lane);
        int j = 0;
        for (; j + 8 <= cnt; j += 8) {
            float4 v[8];
#pragma unroll
            for (int q = 0; q < 8; q++) {
                int s = __shfl_sync(0xffffffffu, idx, j + q);
                v[q] = __ldg((const float4*)(u + (size_t)s * DL_ + lane * 4));
            }
#pragma unroll
            for (int q = 0; q < 8; q++) {
                acc.x += v[q].x; acc.y += v[q].y; acc.z += v[q].z; acc.w += v[q].w;
            }
        }
        for (; j < cnt; j++) {
            int s = __shfl_sync(0xffffffffu, idx, j);
            float4 v = __ldg((const float4*)(u + (size_t)s * DL_ + lane * 4));
            acc.x += v.x; acc.y += v.y; acc.z += v.z; acc.w += v.w;
        }
    }
    float dv = dinv[n];
    float4 b = *(const float4*)(bgcn + lane * 4);
    float4 o;
    o.x = fmaf(dv, acc.x, b.x);
    o.y = fmaf(dv, acc.y, b.y);
    o.z = fmaf(dv, acc.z, b.z);
    o.w = fmaf(dv, acc.w, b.w);
    *(float4*)(g + (size_t)n * DL_ + lane * 4) = o;
}

// ================= mega kernel pieces (512 threads, warp tile 32x32, fp16 2-product) =====
__device__ __forceinline__ void stage_w128(unsigned sb, int woff,
                                           const __half* Wh, const __half* Wl,
                                           int nrows, int tid) {
    int chunks = nrows * 16;
    for (int idx = tid; idx < chunks; idx += 512) {
        int rowb = idx >> 4, cc = idx & 15;
        CP_ASYNC16(sb + woff + rowb * AST + cc * 16, (const char*)(Wh + rowb * 128) + cc * 16);
        CP_ASYNC16(sb + woff + WLO + rowb * AST + cc * 16,
                   (const char*)(Wl + rowb * 128) + cc * 16);
    }
    CP_COMMIT();
}

__device__ __forceinline__ void layer_mma(unsigned sb, int woff,
                                          int warp_m, int warp_n, int lane,
                                          int nks, float acc[2][4][4]) {
#pragma unroll
    for (int i = 0; i < 2; i++)
#pragma unroll
        for (int j = 0; j < 4; j++)
#pragma unroll
            for (int q = 0; q < 4; q++) acc[i][j][q] = 0.0f;
    const int arow = (lane & 7) + ((lane >> 3) & 1) * 8;
    const int akq  = lane >> 4;
    const int lane16 = lane & 15;
    for (int ks = 0; ks < nks; ks++) {
        unsigned aoff = sb + MS_AH + (warp_m + arow) * AST + (ks * 16 + akq * 8) * 2;
        unsigned boff = sb + woff + (ks * 16 + lane16) * AST + warp_n * 2;
        unsigned Ah[2][4], Bhf[4][2];
#pragma unroll
        for (int tm = 0; tm < 2; tm++)
            LDSM_X4(Ah[tm][0], Ah[tm][1], Ah[tm][2], Ah[tm][3], aoff + tm * 16 * AST);
#pragma unroll
        for (int tn = 0; tn < 4; tn++)
            LDSM_X2T(Bhf[tn][0], Bhf[tn][1], boff + tn * 16);
#pragma unroll
        for (int tm = 0; tm < 2; tm++)
#pragma unroll
            for (int tn = 0; tn < 4; tn++)
                MMAF16(acc[tm][tn], Ah[tm][0], Ah[tm][1], Ah[tm][2], Ah[tm][3],
                       Bhf[tn][0], Bhf[tn][1]);
        unsigned Blf[4][2];
        unsigned bloff = boff + WLO;
#pragma unroll
        for (int tn = 0; tn < 4; tn++)
            LDSM_X2T(Blf[tn][0], Blf[tn][1], bloff + tn * 16);
#pragma unroll
        for (int tm = 0; tm < 2; tm++)
#pragma unroll
            for (int tn = 0; tn < 4; tn++)
                MMAF16(acc[tm][tn], Ah[tm][0], Ah[tm][1], Ah[tm][2], Ah[tm][3],
                       Blf[tn][0], Blf[tn][1]);
    }
}

__device__ __forceinline__ void store_act_sig(char* smem, float acc[2][4][4],
                                              const float* __restrict__ bias,
                                              int warp_m, int warp_n, int lane) {
#pragma unroll
    for (int tn = 0; tn < 4; tn++) {
        int c = warp_n + tn * 8 + (lane & 3) * 2;
        float b0 = __ldg(bias + c), b1 = __ldg(bias + c + 1);
#pragma unroll
        for (int tm = 0; tm < 2; tm++)
#pragma unroll
            for (int half = 0; half < 2; half++) {
                int r = warp_m + tm * 16 + (lane >> 2) + half * 8;
                float v0 = acc[tm][tn][half * 2]     + b0;
                float v1 = acc[tm][tn][half * 2 + 1] + b1;
                v0 = __fdividef(1.0f, 1.0f + __expf(-v0));
                v1 = __fdividef(1.0f, 1.0f + __expf(-v1));
                *(unsigned*)(smem + MS_AH + r * AST + c * 2) = hpack2(v0, v1);
            }
    }
}

// mode 0 = input (x -> h -> u); 1 = hop (g -> ... -> u); 2 = last hop (g -> mu,std,h)
__global__ __launch_bounds__(512)
void mega_kernel(int mode, const float* __restrict__ Ain,
                 const __half* __restrict__ WH, const __half* __restrict__ WL,
                 int o_first, const float* __restrict__ b_first,
                 int o_gcn, int o_enc0, const float* __restrict__ b_enc,
                 int o_mu, const float* __restrict__ b_mu,
                 int o_std, const float* __restrict__ b_std,
                 const float* __restrict__ dinv, const float* __restrict__ eps_it,
                 float* __restrict__ u_out, float* __restrict__ mu_out,
                 float* __restrict__ std_out, float* __restrict__ h_out, int M) {
    extern __shared__ __align__(16) char smem[];
    const unsigned sb = smem_u32(smem);
    const int tid  = threadIdx.x;
    const int wid  = tid >> 5;
    const int lane = tid & 31;
    const int brow = blockIdx.x * 128;
    const int warp_m = (wid >> 2) * 32;
    const int warp_n = (wid & 3) * 32;

    // ---- stage initial A (fp32 global -> fp16 smem) ----
    {
        const int K0 = (mode == 0) ? DIN_ : DL_;
        const int qK = K0 >> 2;
        int row = tid >> 2;
        int c0 = (tid & 3) * qK;
        bool ok = (brow + row) < M;
        const float* Ar = Ain + (size_t)(brow + row) * K0 + c0;
        for (int i4 = 0; i4 < (qK >> 2); i4++) {
            float4 v = ok ? *(const float4*)(Ar + i4 * 4) : make_float4(0.f, 0.f, 0.f, 0.f);
            int c = c0 + i4 * 4;
            *(uint2*)(smem + MS_AH + row * AST + c * 2) =
                make_uint2(hpack2(v.x, v.y), hpack2(v.z, v.w));
        }
    }
    stage_w128(sb, MS_W0, WH + ((mode == 0) ? o_first : o_enc0),
               WL + ((mode == 0) ? o_first : o_enc0), (mode == 0) ? 32 : 128, tid);
    CP_WAIT0();
    __syncthreads();

    float acc[2][4][4];

    if (mode == 0) {
        stage_w128(sb, MS_W1, WH + o_gcn, WL + o_gcn, 128, tid);
        layer_mma(sb, MS_W0, warp_m, warp_n, lane, 2, acc);
        __syncthreads();
        store_act_sig(smem, acc, b_first, warp_m, warp_n, lane);
        CP_WAIT0();
        __syncthreads();
        layer_mma(sb, MS_W1, warp_m, warp_n, lane, 8, acc);
#pragma unroll
        for (int tm = 0; tm < 2; tm++)
#pragma unroll
            for (int half = 0; half < 2; half++) {
                int r = brow + warp_m + tm * 16 + (lane >> 2) + half * 8;
                if (r >= M) continue;
                float rs = __ldg(dinv + r);
#pragma unroll
                for (int tn = 0; tn < 4; tn++) {
                    int c = warp_n + tn * 8 + (lane & 3) * 2;
                    float2 o;
                    o.x = acc[tm][tn][half * 2]     * rs;
                    o.y = acc[tm][tn][half * 2 + 1] * rs;
                    *(float2*)(u_out + (size_t)r * DL_ + c) = o;
                }
            }
        return;
    }

    // ---- hop: enc x5 ----
    for (int j = 0; j < 5; j++) {
        int cb = (j & 1) ? MS_W1 : MS_W0;
        int nb = (j & 1) ? MS_W0 : MS_W1;
        int nxt = (j < 4) ? (o_enc0 + (j + 1) * 16384) : o_mu;
        stage_w128(sb, nb, WH + nxt, WL + nxt, 128, tid);
        layer_mma(sb, cb, warp_m, warp_n, lane, 8, acc);
        __syncthreads();
        store_act_sig(smem, acc, b_enc + j * DL_, warp_m, warp_n, lane);
        CP_WAIT0();
        __syncthreads();
    }
    // ---- mu (W in W1); stage W_std -> W0 ----
    stage_w128(sb, MS_W0, WH + o_std, WL + o_std, 128, tid);
    layer_mma(sb, MS_W1, warp_m, warp_n, lane, 8, acc);
    __syncthreads();   // all warps done reading W_mu (W1) before MU parks there
#pragma unroll
    for (int tn = 0; tn < 4; tn++) {
        int c = warp_n + tn * 8 + (lane & 3) * 2;
        float b0 = __ldg(b_mu + c), b1 = __ldg(b_mu + c + 1);
#pragma unroll
        for (int tm = 0; tm < 2; tm++)
#pragma unroll
            for (int half = 0; half < 2; half++) {
                int r = warp_m + tm * 16 + (lane >> 2) + half * 8;
                float2 v;
                v.x = acc[tm][tn][half * 2]     + b0;
                v.y = acc[tm][tn][half * 2 + 1] + b1;
                *(float2*)(smem + MS_MU + r * 528 + c * 4) = v;
                if (mode == 2 && (brow + r) < M)
                    *(float2*)(mu_out + (size_t)(brow + r) * DL_ + c) = v;
            }
    }
    CP_WAIT0();
    __syncthreads();
    // ---- std (W in W0) ----
    layer_mma(sb, MS_W0, warp_m, warp_n, lane, 8, acc);
    __syncthreads();
    if (mode == 1)
        stage_w128(sb, MS_W0, WH + o_gcn, WL + o_gcn, 128, tid);
#pragma unroll
    for (int tn = 0; tn < 4; tn++) {
        int c = warp_n + tn * 8 + (lane & 3) * 2;
        float b0 = __ldg(b_std + c), b1 = __ldg(b_std + c + 1);
#pragma unroll
        for (int tm = 0; tm < 2; tm++)
#pragma unroll
            for (int half = 0; half < 2; half++) {
                int r = warp_m + tm * 16 + (lane >> 2) + half * 8;
                int gr = brow + r;
                float s0 = acc[tm][tn][half * 2]     + b0 - 5.0f;
                float s1 = acc[tm][tn][half * 2 + 1] + b1 - 5.0f;
                s0 = (s0 > 20.0f) ? s0 : log1pf(expf(s0));
                s1 = (s1 > 20.0f) ? s1 : log1pf(expf(s1));
                float2 m = *(const float2*)(smem + MS_MU + r * 528 + c * 4);
                float2 e = make_float2(0.f, 0.f);
                if (gr < M) e = *(const float2*)(eps_it + (size_t)gr * DL_ + c);
                float h0 = fmaf(s0, e.x, m.x);
                float h1 = fmaf(s1, e.y, m.y);
                if (mode == 2 && gr < M) {
                    float2 so; so.x = s0; so.y = s1;
                    *(float2*)(std_out + (size_t)gr * DL_ + c) = so;
                    float2 ho; ho.x = h0; ho.y = h1;
                    *(float2*)(h_out + (size_t)gr * DL_ + c) = ho;
                }
                *(unsigned*)(smem + MS_AH + r * AST + c * 2) = hpack2(h0, h1);
            }
    }
    if (mode == 2) return;
    CP_WAIT0();
    __syncthreads();
    // ---- gcn: u = h @ W_gcn * dinv ----
    layer_mma(sb, MS_W0, warp_m, warp_n, lane, 8, acc);
#pragma unroll
    for (int tm = 0; tm < 2; tm++)
#pragma unroll
        for (int half = 0; half < 2; half++) {
            int r = brow + warp_m + tm * 16 + (lane >> 2) + half * 8;
            if (r >= M) continue;
            float rs = __ldg(dinv + r);
#pragma unroll
            for (int tn = 0; tn < 4; tn++) {
                int c = warp_n + tn * 8 + (lane & 3) * 2;
                float2 o;
                o.x = acc[tm][tn][half * 2]     * rs;
                o.y = acc[tm][tn][half * 2 + 1] * rs;
                *(float2*)(u_out + (size_t)r * DL_ + c) = o;
            }
        }
}

// ---------------- decoder GEMM (fp16 2-product) ----------------
__global__ __launch_bounds__(256)
void gemm_mma(const float* __restrict__ A,
              const __half* __restrict__ Bh, const __half* __restrict__ Bl,
              const float* __restrict__ bias, float* __restrict__ C,
              int M, int K, int ldb, int Ncs, int col0) {
    extern __shared__ __align__(16) char smem[];
    const unsigned sb = smem_u32(smem);
    const int tid  = threadIdx.x;
    const int wid  = tid >> 5;
    const int lane = tid & 31;
    const int brow = blockIdx.x * 128;
    const int warp_m = (wid >> 2) * 64;
    const int warp_n = (wid & 3) * 32;
    const int arow   = (lane & 7) + ((lane >> 3) & 1) * 8;
    const int akq    = (lane >> 4);
    const int lane16 = lane & 15;

    float acc[4][4][4];
#pragma unroll
    for (int i = 0; i < 4; i++)
#pragma unroll
        for (int j = 0; j < 4; j++)
#pragma unroll
            for (int q = 0; q < 4; q++) acc[i][j][q] = 0.0f;

    const int nkt = K >> 5;
    const int sr  = tid >> 1;
    const int skh = (tid & 1) * 16;

#define STAGE_BD(bufi, kt) do { \
    unsigned dbase = sb + (bufi) * ABUF; \
    _Pragma("unroll") \
    for (int s2 = 0; s2 < 2; s2++) { \
        int idx = tid + s2 * 256; \
        int rowb = idx >> 4, cc = idx & 15; \
        const char* sh = (const char*)(Bh + (size_t)((kt) * 32 + rowb) * ldb) + cc * 16; \
        const char* sl = (const char*)(Bl + (size_t)((kt) * 32 + rowb) * ldb) + cc * 16; \
        CP_ASYNC16(dbase + OFF_BHI + rowb * B_STRIDE + cc * 16, sh); \
        CP_ASYNC16(dbase + OFF_BLO + rowb * B_STRIDE + cc * 16, sl); \
    } \
    CP_COMMIT(); \
} while (0)

#define STAGE_AD(bufi, kt) do { \
    char* dh = smem + (bufi) * ABUF; \
    const float* Ar = A + (size_t)(brow + sr) * K + (kt) * 32 + skh; \
    bool okr = (brow + sr) < M; \
    _Pragma("unroll") \
    for (int i4 = 0; i4 < 4; i4++) { \
        float4 v = okr ? *(const float4*)(Ar + i4 * 4) : make_float4(0.f, 0.f, 0.f, 0.f); \
        *(uint2*)(dh + sr * A_STRIDE + (skh + i4 * 4) * 2) = \
            make_uint2(hpack2(v.x, v.y), hpack2(v.z, v.w)); \
    } \
} while (0)

    STAGE_BD(0, 0);
    STAGE_AD(0, 0);
    CP_WAIT0();
    __syncthreads();

    for (int kt = 0; kt < nkt; kt++) {
        const int buf = kt & 1;
        const bool more = (kt + 1) < nkt;
        if (more) {
            STAGE_BD(buf ^ 1, kt + 1);
            STAGE_AD(buf ^ 1, kt + 1);
        }
        const unsigned sba = sb + buf * ABUF;
#pragma unroll
        for (int ks = 0; ks < 2; ks++) {
            unsigned aoff = sba + (warp_m + arow) * A_STRIDE + (ks * 16 + akq * 8) * 2;
            unsigned boff = sba + OFF_BHI + (ks * 16 + lane16) * B_STRIDE + warp_n * 2;
            unsigned Ah[4][4], Bhf[4][2];
#pragma unroll
            for (int tm = 0; tm < 4; tm++)
                LDSM_X4(Ah[tm][0], Ah[tm][1], Ah[tm][2], Ah[tm][3], aoff + tm * 16 * A_STRIDE);
#pragma unroll
            for (int tn = 0; tn < 4; tn++)
                LDSM_X2T(Bhf[tn][0], Bhf[tn][1], boff + tn * 16);
#pragma unroll
            for (int tm = 0; tm < 4; tm++)
#pragma unroll
                for (int tn = 0; tn < 4; tn++)
                    MMAF16(acc[tm][tn], Ah[tm][0], Ah[tm][1], Ah[tm][2], Ah[tm][3],
                           Bhf[tn][0], Bhf[tn][1]);
            unsigned Blf[4][2];
            unsigned bloff = sba + OFF_BLO + (ks * 16 + lane16) * B_STRIDE + warp_n * 2;
#pragma unroll
            for (int tn = 0; tn < 4; tn++)
                LDSM_X2T(Blf[tn][0], Blf[tn][1], bloff + tn * 16);
#pragma unroll
            for (int tm = 0; tm < 4; tm++)
#pragma unroll
                for (int tn = 0; tn < 4; tn++)
                    MMAF16(acc[tm][tn], Ah[tm][0], Ah[tm][1], Ah[tm][2], Ah[tm][3],
                           Blf[tn][0], Blf[tn][1]);
        }
        if (more) CP_WAIT0();
        __syncthreads();
    }

#pragma unroll
    for (int tm = 0; tm < 4; tm++) {
#pragma unroll
        for (int tn = 0; tn < 4; tn++) {
            int gcol = col0 + warp_n + tn * 8 + (lane & 3) * 2;
            float bb0 = __ldg(bias + gcol), bb1 = __ldg(bias + gcol + 1);
#pragma unroll
            for (int half = 0; half < 2; half++) {
                int r = brow + warp_m + tm * 16 + (lane >> 2) + half * 8;
                if (r >= M) continue;
                float v0 = fmaxf(acc[tm][tn][half * 2 + 0] + bb0, 0.0f);
                float v1 = fmaxf(acc[tm][tn][half * 2 + 1] + bb1, 0.0f);
                float2 o; o.x = v0; o.y = v1;
                *(float2*)(C + (size_t)r * Ncs + gcol) = o;
            }
        }
    }
}

// ---------------- fused decoder tail ----------------
__global__ __launch_bounds__(128)
void decoder_tail_kernel(const float* __restrict__ din,
                         const float* __restrict__ W2, const float* __restrict__ b2,
                         const float* __restrict__ W3, const float* __restrict__ b3,
                         const float* __restrict__ W4, const float* __restrict__ b4,
                         const float* __restrict__ Wo, const float* __restrict__ bo,
                         const int* __restrict__ batch, float* __restrict__ sums, int M) {
    __shared__ float w2[128 * 64];
    __shared__ float w3[64 * 32];
    __shared__ float w4[32 * 16];
    __shared__ float wo[160];
    __shared__ float xs [4][128];
    __shared__ float t64[4][64];
    __shared__ float t32[4][32];
    __shared__ float t16[4][16];
    for (int i = threadIdx.x; i < 128 * 64; i += 128) w2[i] = W2[i];
    for (int i = threadIdx.x; i < 64 * 32;  i += 128) w3[i] = W3[i];
    for (int i = threadIdx.x; i < 32 * 16;  i += 128) w4[i] = W4[i];
    for (int i = threadIdx.x; i < 160;      i += 128) wo[i] = Wo[i];
    __syncthreads();
    int warp = threadIdx.x >> 5;
    int lane = threadIdx.x & 31;
    int stride = gridDim.x * 4;
    for (int row = blockIdx.x * 4 + warp; row < M; row += stride) {
        *(float4*)&xs[warp][lane * 4] = *(const float4*)(din + (size_t)row * 128 + lane * 4);
        __syncwarp();
        float s0 = b2[lane], s1 = b2[lane + 32];
#pragma unroll 8
        for (int k = 0; k < 128; k++) {
            float xv = xs[warp][k];
            s0 = fmaf(xv, w2[k * 64 + lane],      s0);
            s1 = fmaf(xv, w2[k * 64 + lane + 32], s1);
        }
        t64[warp][lane]      = fmaxf(s0, 0.0f);
        t64[warp][lane + 32] = fmaxf(s1, 0.0f);
        __syncwarp();
        float s = b3[lane];
#pragma unroll 8
        for (int k = 0; k < 64; k++) s = fmaf(t64[warp][k], w3[k * 32 + lane], s);
        t32[warp][lane] = fmaxf(s, 0.0f);
        __syncwarp();
        if (lane < 16) {
            float t = b4[lane];
#pragma unroll
            for (int k = 0; k < 32; k++) t = fmaf(t32[warp][k], w4[k * 16 + lane], t);
            t16[warp][lane] = fmaxf(t, 0.0f);
        }
        __syncwarp();
        if (lane < 10) {
            float t = bo[lane];
#pragma unroll
            for (int k = 0; k < 16; k++) t = fmaf(t16[warp][k], wo[k * 10 + lane], t);
            float yp = __fdividef(1.0f, 1.0f + __expf(-t));
            atomicAdd(&sums[batch[row] * 10 + lane], yp);
        }
        __syncwarp();
    }
}

__global__ void pool_finalize_kernel(const float* __restrict__ sums, const float* __restrict__ cnt,
                                     const float* __restrict__ y,
                                     float* __restrict__ out_pred, float* __restrict__ out_y) {
    int i = blockIdx.x * blockDim.x + threadIdx.x;
    if (i < GG * DOUT_) {
        out_pred[i] = sums[i] / fmaxf(cnt[i / DOUT_], 1.0f);
        out_y[i]    = y[i];
    }
}

// ---------------- launch ----------------
extern "C" void kernel_launch(void* const* d_in, const int* in_sizes, int n_in,
                              void* d_out, int out_size) {
    const float* x     = (const float*)d_in[0];
    const int*   ei    = (const int*)  d_in[1];
    const int*   batch = (const int*)  d_in[2];
    const float* y     = (const float*)d_in[3];
    const float* eps   = (const float*)d_in[4];
    const float* W_in  = (const float*)d_in[5];
    const float* b_in  = (const float*)d_in[6];
    const float* W_gcn = (const float*)d_in[7];
    const float* b_gcn = (const float*)d_in[8];
    const float* W_enc = (const float*)d_in[9];
    const float* b_enc = (const float*)d_in[10];
    const float* W_mu  = (const float*)d_in[11];
    const float* b_mu  = (const float*)d_in[12];
    const float* W_std = (const float*)d_in[13];
    const float* b_std = (const float*)d_in[14];
    const float* Wd0 = (const float*)d_in[15]; const float* bd0 = (const float*)d_in[16];
    const float* Wd1 = (const float*)d_in[17]; const float* bd1 = (const float*)d_in[18];
    const float* Wd2 = (const float*)d_in[19]; const float* bd2 = (const float*)d_in[20];
    const float* Wd3 = (const float*)d_in[21]; const float* bd3 = (const float*)d_in[22];
    const float* Wd4 = (const float*)d_in[23]; const float* bd4 = (const float*)d_in[24];
    const float* Wo  = (const float*)d_in[25]; const float* bo  = (const float*)d_in[26];

    float *h, *u, *gbuf, *dec1, *dinv, *sums, *cnt;
    int *deg, *off, *cur, *csr;
    unsigned short *wh, *wl;
    cudaGetSymbolAddress((void**)&h,    g_h);
    cudaGetSymbolAddress((void**)&u,    g_u);
    cudaGetSymbolAddress((void**)&gbuf, g_g);
    cudaGetSymbolAddress((void**)&dec1, g_dec1);
    cudaGetSymbolAddress((void**)&dinv, g_dinv);
    cudaGetSymbolAddress((void**)&deg,  g_deg);
    cudaGetSymbolAddress((void**)&off,  g_off);
    cudaGetSymbolAddress((void**)&cur,  g_cur);
    cudaGetSymbolAddress((void**)&csr,  g_csr);
    cudaGetSymbolAddress((void**)&sums, g_sums);
    cudaGetSymbolAddress((void**)&cnt,  g_cnt);
    cudaGetSymbolAddress((void**)&wh,   g_wh);
    cudaGetSymbolAddress((void**)&wl,   g_wl);

    float* out      = (float*)d_out;
    float* out_pred = out;
    float* out_mu   = out + GG * DOUT_;
    float* out_std  = out + GG * DOUT_ + (size_t)NN * DL_;
    float* out_y    = out + GG * DOUT_ + (size_t)2 * NN * DL_;

    const int* src = ei;
    const int* dst = ei + EE;

    cudaFuncSetAttribute(mega_kernel, cudaFuncAttributeMaxDynamicSharedMemorySize, MEGA_SMEM);
    cudaFuncSetAttribute(gemm_mma,   cudaFuncAttributeMaxDynamicSharedMemorySize, SMEM_GEMM);

    WJobs jobs;
    int O[11];
    {
        int o = 0;
        auto set = [&](int i, const float* W, int elems) {
            jobs.j[i].W = W; jobs.j[i].elems = elems; jobs.j[i].off = o; O[i] = o; o += elems;
        };
        set(0, W_in, 32 * 128);
        set(1, W_gcn, 128 * 128);
        for (int j = 0; j < 5; j++) set(2 + j, W_enc + (size_t)j * DL_ * DL_, 128 * 128);
        set(7, W_mu, 128 * 128);
        set(8, W_std, 128 * 128);
        set(9, Wd0, 128 * 256);
        set(10, Wd1, 256 * 128);
    }
    const int GRID = (NN + 127) / 128;
    const __half* WH = (const __half*)wh;
    const __half* WL = (const __half*)wl;

    // order chosen so mega0 is the 5th kernel launch (ncu -s 5 capture slot)
    wsplit_kernel<<<dim3(32, 11), 256>>>(jobs, wh, wl);
    cudaMemsetAsync(deg, 0, NN * sizeof(int));
    count_deg_kernel   <<<(EE + 255) / 256, 256>>>(dst, deg, EE);
    scan_offsets_kernel<<<1, 1024>>>(deg, off, cur, dinv, NN);
    mega_kernel<<<GRID, 512, MEGA_SMEM>>>(0, x, WH, WL, O[0], b_in, O[1], O[2], b_enc,
                                          O[7], b_mu, O[8], b_std, dinv, nullptr,
                                          u, nullptr, nullptr, nullptr, NN);
    csr_fill_kernel    <<<(EE + 255) / 256, 256>>>(src, dst, cur, csr, EE);

    for (int it = 0; it < KK; it++) {
        gather_kernel<<<(NN * 32 + 255) / 256, 256>>>(off, csr, u, dinv, b_gcn, gbuf, NN);
        int mode = (it == KK - 1) ? 2 : 1;
        mega_kernel<<<GRID, 512, MEGA_SMEM>>>(mode, gbuf, WH, WL, O[0], b_in, O[1], O[2], b_enc,
                                              O[7], b_mu, O[8], b_std, dinv,
                                              eps + (size_t)it * NN * DL_,
                                              u, out_mu, out_std, h, NN);
    }

    gemm_mma<<<GRID, 256, SMEM_GEMM>>>(h, WH + O[9], WL + O[9], bd0, dec1, NN, 128, 256, 256, 0);
    gemm_mma<<<GRID, 256, SMEM_GEMM>>>(h, WH + O[9] + 128, WL + O[9] + 128, bd0, dec1,
                                       NN, 128, 256, 256, 128);
    gemm_mma<<<GRID, 256, SMEM_GEMM>>>(dec1, WH + O[10], WL + O[10], bd1, u, NN, 256, 128, 128, 0);

    cudaMemsetAsync(sums, 0, GG * DOUT_ * sizeof(float));
    cudaMemsetAsync(cnt,  0, GG * sizeof(float));
    count_nodes_kernel<<<(NN + 255) / 256, 256>>>(batch, cnt, NN);
    decoder_tail_kernel<<<592, 128>>>(u, Wd2, bd2, Wd3, bd3, Wd4, bd4, Wo, bo,
                                      batch, sums, NN);
    pool_finalize_kernel<<<(GG * DOUT_ + 255) / 256, 256>>>(sums, cnt, y, out_pred, out_y);

    (void)in_sizes; (void)n_in; (void)out_size;
}

// round 11
// speedup vs baseline: 2.9671x; 1.0214x over previous
#include <cuda_runtime.h>
#include <cuda_fp16.h>
#include <math.h>

#define NN   50000
#define EE   800000
#define DIN_ 32
#define DL_  128
#define DOUT_ 10
#define GG   256
#define KK   3

// ---------------- scratch (device globals) ----------------
__device__ __align__(16) float g_h  [NN * DL_];
__device__ __align__(16) float g_u  [NN * DL_];
__device__ __align__(16) float g_g  [NN * DL_];
__device__ __align__(16) float g_dec1[NN * 256];
__device__ __align__(16) float g_dinv[NN];
__device__ __align__(16) int   g_deg [NN];
__device__ __align__(16) int   g_off [NN + 1];
__device__ __align__(16) int   g_cur [NN];
__device__ __align__(16) int   g_csr [EE];
__device__ __align__(16) float g_sums[GG * DOUT_];
__device__ __align__(16) float g_cnt [GG];
__device__ __align__(16) unsigned short g_wh[184320];
__device__ __align__(16) unsigned short g_wl[184320];

// ---------------- asm helpers ----------------
__device__ __forceinline__ unsigned smem_u32(const void* p) {
    unsigned a;
    asm("{ .reg .u64 t; cvta.to.shared.u64 t, %1; cvt.u32.u64 %0, t; }" : "=r"(a) : "l"(p));
    return a;
}
#define CP_ASYNC16(dst_u32, src) \
    asm volatile("cp.async.ca.shared.global [%0], [%1], 16;" :: "r"(dst_u32), "l"(src))
#define CP_COMMIT() asm volatile("cp.async.commit_group;")
#define CP_WAIT0()  asm volatile("cp.async.wait_group 0;")
#define LDSM_X4(r0, r1, r2, r3, addr) \
    asm volatile("ldmatrix.sync.aligned.m8n8.x4.shared.b16 {%0,%1,%2,%3}, [%4];" \
                 : "=r"(r0), "=r"(r1), "=r"(r2), "=r"(r3) : "r"(addr))
#define LDSM_X2T(r0, r1, addr) \
    asm volatile("ldmatrix.sync.aligned.m8n8.x2.trans.shared.b16 {%0,%1}, [%2];" \
                 : "=r"(r0), "=r"(r1) : "r"(addr))
#define MMAF16(c, a0, a1, a2, a3, b0, b1) \
    asm volatile("mma.sync.aligned.m16n8k16.row.col.f32.f16.f16.f32 " \
                 "{%0,%1,%2,%3}, {%4,%5,%6,%7}, {%8,%9}, {%0,%1,%2,%3};" \
                 : "+f"((c)[0]), "+f"((c)[1]), "+f"((c)[2]), "+f"((c)[3]) \
                 : "r"(a0), "r"(a1), "r"(a2), "r"(a3), "r"(b0), "r"(b1))

__device__ __forceinline__ unsigned hpack2(float a, float b) {
    __half2 h = __floats2half2_rn(a, b);
    return *(unsigned*)&h;
}

// ============ mega smem geometry: A tile + ONE W buffer (hi+lo) ============
#define AST    272
#define MS_AH  0
#define MS_W0  34816
#define WLO    34816               // lo offset inside the W region
#define MEGA_SMEM 104448           // 34816 + 69632  -> 2 CTAs/SM

// decoder gemm geometry
#define A_STRIDE 80
#define B_STRIDE 272
#define OFF_BHI  10240
#define OFF_BLO  18944
#define ABUF     27648
#define SMEM_GEMM (2 * ABUF)

// ---------------- preprocessing ----------------
__global__ void count_deg_kernel(const int* __restrict__ dst, int* __restrict__ deg, int E) {
    int i = blockIdx.x * blockDim.x + threadIdx.x;
    if (i < E) atomicAdd(&deg[dst[i]], 1);
}
__global__ void count_nodes_kernel(const int* __restrict__ batch, float* __restrict__ cnt, int M) {
    int i = blockIdx.x * blockDim.x + threadIdx.x;
    if (i < M) atomicAdd(&cnt[batch[i]], 1.0f);
}
__global__ __launch_bounds__(1024)
void scan_offsets_kernel(const int* __restrict__ deg, int* __restrict__ off,
                         int* __restrict__ cursor, float* __restrict__ dinv, int M) {
    __shared__ int part[1024];
    int t = threadIdx.x;
    int chunk = (M + 1023) >> 10;
    int base = t * chunk;
    int s = 0;
    for (int i = 0; i < chunk; i++) { int j = base + i; if (j < M) s += deg[j]; }
    part[t] = s;
    __syncthreads();
    for (int d = 1; d < 1024; d <<= 1) {
        int add = (t >= d) ? part[t - d] : 0;
        __syncthreads();
        part[t] += add;
        __syncthreads();
    }
    int run = part[t] - s;
    for (int i = 0; i < chunk; i++) {
        int j = base + i;
        if (j < M) {
            int dj = deg[j];
            off[j] = run; cursor[j] = run; run += dj;
            dinv[j] = rsqrtf((float)dj + 1.0f);
        }
    }
    if (t == 1023) off[M] = part[1023];
}
__global__ void csr_fill_kernel(const int* __restrict__ src, const int* __restrict__ dst,
                                int* __restrict__ cursor, int* __restrict__ csr, int E) {
    int i = blockIdx.x * blockDim.x + threadIdx.x;
    if (i < E) {
        int p = atomicAdd(&cursor[dst[i]], 1);
        csr[p] = src[i];
    }
}

// ---------------- weight split (fp16 hi/lo) ----------------
struct WJob { const float* W; int elems; int off; };
struct WJobs { WJob j[11]; };
__global__ void wsplit_kernel(WJobs jobs, unsigned short* __restrict__ wh,
                              unsigned short* __restrict__ wl) {
    WJob jb = jobs.j[blockIdx.y];
    for (int i = blockIdx.x * blockDim.x + threadIdx.x; i < jb.elems;
         i += gridDim.x * blockDim.x) {
        float w = jb.W[i];
        __half hb = __float2half_rn(w);
        __half lb = __float2half_rn(w - __half2float(hb));
        wh[jb.off + i] = __half_as_ushort(hb);
        wl[jb.off + i] = __half_as_ushort(lb);
    }
}

// ---------------- gather ----------------
__global__ __launch_bounds__(256)
void gather_kernel(const int* __restrict__ off, const int* __restrict__ csr,
                   const float* __restrict__ u, const float* __restrict__ dinv,
                   const float* __restrict__ bgcn, float* __restrict__ g, int M) {
    int n = (blockIdx.x * blockDim.x + threadIdx.x) >> 5;
    if (n >= M) return;
    int lane = threadIdx.x & 31;
    int e0 = off[n], e1 = off[n + 1];
    int deg = e1 - e0;
    float4 acc = __ldg((const float4*)(u + (size_t)n * DL_ + lane * 4));
    for (int base = 0; base < deg; base += 32) {
        int cnt = min(32, deg - base);
        int idx = 0;
        if (base + lane < deg) idx = __ldg(csr + e0 + base + lane);
        int j = 0;
        for (; j + 8 <= cnt; j += 8) {
            float4 v[8];
#pragma unroll
            for (int q = 0; q < 8; q++) {
                int s = __shfl_sync(0xffffffffu, idx, j + q);
                v[q] = __ldg((const float4*)(u + (size_t)s * DL_ + lane * 4));
            }
#pragma unroll
            for (int q = 0; q < 8; q++) {
                acc.x += v[q].x; acc.y += v[q].y; acc.z += v[q].z; acc.w += v[q].w;
            }
        }
        for (; j < cnt; j++) {
            int s = __shfl_sync(0xffffffffu, idx, j);
            float4 v = __ldg((const float4*)(u + (size_t)s * DL_ + lane * 4));
            acc.x += v.x; acc.y += v.y; acc.z += v.z; acc.w += v.w;
        }
    }
    float dv = dinv[n];
    float4 b = *(const float4*)(bgcn + lane * 4);
    float4 o;
    o.x = fmaf(dv, acc.x, b.x);
    o.y = fmaf(dv, acc.y, b.y);
    o.z = fmaf(dv, acc.z, b.z);
    o.w = fmaf(dv, acc.w, b.w);
    *(float4*)(g + (size_t)n * DL_ + lane * 4) = o;
}

// ========== mega pieces (512 thr, warp 32x32, fp16 2-product, 1 W buffer) ==========
__device__ __forceinline__ void stage_w128(unsigned sb, const __half* Wh, const __half* Wl,
                                           int nrows, int tid) {
    int chunks = nrows * 16;
    for (int idx = tid; idx < chunks; idx += 512) {
        int rowb = idx >> 4, cc = idx & 15;
        CP_ASYNC16(sb + MS_W0 + rowb * AST + cc * 16, (const char*)(Wh + rowb * 128) + cc * 16);
        CP_ASYNC16(sb + MS_W0 + WLO + rowb * AST + cc * 16,
                   (const char*)(Wl + rowb * 128) + cc * 16);
    }
    CP_COMMIT();
}

__device__ __forceinline__ void layer_mma(unsigned sb,
                                          int warp_m, int warp_n, int lane,
                                          int nks, float acc[2][4][4]) {
#pragma unroll
    for (int i = 0; i < 2; i++)
#pragma unroll
        for (int j = 0; j < 4; j++)
#pragma unroll
            for (int q = 0; q < 4; q++) acc[i][j][q] = 0.0f;
    const int arow = (lane & 7) + ((lane >> 3) & 1) * 8;
    const int akq  = lane >> 4;
    const int lane16 = lane & 15;
    for (int ks = 0; ks < nks; ks++) {
        unsigned aoff = sb + MS_AH + (warp_m + arow) * AST + (ks * 16 + akq * 8) * 2;
        unsigned boff = sb + MS_W0 + (ks * 16 + lane16) * AST + warp_n * 2;
        unsigned Ah[2][4], Bf[4][2];
#pragma unroll
        for (int tm = 0; tm < 2; tm++)
            LDSM_X4(Ah[tm][0], Ah[tm][1], Ah[tm][2], Ah[tm][3], aoff + tm * 16 * AST);
#pragma unroll
        for (int tn = 0; tn < 4; tn++)
            LDSM_X2T(Bf[tn][0], Bf[tn][1], boff + tn * 16);
#pragma unroll
        for (int tm = 0; tm < 2; tm++)
#pragma unroll
            for (int tn = 0; tn < 4; tn++)
                MMAF16(acc[tm][tn], Ah[tm][0], Ah[tm][1], Ah[tm][2], Ah[tm][3],
                       Bf[tn][0], Bf[tn][1]);
        // reuse Bf for the lo product (keeps live registers under the 64-reg cap)
#pragma unroll
        for (int tn = 0; tn < 4; tn++)
            LDSM_X2T(Bf[tn][0], Bf[tn][1], boff + WLO + tn * 16);
#pragma unroll
        for (int tm = 0; tm < 2; tm++)
#pragma unroll
            for (int tn = 0; tn < 4; tn++)
                MMAF16(acc[tm][tn], Ah[tm][0], Ah[tm][1], Ah[tm][2], Ah[tm][3],
                       Bf[tn][0], Bf[tn][1]);
    }
}

__device__ __forceinline__ void store_act_sig(char* smem, float acc[2][4][4],
                                              const float* __restrict__ bias,
                                              int warp_m, int warp_n, int lane) {
#pragma unroll
    for (int tn = 0; tn < 4; tn++) {
        int c = warp_n + tn * 8 + (lane & 3) * 2;
        float b0 = __ldg(bias + c), b1 = __ldg(bias + c + 1);
#pragma unroll
        for (int tm = 0; tm < 2; tm++)
#pragma unroll
            for (int half = 0; half < 2; half++) {
                int r = warp_m + tm * 16 + (lane >> 2) + half * 8;
                float v0 = acc[tm][tn][half * 2]     + b0;
                float v1 = acc[tm][tn][half * 2 + 1] + b1;
                v0 = __fdividef(1.0f, 1.0f + __expf(-v0));
                v1 = __fdividef(1.0f, 1.0f + __expf(-v1));
                *(unsigned*)(smem + MS_AH + r * AST + c * 2) = hpack2(v0, v1);
            }
    }
}

// mode 0 = input (x -> h -> u); 1 = hop (g -> ... -> u); 2 = last hop (g -> mu,std,h)
__global__ __launch_bounds__(512, 2)
void mega_kernel(int mode, const float* __restrict__ Ain,
                 const __half* __restrict__ WH, const __half* __restrict__ WL,
                 int o_first, const float* __restrict__ b_first,
                 int o_gcn, int o_enc0, const float* __restrict__ b_enc,
                 int o_mu, const float* __restrict__ b_mu,
                 int o_std, const float* __restrict__ b_std,
                 const float* __restrict__ dinv, const float* __restrict__ eps_it,
                 float* __restrict__ u_out, float* __restrict__ mu_out,
                 float* __restrict__ std_out, float* __restrict__ h_out, int M) {
    extern __shared__ __align__(16) char smem[];
    const unsigned sb = smem_u32(smem);
    const int tid  = threadIdx.x;
    const int wid  = tid >> 5;
    const int lane = tid & 31;
    const int brow = blockIdx.x * 128;
    const int warp_m = (wid >> 2) * 32;
    const int warp_n = (wid & 3) * 32;

    // ---- stage initial A (fp32 global -> fp16 smem) + first W ----
    {
        const int K0 = (mode == 0) ? DIN_ : DL_;
        const int qK = K0 >> 2;
        int row = tid >> 2;
        int c0 = (tid & 3) * qK;
        bool ok = (brow + row) < M;
        const float* Ar = Ain + (size_t)(brow + row) * K0 + c0;
        for (int i4 = 0; i4 < (qK >> 2); i4++) {
            float4 v = ok ? *(const float4*)(Ar + i4 * 4) : make_float4(0.f, 0.f, 0.f, 0.f);
            int c = c0 + i4 * 4;
            *(uint2*)(smem + MS_AH + row * AST + c * 2) =
                make_uint2(hpack2(v.x, v.y), hpack2(v.z, v.w));
        }
    }
    stage_w128(sb, WH + ((mode == 0) ? o_first : o_enc0),
               WL + ((mode == 0) ? o_first : o_enc0), (mode == 0) ? 32 : 128, tid);
    CP_WAIT0();
    __syncthreads();

    float acc[2][4][4];

    if (mode == 0) {
        layer_mma(sb, warp_m, warp_n, lane, 2, acc);
        __syncthreads();                       // all reads of W_in + A done
        stage_w128(sb, WH + o_gcn, WL + o_gcn, 128, tid);
        store_act_sig(smem, acc, b_first, warp_m, warp_n, lane);
        CP_WAIT0();
        __syncthreads();
        layer_mma(sb, warp_m, warp_n, lane, 8, acc);
#pragma unroll
        for (int tm = 0; tm < 2; tm++)
#pragma unroll
            for (int half = 0; half < 2; half++) {
                int r = brow + warp_m + tm * 16 + (lane >> 2) + half * 8;
                if (r >= M) continue;
                float rs = __ldg(dinv + r);
#pragma unroll
                for (int tn = 0; tn < 4; tn++) {
                    int c = warp_n + tn * 8 + (lane & 3) * 2;
                    float2 o;
                    o.x = acc[tm][tn][half * 2]     * rs;
                    o.y = acc[tm][tn][half * 2 + 1] * rs;
                    *(float2*)(u_out + (size_t)r * DL_ + c) = o;
                }
            }
        return;
    }

    // ---- hop: enc x5 ----
    for (int j = 0; j < 5; j++) {
        layer_mma(sb, warp_m, warp_n, lane, 8, acc);
        __syncthreads();
        int nxt = (j < 4) ? (o_enc0 + (j + 1) * 16384) : o_mu;
        stage_w128(sb, WH + nxt, WL + nxt, 128, tid);
        store_act_sig(smem, acc, b_enc + j * DL_, warp_m, warp_n, lane);
        CP_WAIT0();
        __syncthreads();
    }
    // ---- mu: W buffer has W_mu; write mu (+bias) to global ----
    layer_mma(sb, warp_m, warp_n, lane, 8, acc);
    __syncthreads();
    stage_w128(sb, WH + o_std, WL + o_std, 128, tid);
#pragma unroll
    for (int tn = 0; tn < 4; tn++) {
        int c = warp_n + tn * 8 + (lane & 3) * 2;
        float b0 = __ldg(b_mu + c), b1 = __ldg(b_mu + c + 1);
#pragma unroll
        for (int tm = 0; tm < 2; tm++)
#pragma unroll
            for (int half = 0; half < 2; half++) {
                int r = brow + warp_m + tm * 16 + (lane >> 2) + half * 8;
                if (r >= M) continue;
                float2 v;
                v.x = acc[tm][tn][half * 2]     + b0;
                v.y = acc[tm][tn][half * 2 + 1] + b1;
                *(float2*)(mu_out + (size_t)r * DL_ + c) = v;
            }
    }
    CP_WAIT0();
    __syncthreads();
    // ---- std: W buffer has W_std ----
    layer_mma(sb, warp_m, warp_n, lane, 8, acc);
    __syncthreads();
    if (mode == 1)
        stage_w128(sb, WH + o_gcn, WL + o_gcn, 128, tid);
    // combine: h = mu(global) + softplus(std)*eps -> resident A; std/h out if last hop
#pragma unroll
    for (int tn = 0; tn < 4; tn++) {
        int c = warp_n + tn * 8 + (lane & 3) * 2;
        float b0 = __ldg(b_std + c), b1 = __ldg(b_std + c + 1);
#pragma unroll
        for (int tm = 0; tm < 2; tm++)
#pragma unroll
            for (int half = 0; half < 2; half++) {
                int r = warp_m + tm * 16 + (lane >> 2) + half * 8;
                int gr = brow + r;
                float s0 = acc[tm][tn][half * 2]     + b0 - 5.0f;
                float s1 = acc[tm][tn][half * 2 + 1] + b1 - 5.0f;
                s0 = (s0 > 20.0f) ? s0 : log1pf(expf(s0));
                s1 = (s1 > 20.0f) ? s1 : log1pf(expf(s1));
                float2 m = make_float2(0.f, 0.f), e = make_float2(0.f, 0.f);
                if (gr < M) {
                    m = *(const float2*)(mu_out + (size_t)gr * DL_ + c);
                    e = *(const float2*)(eps_it + (size_t)gr * DL_ + c);
                }
                float h0 = fmaf(s0, e.x, m.x);
                float h1 = fmaf(s1, e.y, m.y);
                if (mode == 2 && gr < M) {
                    float2 so; so.x = s0; so.y = s1;
                    *(float2*)(std_out + (size_t)gr * DL_ + c) = so;
                    float2 ho; ho.x = h0; ho.y = h1;
                    *(float2*)(h_out + (size_t)gr * DL_ + c) = ho;
                }
                *(unsigned*)(smem + MS_AH + r * AST + c * 2) = hpack2(h0, h1);
            }
    }
    if (mode == 2) return;
    CP_WAIT0();
    __syncthreads();
    // ---- gcn: u = h @ W_gcn * dinv ----
    layer_mma(sb, warp_m, warp_n, lane, 8, acc);
#pragma unroll
    for (int tm = 0; tm < 2; tm++)
#pragma unroll
        for (int half = 0; half < 2; half++) {
            int r = brow + warp_m + tm * 16 + (lane >> 2) + half * 8;
            if (r >= M) continue;
            float rs = __ldg(dinv + r);
#pragma unroll
            for (int tn = 0; tn < 4; tn++) {
                int c = warp_n + tn * 8 + (lane & 3) * 2;
                float2 o;
                o.x = acc[tm][tn][half * 2]     * rs;
                o.y = acc[tm][tn][half * 2 + 1] * rs;
                *(float2*)(u_out + (size_t)r * DL_ + c) = o;
            }
        }
}

// ---------------- decoder GEMM (fp16 2-product, unchanged) ----------------
__global__ __launch_bounds__(256)
void gemm_mma(const float* __restrict__ A,
              const __half* __restrict__ Bh, const __half* __restrict__ Bl,
              const float* __restrict__ bias, float* __restrict__ C,
              int M, int K, int ldb, int Ncs, int col0) {
    extern __shared__ __align__(16) char smem[];
    const unsigned sb = smem_u32(smem);
    const int tid  = threadIdx.x;
    const int wid  = tid >> 5;
    const int lane = tid & 31;
    const int brow = blockIdx.x * 128;
    const int warp_m = (wid >> 2) * 64;
    const int warp_n = (wid & 3) * 32;
    const int arow   = (lane & 7) + ((lane >> 3) & 1) * 8;
    const int akq    = (lane >> 4);
    const int lane16 = lane & 15;

    float acc[4][4][4];
#pragma unroll
    for (int i = 0; i < 4; i++)
#pragma unroll
        for (int j = 0; j < 4; j++)
#pragma unroll
            for (int q = 0; q < 4; q++) acc[i][j][q] = 0.0f;

    const int nkt = K >> 5;
    const int sr  = tid >> 1;
    const int skh = (tid & 1) * 16;

#define STAGE_BD(bufi, kt) do { \
    unsigned dbase = sb + (bufi) * ABUF; \
    _Pragma("unroll") \
    for (int s2 = 0; s2 < 2; s2++) { \
        int idx = tid + s2 * 256; \
        int rowb = idx >> 4, cc = idx & 15; \
        const char* sh = (const char*)(Bh + (size_t)((kt) * 32 + rowb) * ldb) + cc * 16; \
        const char* sl = (const char*)(Bl + (size_t)((kt) * 32 + rowb) * ldb) + cc * 16; \
        CP_ASYNC16(dbase + OFF_BHI + rowb * B_STRIDE + cc * 16, sh); \
        CP_ASYNC16(dbase + OFF_BLO + rowb * B_STRIDE + cc * 16, sl); \
    } \
    CP_COMMIT(); \
} while (0)

#define STAGE_AD(bufi, kt) do { \
    char* dh = smem + (bufi) * ABUF; \
    const float* Ar = A + (size_t)(brow + sr) * K + (kt) * 32 + skh; \
    bool okr = (brow + sr) < M; \
    _Pragma("unroll") \
    for (int i4 = 0; i4 < 4; i4++) { \
        float4 v = okr ? *(const float4*)(Ar + i4 * 4) : make_float4(0.f, 0.f, 0.f, 0.f); \
        *(uint2*)(dh + sr * A_STRIDE + (skh + i4 * 4) * 2) = \
            make_uint2(hpack2(v.x, v.y), hpack2(v.z, v.w)); \
    } \
} while (0)

    STAGE_BD(0, 0);
    STAGE_AD(0, 0);
    CP_WAIT0();
    __syncthreads();

    for (int kt = 0; kt < nkt; kt++) {
        const int buf = kt & 1;
        const bool more = (kt + 1) < nkt;
        if (more) {
            STAGE_BD(buf ^ 1, kt + 1);
            STAGE_AD(buf ^ 1, kt + 1);
        }
        const unsigned sba = sb + buf * ABUF;
#pragma unroll
        for (int ks = 0; ks < 2; ks++) {
            unsigned aoff = sba + (warp_m + arow) * A_STRIDE + (ks * 16 + akq * 8) * 2;
            unsigned boff = sba + OFF_BHI + (ks * 16 + lane16) * B_STRIDE + warp_n * 2;
            unsigned Ah[4][4], Bf[4][2];
#pragma unroll
            for (int tm = 0; tm < 4; tm++)
                LDSM_X4(Ah[tm][0], Ah[tm][1], Ah[tm][2], Ah[tm][3], aoff + tm * 16 * A_STRIDE);
#pragma unroll
            for (int tn = 0; tn < 4; tn++)
                LDSM_X2T(Bf[tn][0], Bf[tn][1], boff + tn * 16);
#pragma unroll
            for (int tm = 0; tm < 4; tm++)
#pragma unroll
                for (int tn = 0; tn < 4; tn++)
                    MMAF16(acc[tm][tn], Ah[tm][0], Ah[tm][1], Ah[tm][2], Ah[tm][3],
                           Bf[tn][0], Bf[tn][1]);
            unsigned bloff = sba + OFF_BLO + (ks * 16 + lane16) * B_STRIDE + warp_n * 2;
#pragma unroll
            for (int tn = 0; tn < 4; tn++)
                LDSM_X2T(Bf[tn][0], Bf[tn][1], bloff + tn * 16);
#pragma unroll
            for (int tm = 0; tm < 4; tm++)
#pragma unroll
                for (int tn = 0; tn < 4; tn++)
                    MMAF16(acc[tm][tn], Ah[tm][0], Ah[tm][1], Ah[tm][2], Ah[tm][3],
                           Bf[tn][0], Bf[tn][1]);
        }
        if (more) CP_WAIT0();
        __syncthreads();
    }

#pragma unroll
    for (int tm = 0; tm < 4; tm++) {
#pragma unroll
        for (int tn = 0; tn < 4; tn++) {
            int gcol = col0 + warp_n + tn * 8 + (lane & 3) * 2;
            float bb0 = __ldg(bias + gcol), bb1 = __ldg(bias + gcol + 1);
#pragma unroll
            for (int half = 0; half < 2; half++) {
                int r = brow + warp_m + tm * 16 + (lane >> 2) + half * 8;
                if (r >= M) continue;
                float v0 = fmaxf(acc[tm][tn][half * 2 + 0] + bb0, 0.0f);
                float v1 = fmaxf(acc[tm][tn][half * 2 + 1] + bb1, 0.0f);
                float2 o; o.x = v0; o.y = v1;
                *(float2*)(C + (size_t)r * Ncs + gcol) = o;
            }
        }
    }
}

// ---------------- fused decoder tail ----------------
__global__ __launch_bounds__(128)
void decoder_tail_kernel(const float* __restrict__ din,
                         const float* __restrict__ W2, const float* __restrict__ b2,
                         const float* __restrict__ W3, const float* __restrict__ b3,
                         const float* __restrict__ W4, const float* __restrict__ b4,
                         const float* __restrict__ Wo, const float* __restrict__ bo,
                         const int* __restrict__ batch, float* __restrict__ sums, int M) {
    __shared__ float w2[128 * 64];
    __shared__ float w3[64 * 32];
    __shared__ float w4[32 * 16];
    __shared__ float wo[160];
    __shared__ float xs [4][128];
    __shared__ float t64[4][64];
    __shared__ float t32[4][32];
    __shared__ float t16[4][16];
    for (int i = threadIdx.x; i < 128 * 64; i += 128) w2[i] = W2[i];
    for (int i = threadIdx.x; i < 64 * 32;  i += 128) w3[i] = W3[i];
    for (int i = threadIdx.x; i < 32 * 16;  i += 128) w4[i] = W4[i];
    for (int i = threadIdx.x; i < 160;      i += 128) wo[i] = Wo[i];
    __syncthreads();
    int warp = threadIdx.x >> 5;
    int lane = threadIdx.x & 31;
    int stride = gridDim.x * 4;
    for (int row = blockIdx.x * 4 + warp; row < M; row += stride) {
        *(float4*)&xs[warp][lane * 4] = *(const float4*)(din + (size_t)row * 128 + lane * 4);
        __syncwarp();
        float s0 = b2[lane], s1 = b2[lane + 32];
#pragma unroll 8
        for (int k = 0; k < 128; k++) {
            float xv = xs[warp][k];
            s0 = fmaf(xv, w2[k * 64 + lane],      s0);
            s1 = fmaf(xv, w2[k * 64 + lane + 32], s1);
        }
        t64[warp][lane]      = fmaxf(s0, 0.0f);
        t64[warp][lane + 32] = fmaxf(s1, 0.0f);
        __syncwarp();
        float s = b3[lane];
#pragma unroll 8
        for (int k = 0; k < 64; k++) s = fmaf(t64[warp][k], w3[k * 32 + lane], s);
        t32[warp][lane] = fmaxf(s, 0.0f);
        __syncwarp();
        if (lane < 16) {
            float t = b4[lane];
#pragma unroll
            for (int k = 0; k < 32; k++) t = fmaf(t32[warp][k], w4[k * 16 + lane], t);
            t16[warp][lane] = fmaxf(t, 0.0f);
        }
        __syncwarp();
        if (lane < 10) {
            float t = bo[lane];
#pragma unroll
            for (int k = 0; k < 16; k++) t = fmaf(t16[warp][k], wo[k * 10 + lane], t);
            float yp = __fdividef(1.0f, 1.0f + __expf(-t));
            atomicAdd(&sums[batch[row] * 10 + lane], yp);
        }
        __syncwarp();
    }
}

__global__ void pool_finalize_kernel(const float* __restrict__ sums, const float* __restrict__ cnt,
                                     const float* __restrict__ y,
                                     float* __restrict__ out_pred, float* __restrict__ out_y) {
    int i = blockIdx.x * blockDim.x + threadIdx.x;
    if (i < GG * DOUT_) {
        out_pred[i] = sums[i] / fmaxf(cnt[i / DOUT_], 1.0f);
        out_y[i]    = y[i];
    }
}

// ---------------- launch ----------------
extern "C" void kernel_launch(void* const* d_in, const int* in_sizes, int n_in,
                              void* d_out, int out_size) {
    const float* x     = (const float*)d_in[0];
    const int*   ei    = (const int*)  d_in[1];
    const int*   batch = (const int*)  d_in[2];
    const float* y     = (const float*)d_in[3];
    const float* eps   = (const float*)d_in[4];
    const float* W_in  = (const float*)d_in[5];
    const float* b_in  = (const float*)d_in[6];
    const float* W_gcn = (const float*)d_in[7];
    const float* b_gcn = (const float*)d_in[8];
    const float* W_enc = (const float*)d_in[9];
    const float* b_enc = (const float*)d_in[10];
    const float* W_mu  = (const float*)d_in[11];
    const float* b_mu  = (const float*)d_in[12];
    const float* W_std = (const float*)d_in[13];
    const float* b_std = (const float*)d_in[14];
    const float* Wd0 = (const float*)d_in[15]; const float* bd0 = (const float*)d_in[16];
    const float* Wd1 = (const float*)d_in[17]; const float* bd1 = (const float*)d_in[18];
    const float* Wd2 = (const float*)d_in[19]; const float* bd2 = (const float*)d_in[20];
    const float* Wd3 = (const float*)d_in[21]; const float* bd3 = (const float*)d_in[22];
    const float* Wd4 = (const float*)d_in[23]; const float* bd4 = (const float*)d_in[24];
    const float* Wo  = (const float*)d_in[25]; const float* bo  = (const float*)d_in[26];

    float *h, *u, *gbuf, *dec1, *dinv, *sums, *cnt;
    int *deg, *off, *cur, *csr;
    unsigned short *wh, *wl;
    cudaGetSymbolAddress((void**)&h,    g_h);
    cudaGetSymbolAddress((void**)&u,    g_u);
    cudaGetSymbolAddress((void**)&gbuf, g_g);
    cudaGetSymbolAddress((void**)&dec1, g_dec1);
    cudaGetSymbolAddress((void**)&dinv, g_dinv);
    cudaGetSymbolAddress((void**)&deg,  g_deg);
    cudaGetSymbolAddress((void**)&off,  g_off);
    cudaGetSymbolAddress((void**)&cur,  g_cur);
    cudaGetSymbolAddress((void**)&csr,  g_csr);
    cudaGetSymbolAddress((void**)&sums, g_sums);
    cudaGetSymbolAddress((void**)&cnt,  g_cnt);
    cudaGetSymbolAddress((void**)&wh,   g_wh);
    cudaGetSymbolAddress((void**)&wl,   g_wl);

    float* out      = (float*)d_out;
    float* out_pred = out;
    float* out_mu   = out + GG * DOUT_;
    float* out_std  = out + GG * DOUT_ + (size_t)NN * DL_;
    float* out_y    = out + GG * DOUT_ + (size_t)2 * NN * DL_;

    const int* src = ei;
    const int* dst = ei + EE;

    cudaFuncSetAttribute(mega_kernel, cudaFuncAttributeMaxDynamicSharedMemorySize, MEGA_SMEM);
    cudaFuncSetAttribute(gemm_mma,   cudaFuncAttributeMaxDynamicSharedMemorySize, SMEM_GEMM);

    WJobs jobs;
    int O[11];
    {
        int o = 0;
        auto set = [&](int i, const float* W, int elems) {
            jobs.j[i].W = W; jobs.j[i].elems = elems; jobs.j[i].off = o; O[i] = o; o += elems;
        };
        set(0, W_in, 32 * 128);
        set(1, W_gcn, 128 * 128);
        for (int j = 0; j < 5; j++) set(2 + j, W_enc + (size_t)j * DL_ * DL_, 128 * 128);
        set(7, W_mu, 128 * 128);
        set(8, W_std, 128 * 128);
        set(9, Wd0, 128 * 256);
        set(10, Wd1, 256 * 128);
    }
    const int GRID = (NN + 127) / 128;
    const __half* WH = (const __half*)wh;
    const __half* WL = (const __half*)wl;

    // order chosen so a hop mega lands in the ncu -s 5 capture window
    wsplit_kernel<<<dim3(32, 11), 256>>>(jobs, wh, wl);
    cudaMemsetAsync(deg, 0, NN * sizeof(int));
    count_deg_kernel   <<<(EE + 255) / 256, 256>>>(dst, deg, EE);
    scan_offsets_kernel<<<1, 1024>>>(deg, off, cur, dinv, NN);
    mega_kernel<<<GRID, 512, MEGA_SMEM>>>(0, x, WH, WL, O[0], b_in, O[1], O[2], b_enc,
                                          O[7], b_mu, O[8], b_std, dinv, nullptr,
                                          u, out_mu, nullptr, nullptr, NN);
    csr_fill_kernel    <<<(EE + 255) / 256, 256>>>(src, dst, cur, csr, EE);

    for (int it = 0; it < KK; it++) {
        gather_kernel<<<(NN * 32 + 255) / 256, 256>>>(off, csr, u, dinv, b_gcn, gbuf, NN);
        int mode = (it == KK - 1) ? 2 : 1;
        mega_kernel<<<GRID, 512, MEGA_SMEM>>>(mode, gbuf, WH, WL, O[0], b_in, O[1], O[2], b_enc,
                                              O[7], b_mu, O[8], b_std, dinv,
                                              eps + (size_t)it * NN * DL_,
                                              u, out_mu, out_std, h, NN);
    }

    gemm_mma<<<GRID, 256, SMEM_GEMM>>>(h, WH + O[9], WL + O[9], bd0, dec1, NN, 128, 256, 256, 0);
    gemm_mma<<<GRID, 256, SMEM_GEMM>>>(h, WH + O[9] + 128, WL + O[9] + 128, bd0, dec1,
                                       NN, 128, 256, 256, 128);
    gemm_mma<<<GRID, 256, SMEM_GEMM>>>(dec1, WH + O[10], WL + O[10], bd1, u, NN, 256, 128, 128, 0);

    cudaMemsetAsync(sums, 0, GG * DOUT_ * sizeof(float));
    cudaMemsetAsync(cnt,  0, GG * sizeof(float));
    count_nodes_kernel<<<(NN + 255) / 256, 256>>>(batch, cnt, NN);
    decoder_tail_kernel<<<592, 128>>>(u, Wd2, bd2, Wd3, bd3, Wd4, bd4, Wo, bo,
                                      batch, sums, NN);
    pool_finalize_kernel<<<(GG * DOUT_ + 255) / 256, 256>>>(sums, cnt, y, out_pred, out_y);

    (void)in_sizes; (void)n_in; (void)out_size;
}

// round 12
// speedup vs baseline: 3.3572x; 1.1315x over previous
#include <cuda_runtime.h>
#include <cuda_fp16.h>
#include <math.h>

#define NN   50000
#define EE   800000
#define DIN_ 32
#define DL_  128
#define DOUT_ 10
#define GG   256
#define KK   3

// ---------------- scratch (device globals) ----------------
__device__ __align__(16) float g_h  [NN * DL_];
__device__ __align__(16) float g_u  [NN * DL_];
__device__ __align__(16) float g_g  [NN * DL_];
__device__ __align__(16) float g_dec1[NN * 256];
__device__ __align__(16) float g_dinv[NN];
__device__ __align__(16) int   g_deg [NN];
__device__ __align__(16) int   g_off [NN + 1];
__device__ __align__(16) int   g_cur [NN];
__device__ __align__(16) int   g_csr [EE];
__device__ __align__(16) float g_sums[GG * DOUT_];
__device__ __align__(16) float g_cnt [GG];
__device__ __align__(16) unsigned short g_wh[184320];

// ---------------- asm helpers ----------------
__device__ __forceinline__ unsigned smem_u32(const void* p) {
    unsigned a;
    asm("{ .reg .u64 t; cvta.to.shared.u64 t, %1; cvt.u32.u64 %0, t; }" : "=r"(a) : "l"(p));
    return a;
}
#define CP_ASYNC16(dst_u32, src) \
    asm volatile("cp.async.ca.shared.global [%0], [%1], 16;" :: "r"(dst_u32), "l"(src))
#define CP_COMMIT() asm volatile("cp.async.commit_group;")
#define CP_WAIT0()  asm volatile("cp.async.wait_group 0;")
#define LDSM_X4(r0, r1, r2, r3, addr) \
    asm volatile("ldmatrix.sync.aligned.m8n8.x4.shared.b16 {%0,%1,%2,%3}, [%4];" \
                 : "=r"(r0), "=r"(r1), "=r"(r2), "=r"(r3) : "r"(addr))
#define LDSM_X2T(r0, r1, addr) \
    asm volatile("ldmatrix.sync.aligned.m8n8.x2.trans.shared.b16 {%0,%1}, [%2];" \
                 : "=r"(r0), "=r"(r1) : "r"(addr))
#define MMAF16(c, a0, a1, a2, a3, b0, b1) \
    asm volatile("mma.sync.aligned.m16n8k16.row.col.f32.f16.f16.f32 " \
                 "{%0,%1,%2,%3}, {%4,%5,%6,%7}, {%8,%9}, {%0,%1,%2,%3};" \
                 : "+f"((c)[0]), "+f"((c)[1]), "+f"((c)[2]), "+f"((c)[3]) \
                 : "r"(a0), "r"(a1), "r"(a2), "r"(a3), "r"(b0), "r"(b1))

__device__ __forceinline__ unsigned hpack2(float a, float b) {
    __half2 h = __floats2half2_rn(a, b);
    return *(unsigned*)&h;
}

// ===== mega smem geometry: A tile + TWO W buffers (hi only) = 102 KB, 2 CTAs/SM =====
#define AST    272
#define MS_AH  0
#define MS_W0  34816
#define MS_W1  69632
#define MEGA_SMEM 104448

// decoder gemm geometry (single product)
#define A_STRIDE 80
#define B_STRIDE 272
#define OFF_BHI  10240
#define ABUF     18944
#define SMEM_GEMM (2 * ABUF)

// ---------------- preprocessing ----------------
__global__ void count_deg_kernel(const int* __restrict__ dst, int* __restrict__ deg, int E) {
    int i = blockIdx.x * blockDim.x + threadIdx.x;
    if (i < E) atomicAdd(&deg[dst[i]], 1);
}
__global__ void count_nodes_kernel(const int* __restrict__ batch, float* __restrict__ cnt, int M) {
    int i = blockIdx.x * blockDim.x + threadIdx.x;
    if (i < M) atomicAdd(&cnt[batch[i]], 1.0f);
}
__global__ __launch_bounds__(1024)
void scan_offsets_kernel(const int* __restrict__ deg, int* __restrict__ off,
                         int* __restrict__ cursor, float* __restrict__ dinv, int M) {
    __shared__ int part[1024];
    int t = threadIdx.x;
    int chunk = (M + 1023) >> 10;
    int base = t * chunk;
    int s = 0;
    for (int i = 0; i < chunk; i++) { int j = base + i; if (j < M) s += deg[j]; }
    part[t] = s;
    __syncthreads();
    for (int d = 1; d < 1024; d <<= 1) {
        int add = (t >= d) ? part[t - d] : 0;
        __syncthreads();
        part[t] += add;
        __syncthreads();
    }
    int run = part[t] - s;
    for (int i = 0; i < chunk; i++) {
        int j = base + i;
        if (j < M) {
            int dj = deg[j];
            off[j] = run; cursor[j] = run; run += dj;
            dinv[j] = rsqrtf((float)dj + 1.0f);
        }
    }
    if (t == 1023) off[M] = part[1023];
}
__global__ void csr_fill_kernel(const int* __restrict__ src, const int* __restrict__ dst,
                                int* __restrict__ cursor, int* __restrict__ csr, int E) {
    int i = blockIdx.x * blockDim.x + threadIdx.x;
    if (i < E) {
        int p = atomicAdd(&cursor[dst[i]], 1);
        csr[p] = src[i];
    }
}

// ---------------- weight convert (fp16, hi only) ----------------
struct WJob { const float* W; int elems; int off; };
struct WJobs { WJob j[11]; };
__global__ void wsplit_kernel(WJobs jobs, unsigned short* __restrict__ wh) {
    WJob jb = jobs.j[blockIdx.y];
    for (int i = blockIdx.x * blockDim.x + threadIdx.x; i < jb.elems;
         i += gridDim.x * blockDim.x) {
        wh[jb.off + i] = __half_as_ushort(__float2half_rn(jb.W[i]));
    }
}

// ---------------- gather ----------------
__global__ __launch_bounds__(256)
void gather_kernel(const int* __restrict__ off, const int* __restrict__ csr,
                   const float* __restrict__ u, const float* __restrict__ dinv,
                   const float* __restrict__ bgcn, float* __restrict__ g, int M) {
    int n = (blockIdx.x * blockDim.x + threadIdx.x) >> 5;
    if (n >= M) return;
    int lane = threadIdx.x & 31;
    int e0 = off[n], e1 = off[n + 1];
    int deg = e1 - e0;
    float4 acc = __ldg((const float4*)(u + (size_t)n * DL_ + lane * 4));
    for (int base = 0; base < deg; base += 32) {
        int cnt = min(32, deg - base);
        int idx = 0;
        if (base + lane < deg) idx = __ldg(csr + e0 + base + lane);
        int j = 0;
        for (; j + 8 <= cnt; j += 8) {
            float4 v[8];
#pragma unroll
            for (int q = 0; q < 8; q++) {
                int s = __shfl_sync(0xffffffffu, idx, j + q);
                v[q] = __ldg((const float4*)(u + (size_t)s * DL_ + lane * 4));
            }
#pragma unroll
            for (int q = 0; q < 8; q++) {
                acc.x += v[q].x; acc.y += v[q].y; acc.z += v[q].z; acc.w += v[q].w;
            }
        }
        for (; j < cnt; j++) {
            int s = __shfl_sync(0xffffffffu, idx, j);
            float4 v = __ldg((const float4*)(u + (size_t)s * DL_ + lane * 4));
            acc.x += v.x; acc.y += v.y; acc.z += v.z; acc.w += v.w;
        }
    }
    float dv = dinv[n];
    float4 b = *(const float4*)(bgcn + lane * 4);
    float4 o;
    o.x = fmaf(dv, acc.x, b.x);
    o.y = fmaf(dv, acc.y, b.y);
    o.z = fmaf(dv, acc.z, b.z);
    o.w = fmaf(dv, acc.w, b.w);
    *(float4*)(g + (size_t)n * DL_ + lane * 4) = o;
}

// ===== mega pieces (512 thr, warp 32x32, single fp16 product, double-buffered W) =====
__device__ __forceinline__ void stage_w128(unsigned sb, int woff, const __half* Wh,
                                           int nrows, int tid) {
    int chunks = nrows * 16;
    for (int idx = tid; idx < chunks; idx += 512) {
        int rowb = idx >> 4, cc = idx & 15;
        CP_ASYNC16(sb + woff + rowb * AST + cc * 16, (const char*)(Wh + rowb * 128) + cc * 16);
    }
    CP_COMMIT();
}

__device__ __forceinline__ void layer_mma(unsigned sb, int woff,
                                          int warp_m, int warp_n, int lane,
                                          int nks, float acc[2][4][4]) {
#pragma unroll
    for (int i = 0; i < 2; i++)
#pragma unroll
        for (int j = 0; j < 4; j++)
#pragma unroll
            for (int q = 0; q < 4; q++) acc[i][j][q] = 0.0f;
    const int arow = (lane & 7) + ((lane >> 3) & 1) * 8;
    const int akq  = lane >> 4;
    const int lane16 = lane & 15;
    for (int ks = 0; ks < nks; ks++) {
        unsigned aoff = sb + MS_AH + (warp_m + arow) * AST + (ks * 16 + akq * 8) * 2;
        unsigned boff = sb + woff + (ks * 16 + lane16) * AST + warp_n * 2;
        unsigned Ah[2][4], Bf[4][2];
#pragma unroll
        for (int tm = 0; tm < 2; tm++)
            LDSM_X4(Ah[tm][0], Ah[tm][1], Ah[tm][2], Ah[tm][3], aoff + tm * 16 * AST);
#pragma unroll
        for (int tn = 0; tn < 4; tn++)
            LDSM_X2T(Bf[tn][0], Bf[tn][1], boff + tn * 16);
#pragma unroll
        for (int tm = 0; tm < 2; tm++)
#pragma unroll
            for (int tn = 0; tn < 4; tn++)
                MMAF16(acc[tm][tn], Ah[tm][0], Ah[tm][1], Ah[tm][2], Ah[tm][3],
                       Bf[tn][0], Bf[tn][1]);
    }
}

__device__ __forceinline__ void store_act_sig(char* smem, float acc[2][4][4],
                                              const float* __restrict__ bias,
                                              int warp_m, int warp_n, int lane) {
#pragma unroll
    for (int tn = 0; tn < 4; tn++) {
        int c = warp_n + tn * 8 + (lane & 3) * 2;
        float b0 = __ldg(bias + c), b1 = __ldg(bias + c + 1);
#pragma unroll
        for (int tm = 0; tm < 2; tm++)
#pragma unroll
            for (int half = 0; half < 2; half++) {
                int r = warp_m + tm * 16 + (lane >> 2) + half * 8;
                float v0 = acc[tm][tn][half * 2]     + b0;
                float v1 = acc[tm][tn][half * 2 + 1] + b1;
                v0 = __fdividef(1.0f, 1.0f + __expf(-v0));
                v1 = __fdividef(1.0f, 1.0f + __expf(-v1));
                *(unsigned*)(smem + MS_AH + r * AST + c * 2) = hpack2(v0, v1);
            }
    }
}

// mode 0 = input (x -> h -> u); 1 = hop (g -> ... -> u); 2 = last hop (g -> mu,std,h)
__global__ __launch_bounds__(512, 2)
void mega_kernel(int mode, const float* __restrict__ Ain,
                 const __half* __restrict__ WH,
                 int o_first, const float* __restrict__ b_first,
                 int o_gcn, int o_enc0, const float* __restrict__ b_enc,
                 int o_mu, const float* __restrict__ b_mu,
                 int o_std, const float* __restrict__ b_std,
                 const float* __restrict__ dinv, const float* __restrict__ eps_it,
                 float* __restrict__ u_out, float* __restrict__ mu_out,
                 float* __restrict__ std_out, float* __restrict__ h_out, int M) {
    extern __shared__ __align__(16) char smem[];
    const unsigned sb = smem_u32(smem);
    const int tid  = threadIdx.x;
    const int wid  = tid >> 5;
    const int lane = tid & 31;
    const int brow = blockIdx.x * 128;
    const int warp_m = (wid >> 2) * 32;
    const int warp_n = (wid & 3) * 32;

    // ---- stage initial A (fp32 global -> fp16 smem) + first W -> W0 ----
    {
        const int K0 = (mode == 0) ? DIN_ : DL_;
        const int qK = K0 >> 2;
        int row = tid >> 2;
        int c0 = (tid & 3) * qK;
        bool ok = (brow + row) < M;
        const float* Ar = Ain + (size_t)(brow + row) * K0 + c0;
        for (int i4 = 0; i4 < (qK >> 2); i4++) {
            float4 v = ok ? *(const float4*)(Ar + i4 * 4) : make_float4(0.f, 0.f, 0.f, 0.f);
            int c = c0 + i4 * 4;
            *(uint2*)(smem + MS_AH + row * AST + c * 2) =
                make_uint2(hpack2(v.x, v.y), hpack2(v.z, v.w));
        }
    }
    stage_w128(sb, MS_W0, WH + ((mode == 0) ? o_first : o_enc0),
               (mode == 0) ? 32 : 128, tid);
    CP_WAIT0();
    __syncthreads();

    float acc[2][4][4];

    if (mode == 0) {
        stage_w128(sb, MS_W1, WH + o_gcn, 128, tid);   // overlap with first mma
        layer_mma(sb, MS_W0, warp_m, warp_n, lane, 2, acc);
        __syncthreads();
        store_act_sig(smem, acc, b_first, warp_m, warp_n, lane);
        CP_WAIT0();
        __syncthreads();
        layer_mma(sb, MS_W1, warp_m, warp_n, lane, 8, acc);
#pragma unroll
        for (int tm = 0; tm < 2; tm++)
#pragma unroll
            for (int half = 0; half < 2; half++) {
                int r = brow + warp_m + tm * 16 + (lane >> 2) + half * 8;
                if (r >= M) continue;
                float rs = __ldg(dinv + r);
#pragma unroll
                for (int tn = 0; tn < 4; tn++) {
                    int c = warp_n + tn * 8 + (lane & 3) * 2;
                    float2 o;
                    o.x = acc[tm][tn][half * 2]     * rs;
                    o.y = acc[tm][tn][half * 2 + 1] * rs;
                    *(float2*)(u_out + (size_t)r * DL_ + c) = o;
                }
            }
        return;
    }

    // ---- hop: enc x5 (ping-pong W buffers; stage next during current mma) ----
    for (int j = 0; j < 5; j++) {
        int cb = (j & 1) ? MS_W1 : MS_W0;
        int nb = (j & 1) ? MS_W0 : MS_W1;
        int nxt = (j < 4) ? (o_enc0 + (j + 1) * 16384) : o_mu;
        stage_w128(sb, nb, WH + nxt, 128, tid);
        layer_mma(sb, cb, warp_m, warp_n, lane, 8, acc);
        __syncthreads();
        store_act_sig(smem, acc, b_enc + j * DL_, warp_m, warp_n, lane);
        CP_WAIT0();
        __syncthreads();
    }
    // ---- mu (W in W1); stage W_std -> W0 during mma ----
    stage_w128(sb, MS_W0, WH + o_std, 128, tid);
    layer_mma(sb, MS_W1, warp_m, warp_n, lane, 8, acc);
#pragma unroll
    for (int tn = 0; tn < 4; tn++) {
        int c = warp_n + tn * 8 + (lane & 3) * 2;
        float b0 = __ldg(b_mu + c), b1 = __ldg(b_mu + c + 1);
#pragma unroll
        for (int tm = 0; tm < 2; tm++)
#pragma unroll
            for (int half = 0; half < 2; half++) {
                int r = brow + warp_m + tm * 16 + (lane >> 2) + half * 8;
                if (r >= M) continue;
                float2 v;
                v.x = acc[tm][tn][half * 2]     + b0;
                v.y = acc[tm][tn][half * 2 + 1] + b1;
                *(float2*)(mu_out + (size_t)r * DL_ + c) = v;
            }
    }
    CP_WAIT0();
    __syncthreads();
    // ---- std (W in W0); stage gcn -> W1 during mma (mode 1) ----
    if (mode == 1) stage_w128(sb, MS_W1, WH + o_gcn, 128, tid);
    layer_mma(sb, MS_W0, warp_m, warp_n, lane, 8, acc);
    __syncthreads();   // A-tile reads done before combine overwrites it
    // combine: h = mu(global) + softplus(std)*eps -> resident A; std/h out if last hop
#pragma unroll
    for (int tn = 0; tn < 4; tn++) {
        int c = warp_n + tn * 8 + (lane & 3) * 2;
        float b0 = __ldg(b_std + c), b1 = __ldg(b_std + c + 1);
#pragma unroll
        for (int tm = 0; tm < 2; tm++)
#pragma unroll
            for (int half = 0; half < 2; half++) {
                int r = warp_m + tm * 16 + (lane >> 2) + half * 8;
                int gr = brow + r;
                float s0 = acc[tm][tn][half * 2]     + b0 - 5.0f;
                float s1 = acc[tm][tn][half * 2 + 1] + b1 - 5.0f;
                s0 = (s0 > 20.0f) ? s0 : log1pf(expf(s0));
                s1 = (s1 > 20.0f) ? s1 : log1pf(expf(s1));
                float2 m = make_float2(0.f, 0.f), e = make_float2(0.f, 0.f);
                if (gr < M) {
                    m = *(const float2*)(mu_out + (size_t)gr * DL_ + c);
                    e = *(const float2*)(eps_it + (size_t)gr * DL_ + c);
                }
                float h0 = fmaf(s0, e.x, m.x);
                float h1 = fmaf(s1, e.y, m.y);
                if (mode == 2 && gr < M) {
                    float2 so; so.x = s0; so.y = s1;
                    *(float2*)(std_out + (size_t)gr * DL_ + c) = so;
                    float2 ho; ho.x = h0; ho.y = h1;
                    *(float2*)(h_out + (size_t)gr * DL_ + c) = ho;
                }
                *(unsigned*)(smem + MS_AH + r * AST + c * 2) = hpack2(h0, h1);
            }
    }
    if (mode == 2) return;
    CP_WAIT0();
    __syncthreads();
    // ---- gcn: u = h @ W_gcn * dinv ----
    layer_mma(sb, MS_W1, warp_m, warp_n, lane, 8, acc);
#pragma unroll
    for (int tm = 0; tm < 2; tm++)
#pragma unroll
        for (int half = 0; half < 2; half++) {
            int r = brow + warp_m + tm * 16 + (lane >> 2) + half * 8;
            if (r >= M) continue;
            float rs = __ldg(dinv + r);
#pragma unroll
            for (int tn = 0; tn < 4; tn++) {
                int c = warp_n + tn * 8 + (lane & 3) * 2;
                float2 o;
                o.x = acc[tm][tn][half * 2]     * rs;
                o.y = acc[tm][tn][half * 2 + 1] * rs;
                *(float2*)(u_out + (size_t)r * DL_ + c) = o;
            }
        }
}

// ---------------- decoder GEMM (single fp16 product) ----------------
__global__ __launch_bounds__(256)
void gemm_mma(const float* __restrict__ A, const __half* __restrict__ Bh,
              const float* __restrict__ bias, float* __restrict__ C,
              int M, int K, int ldb, int Ncs, int col0) {
    extern __shared__ __align__(16) char smem[];
    const unsigned sb = smem_u32(smem);
    const int tid  = threadIdx.x;
    const int wid  = tid >> 5;
    const int lane = tid & 31;
    const int brow = blockIdx.x * 128;
    const int warp_m = (wid >> 2) * 64;
    const int warp_n = (wid & 3) * 32;
    const int arow   = (lane & 7) + ((lane >> 3) & 1) * 8;
    const int akq    = (lane >> 4);
    const int lane16 = lane & 15;

    float acc[4][4][4];
#pragma unroll
    for (int i = 0; i < 4; i++)
#pragma unroll
        for (int j = 0; j < 4; j++)
#pragma unroll
            for (int q = 0; q < 4; q++) acc[i][j][q] = 0.0f;

    const int nkt = K >> 5;
    const int sr  = tid >> 1;
    const int skh = (tid & 1) * 16;

#define STAGE_BD(bufi, kt) do { \
    unsigned dbase = sb + (bufi) * ABUF; \
    _Pragma("unroll") \
    for (int s2 = 0; s2 < 2; s2++) { \
        int idx = tid + s2 * 256; \
        int rowb = idx >> 4, cc = idx & 15; \
        const char* sh = (const char*)(Bh + (size_t)((kt) * 32 + rowb) * ldb) + cc * 16; \
        CP_ASYNC16(dbase + OFF_BHI + rowb * B_STRIDE + cc * 16, sh); \
    } \
    CP_COMMIT(); \
} while (0)

#define STAGE_AD(bufi, kt) do { \
    char* dh = smem + (bufi) * ABUF; \
    const float* Ar = A + (size_t)(brow + sr) * K + (kt) * 32 + skh; \
    bool okr = (brow + sr) < M; \
    _Pragma("unroll") \
    for (int i4 = 0; i4 < 4; i4++) { \
        float4 v = okr ? *(const float4*)(Ar + i4 * 4) : make_float4(0.f, 0.f, 0.f, 0.f); \
        *(uint2*)(dh + sr * A_STRIDE + (skh + i4 * 4) * 2) = \
            make_uint2(hpack2(v.x, v.y), hpack2(v.z, v.w)); \
    } \
} while (0)

    STAGE_BD(0, 0);
    STAGE_AD(0, 0);
    CP_WAIT0();
    __syncthreads();

    for (int kt = 0; kt < nkt; kt++) {
        const int buf = kt & 1;
        const bool more = (kt + 1) < nkt;
        if (more) {
            STAGE_BD(buf ^ 1, kt + 1);
            STAGE_AD(buf ^ 1, kt + 1);
        }
        const unsigned sba = sb + buf * ABUF;
#pragma unroll
        for (int ks = 0; ks < 2; ks++) {
            unsigned aoff = sba + (warp_m + arow) * A_STRIDE + (ks * 16 + akq * 8) * 2;
            unsigned boff = sba + OFF_BHI + (ks * 16 + lane16) * B_STRIDE + warp_n * 2;
            unsigned Ah[4][4], Bf[4][2];
#pragma unroll
            for (int tm = 0; tm < 4; tm++)
                LDSM_X4(Ah[tm][0], Ah[tm][1], Ah[tm][2], Ah[tm][3], aoff + tm * 16 * A_STRIDE);
#pragma unroll
            for (int tn = 0; tn < 4; tn++)
                LDSM_X2T(Bf[tn][0], Bf[tn][1], boff + tn * 16);
#pragma unroll
            for (int tm = 0; tm < 4; tm++)
#pragma unroll
                for (int tn = 0; tn < 4; tn++)
                    MMAF16(acc[tm][tn], Ah[tm][0], Ah[tm][1], Ah[tm][2], Ah[tm][3],
                           Bf[tn][0], Bf[tn][1]);
        }
        if (more) CP_WAIT0();
        __syncthreads();
    }

#pragma unroll
    for (int tm = 0; tm < 4; tm++) {
#pragma unroll
        for (int tn = 0; tn < 4; tn++) {
            int gcol = col0 + warp_n + tn * 8 + (lane & 3) * 2;
            float bb0 = __ldg(bias + gcol), bb1 = __ldg(bias + gcol + 1);
#pragma unroll
            for (int half = 0; half < 2; half++) {
                int r = brow + warp_m + tm * 16 + (lane >> 2) + half * 8;
                if (r >= M) continue;
                float v0 = fmaxf(acc[tm][tn][half * 2 + 0] + bb0, 0.0f);
                float v1 = fmaxf(acc[tm][tn][half * 2 + 1] + bb1, 0.0f);
                float2 o; o.x = v0; o.y = v1;
                *(float2*)(C + (size_t)r * Ncs + gcol) = o;
            }
        }
    }
}

// ---------------- fused decoder tail ----------------
__global__ __launch_bounds__(128)
void decoder_tail_kernel(const float* __restrict__ din,
                         const float* __restrict__ W2, const float* __restrict__ b2,
                         const float* __restrict__ W3, const float* __restrict__ b3,
                         const float* __restrict__ W4, const float* __restrict__ b4,
                         const float* __restrict__ Wo, const float* __restrict__ bo,
                         const int* __restrict__ batch, float* __restrict__ sums, int M) {
    __shared__ float w2[128 * 64];
    __shared__ float w3[64 * 32];
    __shared__ float w4[32 * 16];
    __shared__ float wo[160];
    __shared__ float xs [4][128];
    __shared__ float t64[4][64];
    __shared__ float t32[4][32];
    __shared__ float t16[4][16];
    for (int i = threadIdx.x; i < 128 * 64; i += 128) w2[i] = W2[i];
    for (int i = threadIdx.x; i < 64 * 32;  i += 128) w3[i] = W3[i];
    for (int i = threadIdx.x; i < 32 * 16;  i += 128) w4[i] = W4[i];
    for (int i = threadIdx.x; i < 160;      i += 128) wo[i] = Wo[i];
    __syncthreads();
    int warp = threadIdx.x >> 5;
    int lane = threadIdx.x & 31;
    int stride = gridDim.x * 4;
    for (int row = blockIdx.x * 4 + warp; row < M; row += stride) {
        *(float4*)&xs[warp][lane * 4] = *(const float4*)(din + (size_t)row * 128 + lane * 4);
        __syncwarp();
        float s0 = b2[lane], s1 = b2[lane + 32];
#pragma unroll 8
        for (int k = 0; k < 128; k++) {
            float xv = xs[warp][k];
            s0 = fmaf(xv, w2[k * 64 + lane],      s0);
            s1 = fmaf(xv, w2[k * 64 + lane + 32], s1);
        }
        t64[warp][lane]      = fmaxf(s0, 0.0f);
        t64[warp][lane + 32] = fmaxf(s1, 0.0f);
        __syncwarp();
        float s = b3[lane];
#pragma unroll 8
        for (int k = 0; k < 64; k++) s = fmaf(t64[warp][k], w3[k * 32 + lane], s);
        t32[warp][lane] = fmaxf(s, 0.0f);
        __syncwarp();
        if (lane < 16) {
            float t = b4[lane];
#pragma unroll
            for (int k = 0; k < 32; k++) t = fmaf(t32[warp][k], w4[k * 16 + lane], t);
            t16[warp][lane] = fmaxf(t, 0.0f);
        }
        __syncwarp();
        if (lane < 10) {
            float t = bo[lane];
#pragma unroll
            for (int k = 0; k < 16; k++) t = fmaf(t16[warp][k], wo[k * 10 + lane], t);
            float yp = __fdividef(1.0f, 1.0f + __expf(-t));
            atomicAdd(&sums[batch[row] * 10 + lane], yp);
        }
        __syncwarp();
    }
}

__global__ void pool_finalize_kernel(const float* __restrict__ sums, const float* __restrict__ cnt,
                                     const float* __restrict__ y,
                                     float* __restrict__ out_pred, float* __restrict__ out_y) {
    int i = blockIdx.x * blockDim.x + threadIdx.x;
    if (i < GG * DOUT_) {
        out_pred[i] = sums[i] / fmaxf(cnt[i / DOUT_], 1.0f);
        out_y[i]    = y[i];
    }
}

// ---------------- launch ----------------
extern "C" void kernel_launch(void* const* d_in, const int* in_sizes, int n_in,
                              void* d_out, int out_size) {
    const float* x     = (const float*)d_in[0];
    const int*   ei    = (const int*)  d_in[1];
    const int*   batch = (const int*)  d_in[2];
    const float* y     = (const float*)d_in[3];
    const float* eps   = (const float*)d_in[4];
    const float* W_in  = (const float*)d_in[5];
    const float* b_in  = (const float*)d_in[6];
    const float* W_gcn = (const float*)d_in[7];
    const float* b_gcn = (const float*)d_in[8];
    const float* W_enc = (const float*)d_in[9];
    const float* b_enc = (const float*)d_in[10];
    const float* W_mu  = (const float*)d_in[11];
    const float* b_mu  = (const float*)d_in[12];
    const float* W_std = (const float*)d_in[13];
    const float* b_std = (const float*)d_in[14];
    const float* Wd0 = (const float*)d_in[15]; const float* bd0 = (const float*)d_in[16];
    const float* Wd1 = (const float*)d_in[17]; const float* bd1 = (const float*)d_in[18];
    const float* Wd2 = (const float*)d_in[19]; const float* bd2 = (const float*)d_in[20];
    const float* Wd3 = (const float*)d_in[21]; const float* bd3 = (const float*)d_in[22];
    const float* Wd4 = (const float*)d_in[23]; const float* bd4 = (const float*)d_in[24];
    const float* Wo  = (const float*)d_in[25]; const float* bo  = (const float*)d_in[26];

    float *h, *u, *gbuf, *dec1, *dinv, *sums, *cnt;
    int *deg, *off, *cur, *csr;
    unsigned short *wh;
    cudaGetSymbolAddress((void**)&h,    g_h);
    cudaGetSymbolAddress((void**)&u,    g_u);
    cudaGetSymbolAddress((void**)&gbuf, g_g);
    cudaGetSymbolAddress((void**)&dec1, g_dec1);
    cudaGetSymbolAddress((void**)&dinv, g_dinv);
    cudaGetSymbolAddress((void**)&deg,  g_deg);
    cudaGetSymbolAddress((void**)&off,  g_off);
    cudaGetSymbolAddress((void**)&cur,  g_cur);
    cudaGetSymbolAddress((void**)&csr,  g_csr);
    cudaGetSymbolAddress((void**)&sums, g_sums);
    cudaGetSymbolAddress((void**)&cnt,  g_cnt);
    cudaGetSymbolAddress((void**)&wh,   g_wh);

    float* out      = (float*)d_out;
    float* out_pred = out;
    float* out_mu   = out + GG * DOUT_;
    float* out_std  = out + GG * DOUT_ + (size_t)NN * DL_;
    float* out_y    = out + GG * DOUT_ + (size_t)2 * NN * DL_;

    const int* src = ei;
    const int* dst = ei + EE;

    cudaFuncSetAttribute(mega_kernel, cudaFuncAttributeMaxDynamicSharedMemorySize, MEGA_SMEM);
    cudaFuncSetAttribute(gemm_mma,   cudaFuncAttributeMaxDynamicSharedMemorySize, SMEM_GEMM);

    WJobs jobs;
    int O[11];
    {
        int o = 0;
        auto set = [&](int i, const float* W, int elems) {
            jobs.j[i].W = W; jobs.j[i].elems = elems; jobs.j[i].off = o; O[i] = o; o += elems;
        };
        set(0, W_in, 32 * 128);
        set(1, W_gcn, 128 * 128);
        for (int j = 0; j < 5; j++) set(2 + j, W_enc + (size_t)j * DL_ * DL_, 128 * 128);
        set(7, W_mu, 128 * 128);
        set(8, W_std, 128 * 128);
        set(9, Wd0, 128 * 256);
        set(10, Wd1, 256 * 128);
    }
    const int GRID = (NN + 127) / 128;
    const __half* WH = (const __half*)wh;

    // order chosen so a mega lands in the ncu -s 5 capture window
    wsplit_kernel<<<dim3(32, 11), 256>>>(jobs, wh);
    cudaMemsetAsync(deg, 0, NN * sizeof(int));
    count_deg_kernel   <<<(EE + 255) / 256, 256>>>(dst, deg, EE);
    scan_offsets_kernel<<<1, 1024>>>(deg, off, cur, dinv, NN);
    mega_kernel<<<GRID, 512, MEGA_SMEM>>>(0, x, WH, O[0], b_in, O[1], O[2], b_enc,
                                          O[7], b_mu, O[8], b_std, dinv, nullptr,
                                          u, out_mu, nullptr, nullptr, NN);
    csr_fill_kernel    <<<(EE + 255) / 256, 256>>>(src, dst, cur, csr, EE);

    for (int it = 0; it < KK; it++) {
        gather_kernel<<<(NN * 32 + 255) / 256, 256>>>(off, csr, u, dinv, b_gcn, gbuf, NN);
        int mode = (it == KK - 1) ? 2 : 1;
        mega_kernel<<<GRID, 512, MEGA_SMEM>>>(mode, gbuf, WH, O[0], b_in, O[1], O[2], b_enc,
                                              O[7], b_mu, O[8], b_std, dinv,
                                              eps + (size_t)it * NN * DL_,
                                              u, out_mu, out_std, h, NN);
    }

    gemm_mma<<<GRID, 256, SMEM_GEMM>>>(h, WH + O[9], bd0, dec1, NN, 128, 256, 256, 0);
    gemm_mma<<<GRID, 256, SMEM_GEMM>>>(h, WH + O[9] + 128, bd0, dec1, NN, 128, 256, 256, 128);
    gemm_mma<<<GRID, 256, SMEM_GEMM>>>(dec1, WH + O[10], bd1, u, NN, 256, 128, 128, 0);

    cudaMemsetAsync(sums, 0, GG * DOUT_ * sizeof(float));
    cudaMemsetAsync(cnt,  0, GG * sizeof(float));
    count_nodes_kernel<<<(NN + 255) / 256, 256>>>(batch, cnt, NN);
    decoder_tail_kernel<<<592, 128>>>(u, Wd2, bd2, Wd3, bd3, Wd4, bd4, Wo, bo,
                                      batch, sums, NN);
    pool_finalize_kernel<<<(GG * DOUT_ + 255) / 256, 256>>>(sums, cnt, y, out_pred, out_y);

    (void)in_sizes; (void)n_in; (void)out_size;
}

// round 13
// speedup vs baseline: 3.4674x; 1.0328x over previous
#include <cuda_runtime.h>
#include <cuda_fp16.h>
#include <math.h>

#define NN   50000
#define EE   800000
#define DIN_ 32
#define DL_  128
#define DOUT_ 10
#define GG   256
#define KK   3

// ---------------- scratch (device globals) ----------------
__device__ __align__(16) float g_h  [NN * DL_];
__device__ __align__(16) float g_u  [NN * DL_];
__device__ __align__(16) float g_dec1[NN * 256];
__device__ __align__(16) float g_dinv[NN];
__device__ __align__(16) int   g_deg [NN];
__device__ __align__(16) int   g_off [NN + 1];
__device__ __align__(16) int   g_cur [NN];
__device__ __align__(16) int   g_csr [EE];
__device__ __align__(16) float g_sums[GG * DOUT_];
__device__ __align__(16) float g_cnt [GG];
__device__ __align__(16) unsigned short g_wh[184320];

// ---------------- asm helpers ----------------
__device__ __forceinline__ unsigned smem_u32(const void* p) {
    unsigned a;
    asm("{ .reg .u64 t; cvta.to.shared.u64 t, %1; cvt.u32.u64 %0, t; }" : "=r"(a) : "l"(p));
    return a;
}
#define CP_ASYNC16(dst_u32, src) \
    asm volatile("cp.async.ca.shared.global [%0], [%1], 16;" :: "r"(dst_u32), "l"(src))
#define CP_COMMIT() asm volatile("cp.async.commit_group;")
#define CP_WAIT0()  asm volatile("cp.async.wait_group 0;")
#define LDSM_X4(r0, r1, r2, r3, addr) \
    asm volatile("ldmatrix.sync.aligned.m8n8.x4.shared.b16 {%0,%1,%2,%3}, [%4];" \
                 : "=r"(r0), "=r"(r1), "=r"(r2), "=r"(r3) : "r"(addr))
#define LDSM_X2T(r0, r1, addr) \
    asm volatile("ldmatrix.sync.aligned.m8n8.x2.trans.shared.b16 {%0,%1}, [%2];" \
                 : "=r"(r0), "=r"(r1) : "r"(addr))
#define MMAF16(c, a0, a1, a2, a3, b0, b1) \
    asm volatile("mma.sync.aligned.m16n8k16.row.col.f32.f16.f16.f32 " \
                 "{%0,%1,%2,%3}, {%4,%5,%6,%7}, {%8,%9}, {%0,%1,%2,%3};" \
                 : "+f"((c)[0]), "+f"((c)[1]), "+f"((c)[2]), "+f"((c)[3]) \
                 : "r"(a0), "r"(a1), "r"(a2), "r"(a3), "r"(b0), "r"(b1))
#define BAR_GROUP(id) asm volatile("bar.sync %0, 128;" :: "r"(id) : "memory")

__device__ __forceinline__ unsigned hpack2(float a, float b) {
    __half2 h = __floats2half2_rn(a, b);
    return *(unsigned*)&h;
}

// ===== mega smem geometry: A tile + TWO W buffers (hi only) = 102 KB, 2 CTAs/SM =====
#define AST    272
#define MS_AH  0
#define MS_W0  34816
#define MS_W1  69632
#define MEGA_SMEM 104448

// decoder gemm geometry (single product)
#define A_STRIDE 80
#define B_STRIDE 272
#define OFF_BHI  10240
#define ABUF     18944
#define SMEM_GEMM (2 * ABUF)

// ---------------- preprocessing ----------------
__global__ void count_deg_kernel(const int* __restrict__ dst, int* __restrict__ deg, int E) {
    int i = blockIdx.x * blockDim.x + threadIdx.x;
    if (i < E) atomicAdd(&deg[dst[i]], 1);
}
__global__ void count_nodes_kernel(const int* __restrict__ batch, float* __restrict__ cnt, int M) {
    int i = blockIdx.x * blockDim.x + threadIdx.x;
    if (i < M) atomicAdd(&cnt[batch[i]], 1.0f);
}
__global__ __launch_bounds__(1024)
void scan_offsets_kernel(const int* __restrict__ deg, int* __restrict__ off,
                         int* __restrict__ cursor, float* __restrict__ dinv, int M) {
    __shared__ int part[1024];
    int t = threadIdx.x;
    int chunk = (M + 1023) >> 10;
    int base = t * chunk;
    int s = 0;
    for (int i = 0; i < chunk; i++) { int j = base + i; if (j < M) s += deg[j]; }
    part[t] = s;
    __syncthreads();
    for (int d = 1; d < 1024; d <<= 1) {
        int add = (t >= d) ? part[t - d] : 0;
        __syncthreads();
        part[t] += add;
        __syncthreads();
    }
    int run = part[t] - s;
    for (int i = 0; i < chunk; i++) {
        int j = base + i;
        if (j < M) {
            int dj = deg[j];
            off[j] = run; cursor[j] = run; run += dj;
            dinv[j] = rsqrtf((float)dj + 1.0f);
        }
    }
    if (t == 1023) off[M] = part[1023];
}
__global__ void csr_fill_kernel(const int* __restrict__ src, const int* __restrict__ dst,
                                int* __restrict__ cursor, int* __restrict__ csr, int E) {
    int i = blockIdx.x * blockDim.x + threadIdx.x;
    if (i < E) {
        int p = atomicAdd(&cursor[dst[i]], 1);
        csr[p] = src[i];
    }
}

// ---------------- weight convert (fp16) ----------------
struct WJob { const float* W; int elems; int off; };
struct WJobs { WJob j[11]; };
__global__ void wsplit_kernel(WJobs jobs, unsigned short* __restrict__ wh) {
    WJob jb = jobs.j[blockIdx.y];
    for (int i = blockIdx.x * blockDim.x + threadIdx.x; i < jb.elems;
         i += gridDim.x * blockDim.x) {
        wh[jb.off + i] = __half_as_ushort(__float2half_rn(jb.W[i]));
    }
}

// ===== mega pieces (512 thr, warp 32x32, single fp16 product, double-buffered W) =====
__device__ __forceinline__ void stage_w128(unsigned sb, int woff, const __half* Wh,
                                           int nrows, int tid) {
    int chunks = nrows * 16;
    for (int idx = tid; idx < chunks; idx += 512) {
        int rowb = idx >> 4, cc = idx & 15;
        CP_ASYNC16(sb + woff + rowb * AST + cc * 16, (const char*)(Wh + rowb * 128) + cc * 16);
    }
    CP_COMMIT();
}

__device__ __forceinline__ void layer_mma(unsigned sb, int woff,
                                          int warp_m, int warp_n, int lane,
                                          int nks, float acc[2][4][4]) {
#pragma unroll
    for (int i = 0; i < 2; i++)
#pragma unroll
        for (int j = 0; j < 4; j++)
#pragma unroll
            for (int q = 0; q < 4; q++) acc[i][j][q] = 0.0f;
    const int arow = (lane & 7) + ((lane >> 3) & 1) * 8;
    const int akq  = lane >> 4;
    const int lane16 = lane & 15;
    for (int ks = 0; ks < nks; ks++) {
        unsigned aoff = sb + MS_AH + (warp_m + arow) * AST + (ks * 16 + akq * 8) * 2;
        unsigned boff = sb + woff + (ks * 16 + lane16) * AST + warp_n * 2;
        unsigned Ah[2][4], Bf[4][2];
#pragma unroll
        for (int tm = 0; tm < 2; tm++)
            LDSM_X4(Ah[tm][0], Ah[tm][1], Ah[tm][2], Ah[tm][3], aoff + tm * 16 * AST);
#pragma unroll
        for (int tn = 0; tn < 4; tn++)
            LDSM_X2T(Bf[tn][0], Bf[tn][1], boff + tn * 16);
#pragma unroll
        for (int tm = 0; tm < 2; tm++)
#pragma unroll
            for (int tn = 0; tn < 4; tn++)
                MMAF16(acc[tm][tn], Ah[tm][0], Ah[tm][1], Ah[tm][2], Ah[tm][3],
                       Bf[tn][0], Bf[tn][1]);
    }
}

__device__ __forceinline__ void store_act_sig(char* smem, float acc[2][4][4],
                                              const float* __restrict__ bias,
                                              int warp_m, int warp_n, int lane) {
#pragma unroll
    for (int tn = 0; tn < 4; tn++) {
        int c = warp_n + tn * 8 + (lane & 3) * 2;
        float b0 = __ldg(bias + c), b1 = __ldg(bias + c + 1);
#pragma unroll
        for (int tm = 0; tm < 2; tm++)
#pragma unroll
            for (int half = 0; half < 2; half++) {
                int r = warp_m + tm * 16 + (lane >> 2) + half * 8;
                float v0 = acc[tm][tn][half * 2]     + b0;
                float v1 = acc[tm][tn][half * 2 + 1] + b1;
                v0 = __fdividef(1.0f, 1.0f + __expf(-v0));
                v1 = __fdividef(1.0f, 1.0f + __expf(-v1));
                *(unsigned*)(smem + MS_AH + r * AST + c * 2) = hpack2(v0, v1);
            }
    }
}

// mode 0 = input (x -> h -> u); 1 = hop (gather -> ... -> u); 2 = last hop (gather -> mu,std,h)
__global__ __launch_bounds__(512, 2)
void mega_kernel(int mode, const float* __restrict__ Ain,
                 const __half* __restrict__ WH,
                 int o_first, const float* __restrict__ b_first,
                 int o_gcn, int o_enc0, const float* __restrict__ b_enc,
                 int o_mu, const float* __restrict__ b_mu,
                 int o_std, const float* __restrict__ b_std,
                 const float* __restrict__ dinv, const float* __restrict__ eps_it,
                 const int* __restrict__ off, const int* __restrict__ csr,
                 const float* __restrict__ bgcn,
                 float* __restrict__ u_out, float* __restrict__ mu_out,
                 float* __restrict__ std_out, float* __restrict__ h_out, int M) {
    extern __shared__ __align__(16) char smem[];
    const unsigned sb = smem_u32(smem);
    const int tid  = threadIdx.x;
    const int wid  = tid >> 5;
    const int lane = tid & 31;
    const int brow = blockIdx.x * 128;
    const int warp_m = (wid >> 2) * 32;
    const int warp_n = (wid & 3) * 32;
    const int gbar = 1 + (wid >> 2);   // row-group barrier id (1..4)

    // ---- first W -> W0 (issued before the long A staging so cp overlaps it) ----
    stage_w128(sb, MS_W0, WH + ((mode == 0) ? o_first : o_enc0),
               (mode == 0) ? 32 : 128, tid);

    if (mode == 0) {
        // plain A staging from x (fp32 -> fp16)
        int row = tid >> 2;
        int c0 = (tid & 3) * 8;
        bool ok = (brow + row) < M;
        const float* Ar = Ain + (size_t)(brow + row) * DIN_ + c0;
        for (int i4 = 0; i4 < 2; i4++) {
            float4 v = ok ? *(const float4*)(Ar + i4 * 4) : make_float4(0.f, 0.f, 0.f, 0.f);
            int c = c0 + i4 * 4;
            *(uint2*)(smem + MS_AH + row * AST + c * 2) =
                make_uint2(hpack2(v.x, v.y), hpack2(v.z, v.w));
        }
    } else {
        // fused gather staging: A[r] = fp16( dinv*(u_self + sum u_nbr) + b_gcn )
        float4 bg = *(const float4*)(bgcn + lane * 4);
        for (int rr = wid; rr < 128; rr += 16) {
            int gr = brow + rr;
            float4 a4 = make_float4(0.f, 0.f, 0.f, 0.f);
            if (gr < M) {
                a4 = __ldg((const float4*)(Ain + (size_t)gr * DL_ + lane * 4));
                int e0 = off[gr], e1 = off[gr + 1];
                int deg = e1 - e0;
                for (int base = 0; base < deg; base += 32) {
                    int cnt = min(32, deg - base);
                    int idx = 0;
                    if (base + lane < deg) idx = __ldg(csr + e0 + base + lane);
                    int j = 0;
                    for (; j + 8 <= cnt; j += 8) {
                        float4 v[8];
#pragma unroll
                        for (int q = 0; q < 8; q++) {
                            int s = __shfl_sync(0xffffffffu, idx, j + q);
                            v[q] = __ldg((const float4*)(Ain + (size_t)s * DL_ + lane * 4));
                        }
#pragma unroll
                        for (int q = 0; q < 8; q++) {
                            a4.x += v[q].x; a4.y += v[q].y; a4.z += v[q].z; a4.w += v[q].w;
                        }
                    }
                    for (; j < cnt; j++) {
                        int s = __shfl_sync(0xffffffffu, idx, j);
                        float4 v = __ldg((const float4*)(Ain + (size_t)s * DL_ + lane * 4));
                        a4.x += v.x; a4.y += v.y; a4.z += v.z; a4.w += v.w;
                    }
                }
                float dv = __ldg(dinv + gr);
                a4.x = fmaf(dv, a4.x, bg.x);
                a4.y = fmaf(dv, a4.y, bg.y);
                a4.z = fmaf(dv, a4.z, bg.z);
                a4.w = fmaf(dv, a4.w, bg.w);
            }
            *(uint2*)(smem + MS_AH + rr * AST + lane * 8) =
                make_uint2(hpack2(a4.x, a4.y), hpack2(a4.z, a4.w));
        }
    }
    CP_WAIT0();
    __syncthreads();

    float acc[2][4][4];

    if (mode == 0) {
        stage_w128(sb, MS_W1, WH + o_gcn, 128, tid);   // overlap with first mma
        layer_mma(sb, MS_W0, warp_m, warp_n, lane, 2, acc);
        BAR_GROUP(gbar);
        store_act_sig(smem, acc, b_first, warp_m, warp_n, lane);
        CP_WAIT0();
        __syncthreads();
        layer_mma(sb, MS_W1, warp_m, warp_n, lane, 8, acc);
#pragma unroll
        for (int tm = 0; tm < 2; tm++)
#pragma unroll
            for (int half = 0; half < 2; half++) {
                int r = brow + warp_m + tm * 16 + (lane >> 2) + half * 8;
                if (r >= M) continue;
                float rs = __ldg(dinv + r);
#pragma unroll
                for (int tn = 0; tn < 4; tn++) {
                    int c = warp_n + tn * 8 + (lane & 3) * 2;
                    float2 o;
                    o.x = acc[tm][tn][half * 2]     * rs;
                    o.y = acc[tm][tn][half * 2 + 1] * rs;
                    *(float2*)(u_out + (size_t)r * DL_ + c) = o;
                }
            }
        return;
    }

    // ---- hop: enc x5 (ping-pong W; stage next during current mma) ----
    for (int j = 0; j < 5; j++) {
        int cb = (j & 1) ? MS_W1 : MS_W0;
        int nb = (j & 1) ? MS_W0 : MS_W1;
        int nxt = (j < 4) ? (o_enc0 + (j + 1) * 16384) : o_mu;
        stage_w128(sb, nb, WH + nxt, 128, tid);
        layer_mma(sb, cb, warp_m, warp_n, lane, 8, acc);
        BAR_GROUP(gbar);
        store_act_sig(smem, acc, b_enc + j * DL_, warp_m, warp_n, lane);
        CP_WAIT0();
        __syncthreads();
    }
    // ---- mu (W in W1); stage W_std -> W0 during mma ----
    stage_w128(sb, MS_W0, WH + o_std, 128, tid);
    layer_mma(sb, MS_W1, warp_m, warp_n, lane, 8, acc);
#pragma unroll
    for (int tn = 0; tn < 4; tn++) {
        int c = warp_n + tn * 8 + (lane & 3) * 2;
        float b0 = __ldg(b_mu + c), b1 = __ldg(b_mu + c + 1);
#pragma unroll
        for (int tm = 0; tm < 2; tm++)
#pragma unroll
            for (int half = 0; half < 2; half++) {
                int r = brow + warp_m + tm * 16 + (lane >> 2) + half * 8;
                if (r >= M) continue;
                float2 v;
                v.x = acc[tm][tn][half * 2]     + b0;
                v.y = acc[tm][tn][half * 2 + 1] + b1;
                *(float2*)(mu_out + (size_t)r * DL_ + c) = v;
            }
    }
    CP_WAIT0();
    __syncthreads();
    // ---- std (W in W0); stage gcn -> W1 during mma (mode 1) ----
    if (mode == 1) stage_w128(sb, MS_W1, WH + o_gcn, 128, tid);
    layer_mma(sb, MS_W0, warp_m, warp_n, lane, 8, acc);
    BAR_GROUP(gbar);   // group's A reads done before combine overwrites
    // combine: h = mu(global) + softplus(std)*eps -> resident A; std/h out if last hop
#pragma unroll
    for (int tn = 0; tn < 4; tn++) {
        int c = warp_n + tn * 8 + (lane & 3) * 2;
        float b0 = __ldg(b_std + c), b1 = __ldg(b_std + c + 1);
#pragma unroll
        for (int tm = 0; tm < 2; tm++)
#pragma unroll
            for (int half = 0; half < 2; half++) {
                int r = warp_m + tm * 16 + (lane >> 2) + half * 8;
                int gr = brow + r;
                float s0 = acc[tm][tn][half * 2]     + b0 - 5.0f;
                float s1 = acc[tm][tn][half * 2 + 1] + b1 - 5.0f;
                s0 = (s0 > 20.0f) ? s0 : log1pf(expf(s0));
                s1 = (s1 > 20.0f) ? s1 : log1pf(expf(s1));
                float2 m = make_float2(0.f, 0.f), e = make_float2(0.f, 0.f);
                if (gr < M) {
                    m = *(const float2*)(mu_out + (size_t)gr * DL_ + c);
                    e = *(const float2*)(eps_it + (size_t)gr * DL_ + c);
                }
                float h0 = fmaf(s0, e.x, m.x);
                float h1 = fmaf(s1, e.y, m.y);
                if (mode == 2 && gr < M) {
                    float2 so; so.x = s0; so.y = s1;
                    *(float2*)(std_out + (size_t)gr * DL_ + c) = so;
                    float2 ho; ho.x = h0; ho.y = h1;
                    *(float2*)(h_out + (size_t)gr * DL_ + c) = ho;
                }
                *(unsigned*)(smem + MS_AH + r * AST + c * 2) = hpack2(h0, h1);
            }
    }
    if (mode == 2) return;
    CP_WAIT0();
    __syncthreads();
    // ---- gcn: u = h @ W_gcn * dinv ----
    layer_mma(sb, MS_W1, warp_m, warp_n, lane, 8, acc);
#pragma unroll
    for (int tm = 0; tm < 2; tm++)
#pragma unroll
        for (int half = 0; half < 2; half++) {
            int r = brow + warp_m + tm * 16 + (lane >> 2) + half * 8;
            if (r >= M) continue;
            float rs = __ldg(dinv + r);
#pragma unroll
            for (int tn = 0; tn < 4; tn++) {
                int c = warp_n + tn * 8 + (lane & 3) * 2;
                float2 o;
                o.x = acc[tm][tn][half * 2]     * rs;
                o.y = acc[tm][tn][half * 2 + 1] * rs;
                *(float2*)(u_out + (size_t)r * DL_ + c) = o;
            }
        }
}

// ---------------- decoder GEMM (single fp16 product) ----------------
__global__ __launch_bounds__(256)
void gemm_mma(const float* __restrict__ A, const __half* __restrict__ Bh,
              const float* __restrict__ bias, float* __restrict__ C,
              int M, int K, int ldb, int Ncs, int col0) {
    extern __shared__ __align__(16) char smem[];
    const unsigned sb = smem_u32(smem);
    const int tid  = threadIdx.x;
    const int wid  = tid >> 5;
    const int lane = tid & 31;
    const int brow = blockIdx.x * 128;
    const int warp_m = (wid >> 2) * 64;
    const int warp_n = (wid & 3) * 32;
    const int arow   = (lane & 7) + ((lane >> 3) & 1) * 8;
    const int akq    = (lane >> 4);
    const int lane16 = lane & 15;

    float acc[4][4][4];
#pragma unroll
    for (int i = 0; i < 4; i++)
#pragma unroll
        for (int j = 0; j < 4; j++)
#pragma unroll
            for (int q = 0; q < 4; q++) acc[i][j][q] = 0.0f;

    const int nkt = K >> 5;
    const int sr  = tid >> 1;
    const int skh = (tid & 1) * 16;

#define STAGE_BD(bufi, kt) do { \
    unsigned dbase = sb + (bufi) * ABUF; \
    _Pragma("unroll") \
    for (int s2 = 0; s2 < 2; s2++) { \
        int idx = tid + s2 * 256; \
        int rowb = idx >> 4, cc = idx & 15; \
        const char* sh = (const char*)(Bh + (size_t)((kt) * 32 + rowb) * ldb) + cc * 16; \
        CP_ASYNC16(dbase + OFF_BHI + rowb * B_STRIDE + cc * 16, sh); \
    } \
    CP_COMMIT(); \
} while (0)

#define STAGE_AD(bufi, kt) do { \
    char* dh = smem + (bufi) * ABUF; \
    const float* Ar = A + (size_t)(brow + sr) * K + (kt) * 32 + skh; \
    bool okr = (brow + sr) < M; \
    _Pragma("unroll") \
    for (int i4 = 0; i4 < 4; i4++) { \
        float4 v = okr ? *(const float4*)(Ar + i4 * 4) : make_float4(0.f, 0.f, 0.f, 0.f); \
        *(uint2*)(dh + sr * A_STRIDE + (skh + i4 * 4) * 2) = \
            make_uint2(hpack2(v.x, v.y), hpack2(v.z, v.w)); \
    } \
} while (0)

    STAGE_BD(0, 0);
    STAGE_AD(0, 0);
    CP_WAIT0();
    __syncthreads();

    for (int kt = 0; kt < nkt; kt++) {
        const int buf = kt & 1;
        const bool more = (kt + 1) < nkt;
        if (more) {
            STAGE_BD(buf ^ 1, kt + 1);
            STAGE_AD(buf ^ 1, kt + 1);
        }
        const unsigned sba = sb + buf * ABUF;
#pragma unroll
        for (int ks = 0; ks < 2; ks++) {
            unsigned aoff = sba + (warp_m + arow) * A_STRIDE + (ks * 16 + akq * 8) * 2;
            unsigned boff = sba + OFF_BHI + (ks * 16 + lane16) * B_STRIDE + warp_n * 2;
            unsigned Ah[4][4], Bf[4][2];
#pragma unroll
            for (int tm = 0; tm < 4; tm++)
                LDSM_X4(Ah[tm][0], Ah[tm][1], Ah[tm][2], Ah[tm][3], aoff + tm * 16 * A_STRIDE);
#pragma unroll
            for (int tn = 0; tn < 4; tn++)
                LDSM_X2T(Bf[tn][0], Bf[tn][1], boff + tn * 16);
#pragma unroll
            for (int tm = 0; tm < 4; tm++)
#pragma unroll
                for (int tn = 0; tn < 4; tn++)
                    MMAF16(acc[tm][tn], Ah[tm][0], Ah[tm][1], Ah[tm][2], Ah[tm][3],
                           Bf[tn][0], Bf[tn][1]);
        }
        if (more) CP_WAIT0();
        __syncthreads();
    }

#pragma unroll
    for (int tm = 0; tm < 4; tm++) {
#pragma unroll
        for (int tn = 0; tn < 4; tn++) {
            int gcol = col0 + warp_n + tn * 8 + (lane & 3) * 2;
            float bb0 = __ldg(bias + gcol), bb1 = __ldg(bias + gcol + 1);
#pragma unroll
            for (int half = 0; half < 2; half++) {
                int r = brow + warp_m + tm * 16 + (lane >> 2) + half * 8;
                if (r >= M) continue;
                float v0 = fmaxf(acc[tm][tn][half * 2 + 0] + bb0, 0.0f);
                float v1 = fmaxf(acc[tm][tn][half * 2 + 1] + bb1, 0.0f);
                float2 o; o.x = v0; o.y = v1;
                *(float2*)(C + (size_t)r * Ncs + gcol) = o;
            }
        }
    }
}

// ---------------- fused decoder tail ----------------
__global__ __launch_bounds__(128)
void decoder_tail_kernel(const float* __restrict__ din,
                         const float* __restrict__ W2, const float* __restrict__ b2,
                         const float* __restrict__ W3, const float* __restrict__ b3,
                         const float* __restrict__ W4, const float* __restrict__ b4,
                         const float* __restrict__ Wo, const float* __restrict__ bo,
                         const int* __restrict__ batch, float* __restrict__ sums, int M) {
    __shared__ float w2[128 * 64];
    __shared__ float w3[64 * 32];
    __shared__ float w4[32 * 16];
    __shared__ float wo[160];
    __shared__ float xs [4][128];
    __shared__ float t64[4][64];
    __shared__ float t32[4][32];
    __shared__ float t16[4][16];
    for (int i = threadIdx.x; i < 128 * 64; i += 128) w2[i] = W2[i];
    for (int i = threadIdx.x; i < 64 * 32;  i += 128) w3[i] = W3[i];
    for (int i = threadIdx.x; i < 32 * 16;  i += 128) w4[i] = W4[i];
    for (int i = threadIdx.x; i < 160;      i += 128) wo[i] = Wo[i];
    __syncthreads();
    int warp = threadIdx.x >> 5;
    int lane = threadIdx.x & 31;
    int stride = gridDim.x * 4;
    for (int row = blockIdx.x * 4 + warp; row < M; row += stride) {
        *(float4*)&xs[warp][lane * 4] = *(const float4*)(din + (size_t)row * 128 + lane * 4);
        __syncwarp();
        float s0 = b2[lane], s1 = b2[lane + 32];
#pragma unroll 8
        for (int k = 0; k < 128; k++) {
            float xv = xs[warp][k];
            s0 = fmaf(xv, w2[k * 64 + lane],      s0);
            s1 = fmaf(xv, w2[k * 64 + lane + 32], s1);
        }
        t64[warp][lane]      = fmaxf(s0, 0.0f);
        t64[warp][lane + 32] = fmaxf(s1, 0.0f);
        __syncwarp();
        float s = b3[lane];
#pragma unroll 8
        for (int k = 0; k < 64; k++) s = fmaf(t64[warp][k], w3[k * 32 + lane], s);
        t32[warp][lane] = fmaxf(s, 0.0f);
        __syncwarp();
        if (lane < 16) {
            float t = b4[lane];
#pragma unroll
            for (int k = 0; k < 32; k++) t = fmaf(t32[warp][k], w4[k * 16 + lane], t);
            t16[warp][lane] = fmaxf(t, 0.0f);
        }
        __syncwarp();
        if (lane < 10) {
            float t = bo[lane];
#pragma unroll
            for (int k = 0; k < 16; k++) t = fmaf(t16[warp][k], wo[k * 10 + lane], t);
            float yp = __fdividef(1.0f, 1.0f + __expf(-t));
            atomicAdd(&sums[batch[row] * 10 + lane], yp);
        }
        __syncwarp();
    }
}

__global__ void pool_finalize_kernel(const float* __restrict__ sums, const float* __restrict__ cnt,
                                     const float* __restrict__ y,
                                     float* __restrict__ out_pred, float* __restrict__ out_y) {
    int i = blockIdx.x * blockDim.x + threadIdx.x;
    if (i < GG * DOUT_) {
        out_pred[i] = sums[i] / fmaxf(cnt[i / DOUT_], 1.0f);
        out_y[i]    = y[i];
    }
}

// ---------------- launch ----------------
extern "C" void kernel_launch(void* const* d_in, const int* in_sizes, int n_in,
                              void* d_out, int out_size) {
    const float* x     = (const float*)d_in[0];
    const int*   ei    = (const int*)  d_in[1];
    const int*   batch = (const int*)  d_in[2];
    const float* y     = (const float*)d_in[3];
    const float* eps   = (const float*)d_in[4];
    const float* W_in  = (const float*)d_in[5];
    const float* b_in  = (const float*)d_in[6];
    const float* W_gcn = (const float*)d_in[7];
    const float* b_gcn = (const float*)d_in[8];
    const float* W_enc = (const float*)d_in[9];
    const float* b_enc = (const float*)d_in[10];
    const float* W_mu  = (const float*)d_in[11];
    const float* b_mu  = (const float*)d_in[12];
    const float* W_std = (const float*)d_in[13];
    const float* b_std = (const float*)d_in[14];
    const float* Wd0 = (const float*)d_in[15]; const float* bd0 = (const float*)d_in[16];
    const float* Wd1 = (const float*)d_in[17]; const float* bd1 = (const float*)d_in[18];
    const float* Wd2 = (const float*)d_in[19]; const float* bd2 = (const float*)d_in[20];
    const float* Wd3 = (const float*)d_in[21]; const float* bd3 = (const float*)d_in[22];
    const float* Wd4 = (const float*)d_in[23]; const float* bd4 = (const float*)d_in[24];
    const float* Wo  = (const float*)d_in[25]; const float* bo  = (const float*)d_in[26];

    float *h, *u, *dec1, *dinv, *sums, *cnt;
    int *deg, *off, *cur, *csr;
    unsigned short *wh;
    cudaGetSymbolAddress((void**)&h,    g_h);
    cudaGetSymbolAddress((void**)&u,    g_u);
    cudaGetSymbolAddress((void**)&dec1, g_dec1);
    cudaGetSymbolAddress((void**)&dinv, g_dinv);
    cudaGetSymbolAddress((void**)&deg,  g_deg);
    cudaGetSymbolAddress((void**)&off,  g_off);
    cudaGetSymbolAddress((void**)&cur,  g_cur);
    cudaGetSymbolAddress((void**)&csr,  g_csr);
    cudaGetSymbolAddress((void**)&sums, g_sums);
    cudaGetSymbolAddress((void**)&cnt,  g_cnt);
    cudaGetSymbolAddress((void**)&wh,   g_wh);

    float* out      = (float*)d_out;
    float* out_pred = out;
    float* out_mu   = out + GG * DOUT_;
    float* out_std  = out + GG * DOUT_ + (size_t)NN * DL_;
    float* out_y    = out + GG * DOUT_ + (size_t)2 * NN * DL_;

    const int* src = ei;
    const int* dst = ei + EE;

    cudaFuncSetAttribute(mega_kernel, cudaFuncAttributeMaxDynamicSharedMemorySize, MEGA_SMEM);
    cudaFuncSetAttribute(gemm_mma,   cudaFuncAttributeMaxDynamicSharedMemorySize, SMEM_GEMM);

    WJobs jobs;
    int O[11];
    {
        int o = 0;
        auto set = [&](int i, const float* W, int elems) {
            jobs.j[i].W = W; jobs.j[i].elems = elems; jobs.j[i].off = o; O[i] = o; o += elems;
        };
        set(0, W_in, 32 * 128);
        set(1, W_gcn, 128 * 128);
        for (int j = 0; j < 5; j++) set(2 + j, W_enc + (size_t)j * DL_ * DL_, 128 * 128);
        set(7, W_mu, 128 * 128);
        set(8, W_std, 128 * 128);
        set(9, Wd0, 128 * 256);
        set(10, Wd1, 256 * 128);
    }
    const int GRID = (NN + 127) / 128;
    const __half* WH = (const __half*)wh;

    wsplit_kernel<<<dim3(32, 11), 256>>>(jobs, wh);
    cudaMemsetAsync(deg, 0, NN * sizeof(int));
    count_deg_kernel   <<<(EE + 255) / 256, 256>>>(dst, deg, EE);
    scan_offsets_kernel<<<1, 1024>>>(deg, off, cur, dinv, NN);
    mega_kernel<<<GRID, 512, MEGA_SMEM>>>(0, x, WH, O[0], b_in, O[1], O[2], b_enc,
                                          O[7], b_mu, O[8], b_std, dinv, nullptr,
                                          nullptr, nullptr, nullptr,
                                          u, out_mu, nullptr, nullptr, NN);
    csr_fill_kernel    <<<(EE + 255) / 256, 256>>>(src, dst, cur, csr, EE);

    for (int it = 0; it < KK; it++) {
        int mode = (it == KK - 1) ? 2 : 1;
        mega_kernel<<<GRID, 512, MEGA_SMEM>>>(mode, u, WH, O[0], b_in, O[1], O[2], b_enc,
                                              O[7], b_mu, O[8], b_std, dinv,
                                              eps + (size_t)it * NN * DL_,
                                              off, csr, b_gcn,
                                              u, out_mu, out_std, h, NN);
    }

    gemm_mma<<<GRID, 256, SMEM_GEMM>>>(h, WH + O[9], bd0, dec1, NN, 128, 256, 256, 0);
    gemm_mma<<<GRID, 256, SMEM_GEMM>>>(h, WH + O[9] + 128, bd0, dec1, NN, 128, 256, 256, 128);
    gemm_mma<<<GRID, 256, SMEM_GEMM>>>(dec1, WH + O[10], bd1, u, NN, 256, 128, 128, 0);

    cudaMemsetAsync(sums, 0, GG * DOUT_ * sizeof(float));
    cudaMemsetAsync(cnt,  0, GG * sizeof(float));
    count_nodes_kernel<<<(NN + 255) / 256, 256>>>(batch, cnt, NN);
    decoder_tail_kernel<<<592, 128>>>(u, Wd2, bd2, Wd3, bd3, Wd4, bd4, Wo, bo,
                                      batch, sums, NN);
    pool_finalize_kernel<<<(GG * DOUT_ + 255) / 256, 256>>>(sums, cnt, y, out_pred, out_y);

    (void)in_sizes; (void)n_in; (void)out_size;
}

// round 14
// speedup vs baseline: 3.8152x; 1.1003x over previous
#include <cuda_runtime.h>
#include <cuda_fp16.h>
#include <math.h>

#define NN   50000
#define EE   800000
#define DIN_ 32
#define DL_  128
#define DOUT_ 10
#define GG   256
#define KK   3

// ---------------- scratch (device globals) ----------------
__device__ __align__(16) float g_u  [NN * DL_];
__device__ __align__(16) float g_dinv[NN];
__device__ __align__(16) int   g_deg [NN];
__device__ __align__(16) int   g_off [NN + 1];
__device__ __align__(16) int   g_cur [NN];
__device__ __align__(16) int   g_csr [EE];
__device__ __align__(16) float g_sums[GG * DOUT_];
__device__ __align__(16) float g_cnt [GG];
__device__ __align__(16) unsigned short g_wh[184320];

// ---------------- asm helpers ----------------
__device__ __forceinline__ unsigned smem_u32(const void* p) {
    unsigned a;
    asm("{ .reg .u64 t; cvta.to.shared.u64 t, %1; cvt.u32.u64 %0, t; }" : "=r"(a) : "l"(p));
    return a;
}
#define CP_ASYNC16(dst_u32, src) \
    asm volatile("cp.async.ca.shared.global [%0], [%1], 16;" :: "r"(dst_u32), "l"(src))
#define CP_COMMIT() asm volatile("cp.async.commit_group;")
#define CP_WAIT0()  asm volatile("cp.async.wait_group 0;")
#define LDSM_X4(r0, r1, r2, r3, addr) \
    asm volatile("ldmatrix.sync.aligned.m8n8.x4.shared.b16 {%0,%1,%2,%3}, [%4];" \
                 : "=r"(r0), "=r"(r1), "=r"(r2), "=r"(r3) : "r"(addr))
#define LDSM_X2T(r0, r1, addr) \
    asm volatile("ldmatrix.sync.aligned.m8n8.x2.trans.shared.b16 {%0,%1}, [%2];" \
                 : "=r"(r0), "=r"(r1) : "r"(addr))
#define MMAF16(c, a0, a1, a2, a3, b0, b1) \
    asm volatile("mma.sync.aligned.m16n8k16.row.col.f32.f16.f16.f32 " \
                 "{%0,%1,%2,%3}, {%4,%5,%6,%7}, {%8,%9}, {%0,%1,%2,%3};" \
                 : "+f"((c)[0]), "+f"((c)[1]), "+f"((c)[2]), "+f"((c)[3]) \
                 : "r"(a0), "r"(a1), "r"(a2), "r"(a3), "r"(b0), "r"(b1))
#define BAR_GROUP(id) asm volatile("bar.sync %0, 128;" :: "r"(id) : "memory")

__device__ __forceinline__ unsigned hpack2(float a, float b) {
    __half2 h = __floats2half2_rn(a, b);
    return *(unsigned*)&h;
}

// ===== mega smem geometry: A tile + TWO W buffers (fp16) = 102 KB, 2 CTAs/SM =====
#define AST    272
#define MS_AH  0
#define MS_W0  34816
#define MS_W1  69632
#define MEGA_SMEM 104448

// ---------------- preprocessing ----------------
__global__ void count_deg_kernel(const int* __restrict__ dst, int* __restrict__ deg, int E) {
    int i = blockIdx.x * blockDim.x + threadIdx.x;
    if (i < E) atomicAdd(&deg[dst[i]], 1);
}
__global__ void count_nodes_kernel(const int* __restrict__ batch, float* __restrict__ cnt, int M) {
    int i = blockIdx.x * blockDim.x + threadIdx.x;
    if (i < M) atomicAdd(&cnt[batch[i]], 1.0f);
}
__global__ __launch_bounds__(1024)
void scan_offsets_kernel(const int* __restrict__ deg, int* __restrict__ off,
                         int* __restrict__ cursor, float* __restrict__ dinv, int M) {
    __shared__ int part[1024];
    int t = threadIdx.x;
    int chunk = (M + 1023) >> 10;
    int base = t * chunk;
    int s = 0;
    for (int i = 0; i < chunk; i++) { int j = base + i; if (j < M) s += deg[j]; }
    part[t] = s;
    __syncthreads();
    for (int d = 1; d < 1024; d <<= 1) {
        int add = (t >= d) ? part[t - d] : 0;
        __syncthreads();
        part[t] += add;
        __syncthreads();
    }
    int run = part[t] - s;
    for (int i = 0; i < chunk; i++) {
        int j = base + i;
        if (j < M) {
            int dj = deg[j];
            off[j] = run; cursor[j] = run; run += dj;
            dinv[j] = rsqrtf((float)dj + 1.0f);
        }
    }
    if (t == 1023) off[M] = part[1023];
}
__global__ void csr_fill_kernel(const int* __restrict__ src, const int* __restrict__ dst,
                                int* __restrict__ cursor, int* __restrict__ csr, int E) {
    int i = blockIdx.x * blockDim.x + threadIdx.x;
    if (i < E) {
        int p = atomicAdd(&cursor[dst[i]], 1);
        csr[p] = src[i];
    }
}

// ---------------- weight convert (fp16) ----------------
struct WJob { const float* W; int elems; int off; };
struct WJobs { WJob j[11]; };
__global__ void wsplit_kernel(WJobs jobs, unsigned short* __restrict__ wh) {
    WJob jb = jobs.j[blockIdx.y];
    for (int i = blockIdx.x * blockDim.x + threadIdx.x; i < jb.elems;
         i += gridDim.x * blockDim.x) {
        wh[jb.off + i] = __half_as_ushort(__float2half_rn(jb.W[i]));
    }
}

// ===== mega pieces (512 thr, warp 32x32, single fp16 product) =====
__device__ __forceinline__ void stage_w(unsigned sb, int woff, const __half* Wh,
                                        int nrows, int ldb, int tid) {
    int chunks = nrows * 16;
    for (int idx = tid; idx < chunks; idx += 512) {
        int rowb = idx >> 4, cc = idx & 15;
        CP_ASYNC16(sb + woff + rowb * AST + cc * 16,
                   (const char*)(Wh + (size_t)rowb * ldb) + cc * 16);
    }
    CP_COMMIT();
}

// acc (+)= A(sm @ aoff_base) @ W(sm @ woff);  zero=1 clears acc first
__device__ __forceinline__ void layer_mma(unsigned sb, int abase, int woff,
                                          int warp_m, int warp_n, int lane,
                                          int nks, float acc[2][4][4], int zero) {
    if (zero) {
#pragma unroll
        for (int i = 0; i < 2; i++)
#pragma unroll
            for (int j = 0; j < 4; j++)
#pragma unroll
                for (int q = 0; q < 4; q++) acc[i][j][q] = 0.0f;
    }
    const int arow = (lane & 7) + ((lane >> 3) & 1) * 8;
    const int akq  = lane >> 4;
    const int lane16 = lane & 15;
    for (int ks = 0; ks < nks; ks++) {
        unsigned aoff = sb + abase + (warp_m + arow) * AST + (ks * 16 + akq * 8) * 2;
        unsigned boff = sb + woff + (ks * 16 + lane16) * AST + warp_n * 2;
        unsigned Ah[2][4], Bf[4][2];
#pragma unroll
        for (int tm = 0; tm < 2; tm++)
            LDSM_X4(Ah[tm][0], Ah[tm][1], Ah[tm][2], Ah[tm][3], aoff + tm * 16 * AST);
#pragma unroll
        for (int tn = 0; tn < 4; tn++)
            LDSM_X2T(Bf[tn][0], Bf[tn][1], boff + tn * 16);
#pragma unroll
        for (int tm = 0; tm < 2; tm++)
#pragma unroll
            for (int tn = 0; tn < 4; tn++)
                MMAF16(acc[tm][tn], Ah[tm][0], Ah[tm][1], Ah[tm][2], Ah[tm][3],
                       Bf[tn][0], Bf[tn][1]);
    }
}

// act: 1 sigmoid, 2 relu; writes fp16 tile at smem base `tbase`
__device__ __forceinline__ void store_tile(char* smem, int tbase, float acc[2][4][4],
                                           const float* __restrict__ bias, int act,
                                           int warp_m, int warp_n, int lane) {
#pragma unroll
    for (int tn = 0; tn < 4; tn++) {
        int c = warp_n + tn * 8 + (lane & 3) * 2;
        float b0 = __ldg(bias + c), b1 = __ldg(bias + c + 1);
#pragma unroll
        for (int tm = 0; tm < 2; tm++)
#pragma unroll
            for (int half = 0; half < 2; half++) {
                int r = warp_m + tm * 16 + (lane >> 2) + half * 8;
                float v0 = acc[tm][tn][half * 2]     + b0;
                float v1 = acc[tm][tn][half * 2 + 1] + b1;
                if (act == 1) {
                    v0 = __fdividef(1.0f, 1.0f + __expf(-v0));
                    v1 = __fdividef(1.0f, 1.0f + __expf(-v1));
                } else {
                    v0 = fmaxf(v0, 0.0f);
                    v1 = fmaxf(v1, 0.0f);
                }
                *(unsigned*)(smem + tbase + r * AST + c * 2) = hpack2(v0, v1);
            }
    }
}

// mode 0 = input (x -> h -> u); 1 = hop (gather -> ... -> u);
// mode 2 = last hop (gather -> mu,std -> h -> fused decoder dec1,dec2 -> u)
__global__ __launch_bounds__(512, 2)
void mega_kernel(int mode, const float* __restrict__ Ain,
                 const __half* __restrict__ WH,
                 int o_first, const float* __restrict__ b_first,
                 int o_gcn, int o_enc0, const float* __restrict__ b_enc,
                 int o_mu, const float* __restrict__ b_mu,
                 int o_std, const float* __restrict__ b_std,
                 int o_wd0, const float* __restrict__ bd0,
                 int o_wd1, const float* __restrict__ bd1,
                 const float* __restrict__ dinv, const float* __restrict__ eps_it,
                 const int* __restrict__ off, const int* __restrict__ csr,
                 const float* __restrict__ bgcn,
                 float* __restrict__ u_out, float* __restrict__ mu_out,
                 float* __restrict__ std_out, int M) {
    extern __shared__ __align__(16) char smem[];
    const unsigned sb = smem_u32(smem);
    const int tid  = threadIdx.x;
    const int wid  = tid >> 5;
    const int lane = tid & 31;
    const int brow = blockIdx.x * 128;
    const int warp_m = (wid >> 2) * 32;
    const int warp_n = (wid & 3) * 32;
    const int gbar = 1 + (wid >> 2);

    // ---- first W -> W0 (issued before A staging for overlap) ----
    stage_w(sb, MS_W0, WH + ((mode == 0) ? o_first : o_enc0),
            (mode == 0) ? 32 : 128, 128, tid);

    if (mode == 0) {
        int row = tid >> 2;
        int c0 = (tid & 3) * 8;
        bool ok = (brow + row) < M;
        const float* Ar = Ain + (size_t)(brow + row) * DIN_ + c0;
        for (int i4 = 0; i4 < 2; i4++) {
            float4 v = ok ? *(const float4*)(Ar + i4 * 4) : make_float4(0.f, 0.f, 0.f, 0.f);
            int c = c0 + i4 * 4;
            *(uint2*)(smem + MS_AH + row * AST + c * 2) =
                make_uint2(hpack2(v.x, v.y), hpack2(v.z, v.w));
        }
    } else {
        // fused gather staging: A[r] = fp16( dinv*(u_self + sum u_nbr) + b_gcn )
        float4 bg = *(const float4*)(bgcn + lane * 4);
        for (int rr = wid; rr < 128; rr += 16) {
            int gr = brow + rr;
            float4 a4 = make_float4(0.f, 0.f, 0.f, 0.f);
            if (gr < M) {
                a4 = __ldg((const float4*)(Ain + (size_t)gr * DL_ + lane * 4));
                int e0 = off[gr], e1 = off[gr + 1];
                int deg = e1 - e0;
                for (int base = 0; base < deg; base += 32) {
                    int cnt = min(32, deg - base);
                    int idx = 0;
                    if (base + lane < deg) idx = __ldg(csr + e0 + base + lane);
                    int j = 0;
                    for (; j + 8 <= cnt; j += 8) {
                        float4 v[8];
#pragma unroll
                        for (int q = 0; q < 8; q++) {
                            int s = __shfl_sync(0xffffffffu, idx, j + q);
                            v[q] = __ldg((const float4*)(Ain + (size_t)s * DL_ + lane * 4));
                        }
#pragma unroll
                        for (int q = 0; q < 8; q++) {
                            a4.x += v[q].x; a4.y += v[q].y; a4.z += v[q].z; a4.w += v[q].w;
                        }
                    }
                    for (; j < cnt; j++) {
                        int s = __shfl_sync(0xffffffffu, idx, j);
                        float4 v = __ldg((const float4*)(Ain + (size_t)s * DL_ + lane * 4));
                        a4.x += v.x; a4.y += v.y; a4.z += v.z; a4.w += v.w;
                    }
                }
                float dv = __ldg(dinv + gr);
                a4.x = fmaf(dv, a4.x, bg.x);
                a4.y = fmaf(dv, a4.y, bg.y);
                a4.z = fmaf(dv, a4.z, bg.z);
                a4.w = fmaf(dv, a4.w, bg.w);
            }
            *(uint2*)(smem + MS_AH + rr * AST + lane * 8) =
                make_uint2(hpack2(a4.x, a4.y), hpack2(a4.z, a4.w));
        }
    }
    CP_WAIT0();
    __syncthreads();

    float acc[2][4][4];

    if (mode == 0) {
        stage_w(sb, MS_W1, WH + o_gcn, 128, 128, tid);
        layer_mma(sb, MS_AH, MS_W0, warp_m, warp_n, lane, 2, acc, 1);
        BAR_GROUP(gbar);
        store_tile(smem, MS_AH, acc, b_first, 1, warp_m, warp_n, lane);
        CP_WAIT0();
        __syncthreads();
        layer_mma(sb, MS_AH, MS_W1, warp_m, warp_n, lane, 8, acc, 1);
#pragma unroll
        for (int tm = 0; tm < 2; tm++)
#pragma unroll
            for (int half = 0; half < 2; half++) {
                int r = brow + warp_m + tm * 16 + (lane >> 2) + half * 8;
                if (r >= M) continue;
                float rs = __ldg(dinv + r);
#pragma unroll
                for (int tn = 0; tn < 4; tn++) {
                    int c = warp_n + tn * 8 + (lane & 3) * 2;
                    float2 o;
                    o.x = acc[tm][tn][half * 2]     * rs;
                    o.y = acc[tm][tn][half * 2 + 1] * rs;
                    *(float2*)(u_out + (size_t)r * DL_ + c) = o;
                }
            }
        return;
    }

    // ---- hop: enc x5 (ping-pong W; stage next during current mma) ----
    for (int j = 0; j < 5; j++) {
        int cb = (j & 1) ? MS_W1 : MS_W0;
        int nb = (j & 1) ? MS_W0 : MS_W1;
        int nxt = (j < 4) ? (o_enc0 + (j + 1) * 16384) : o_mu;
        stage_w(sb, nb, WH + nxt, 128, 128, tid);
        layer_mma(sb, MS_AH, cb, warp_m, warp_n, lane, 8, acc, 1);
        BAR_GROUP(gbar);
        store_tile(smem, MS_AH, acc, b_enc + j * DL_, 1, warp_m, warp_n, lane);
        CP_WAIT0();
        __syncthreads();
    }
    // ---- mu (W in W1); stage W_std -> W0 during mma ----
    stage_w(sb, MS_W0, WH + o_std, 128, 128, tid);
    layer_mma(sb, MS_AH, MS_W1, warp_m, warp_n, lane, 8, acc, 1);
#pragma unroll
    for (int tn = 0; tn < 4; tn++) {
        int c = warp_n + tn * 8 + (lane & 3) * 2;
        float b0 = __ldg(b_mu + c), b1 = __ldg(b_mu + c + 1);
#pragma unroll
        for (int tm = 0; tm < 2; tm++)
#pragma unroll
            for (int half = 0; half < 2; half++) {
                int r = brow + warp_m + tm * 16 + (lane >> 2) + half * 8;
                if (r >= M) continue;
                float2 v;
                v.x = acc[tm][tn][half * 2]     + b0;
                v.y = acc[tm][tn][half * 2 + 1] + b1;
                *(float2*)(mu_out + (size_t)r * DL_ + c) = v;
            }
    }
    CP_WAIT0();
    __syncthreads();
    // ---- std (W in W0); stage next (gcn | Wd0a) -> W1 during mma ----
    if (mode == 1) stage_w(sb, MS_W1, WH + o_gcn, 128, 128, tid);
    else           stage_w(sb, MS_W1, WH + o_wd0, 128, 256, tid);
    layer_mma(sb, MS_AH, MS_W0, warp_m, warp_n, lane, 8, acc, 1);
    BAR_GROUP(gbar);
    // combine: h = mu(global) + softplus(std)*eps -> resident A; std out if last hop
#pragma unroll
    for (int tn = 0; tn < 4; tn++) {
        int c = warp_n + tn * 8 + (lane & 3) * 2;
        float b0 = __ldg(b_std + c), b1 = __ldg(b_std + c + 1);
#pragma unroll
        for (int tm = 0; tm < 2; tm++)
#pragma unroll
            for (int half = 0; half < 2; half++) {
                int r = warp_m + tm * 16 + (lane >> 2) + half * 8;
                int gr = brow + r;
                float s0 = acc[tm][tn][half * 2]     + b0 - 5.0f;
                float s1 = acc[tm][tn][half * 2 + 1] + b1 - 5.0f;
                s0 = (s0 > 20.0f) ? s0 : log1pf(expf(s0));
                s1 = (s1 > 20.0f) ? s1 : log1pf(expf(s1));
                float2 m = make_float2(0.f, 0.f), e = make_float2(0.f, 0.f);
                if (gr < M) {
                    m = *(const float2*)(mu_out + (size_t)gr * DL_ + c);
                    e = *(const float2*)(eps_it + (size_t)gr * DL_ + c);
                }
                float h0 = fmaf(s0, e.x, m.x);
                float h1 = fmaf(s1, e.y, m.y);
                if (mode == 2 && gr < M) {
                    float2 so; so.x = s0; so.y = s1;
                    *(float2*)(std_out + (size_t)gr * DL_ + c) = so;
                }
                *(unsigned*)(smem + MS_AH + r * AST + c * 2) = hpack2(h0, h1);
            }
    }
    CP_WAIT0();
    __syncthreads();

    if (mode == 1) {
        // ---- gcn: u = h @ W_gcn * dinv ----
        layer_mma(sb, MS_AH, MS_W1, warp_m, warp_n, lane, 8, acc, 1);
#pragma unroll
        for (int tm = 0; tm < 2; tm++)
#pragma unroll
            for (int half = 0; half < 2; half++) {
                int r = brow + warp_m + tm * 16 + (lane >> 2) + half * 8;
                if (r >= M) continue;
                float rs = __ldg(dinv + r);
#pragma unroll
                for (int tn = 0; tn < 4; tn++) {
                    int c = warp_n + tn * 8 + (lane & 3) * 2;
                    float2 o;
                    o.x = acc[tm][tn][half * 2]     * rs;
                    o.y = acc[tm][tn][half * 2 + 1] * rs;
                    *(float2*)(u_out + (size_t)r * DL_ + c) = o;
                }
            }
        return;
    }

    // ======== mode 2: fused decoder dec1 = relu(h@Wd0+bd0) [256], dec2 = relu(dec1@Wd1+bd1) ========
    // h in A-tile; Wd0a in W1. Stage Wd0b -> W0.
    stage_w(sb, MS_W0, WH + o_wd0 + 128, 128, 256, tid);
    layer_mma(sb, MS_AH, MS_W1, warp_m, warp_n, lane, 8, acc, 1);   // dec1a = h@Wd0a
    __syncthreads();                                                // all W1 readers done
    store_tile(smem, MS_W1, acc, bd0, 2, warp_m, warp_n, lane);     // dec1a -> W1
    CP_WAIT0();
    __syncthreads();                                                // Wd0b ready, dec1a visible
    layer_mma(sb, MS_AH, MS_W0, warp_m, warp_n, lane, 8, acc, 1);   // dec1b = h@Wd0b
    __syncthreads();                                                // A + W0 readers done
    store_tile(smem, MS_AH, acc, bd0 + 128, 2, warp_m, warp_n, lane); // dec1b -> A-tile
    stage_w(sb, MS_W0, WH + o_wd1, 128, 128, tid);                  // Wd1a -> W0
    CP_WAIT0();
    __syncthreads();
    layer_mma(sb, MS_W1, MS_W0, warp_m, warp_n, lane, 8, acc, 1);   // acc = dec1a@Wd1a
    __syncthreads();                                                // W0 readers done
    stage_w(sb, MS_W0, WH + o_wd1 + 128 * 128, 128, 128, tid);      // Wd1b -> W0
    CP_WAIT0();
    __syncthreads();
    layer_mma(sb, MS_AH, MS_W0, warp_m, warp_n, lane, 8, acc, 0);   // acc += dec1b@Wd1b
    // epilogue: u = relu(acc + bd1) -> global
#pragma unroll
    for (int tn = 0; tn < 4; tn++) {
        int c = warp_n + tn * 8 + (lane & 3) * 2;
        float b0 = __ldg(bd1 + c), b1 = __ldg(bd1 + c + 1);
#pragma unroll
        for (int tm = 0; tm < 2; tm++)
#pragma unroll
            for (int half = 0; half < 2; half++) {
                int r = brow + warp_m + tm * 16 + (lane >> 2) + half * 8;
                if (r >= M) continue;
                float2 o;
                o.x = fmaxf(acc[tm][tn][half * 2]     + b0, 0.0f);
                o.y = fmaxf(acc[tm][tn][half * 2 + 1] + b1, 0.0f);
                *(float2*)(u_out + (size_t)r * DL_ + c) = o;
            }
    }
}

// ---------------- fused decoder tail: [N,128] -> 64 -> 32 -> 16 -> 10 -> sigmoid -> pool ----------------
__global__ __launch_bounds__(128)
void decoder_tail_kernel(const float* __restrict__ din,
                         const float* __restrict__ W2, const float* __restrict__ b2,
                         const float* __restrict__ W3, const float* __restrict__ b3,
                         const float* __restrict__ W4, const float* __restrict__ b4,
                         const float* __restrict__ Wo, const float* __restrict__ bo,
                         const int* __restrict__ batch, float* __restrict__ sums, int M) {
    __shared__ float w2[128 * 64];
    __shared__ float w3[64 * 32];
    __shared__ float w4[32 * 16];
    __shared__ float wo[160];
    __shared__ float xs [4][128];
    __shared__ float t64[4][64];
    __shared__ float t32[4][32];
    __shared__ float t16[4][16];
    for (int i = threadIdx.x; i < 128 * 64; i += 128) w2[i] = W2[i];
    for (int i = threadIdx.x; i < 64 * 32;  i += 128) w3[i] = W3[i];
    for (int i = threadIdx.x; i < 32 * 16;  i += 128) w4[i] = W4[i];
    for (int i = threadIdx.x; i < 160;      i += 128) wo[i] = Wo[i];
    __syncthreads();
    int warp = threadIdx.x >> 5;
    int lane = threadIdx.x & 31;
    int stride = gridDim.x * 4;
    for (int row = blockIdx.x * 4 + warp; row < M; row += stride) {
        *(float4*)&xs[warp][lane * 4] = *(const float4*)(din + (size_t)row * 128 + lane * 4);
        __syncwarp();
        float s0 = b2[lane], s1 = b2[lane + 32];
#pragma unroll 8
        for (int k = 0; k < 128; k++) {
            float xv = xs[warp][k];
            s0 = fmaf(xv, w2[k * 64 + lane],      s0);
            s1 = fmaf(xv, w2[k * 64 + lane + 32], s1);
        }
        t64[warp][lane]      = fmaxf(s0, 0.0f);
        t64[warp][lane + 32] = fmaxf(s1, 0.0f);
        __syncwarp();
        float s = b3[lane];
#pragma unroll 8
        for (int k = 0; k < 64; k++) s = fmaf(t64[warp][k], w3[k * 32 + lane], s);
        t32[warp][lane] = fmaxf(s, 0.0f);
        __syncwarp();
        if (lane < 16) {
            float t = b4[lane];
#pragma unroll
            for (int k = 0; k < 32; k++) t = fmaf(t32[warp][k], w4[k * 16 + lane], t);
            t16[warp][lane] = fmaxf(t, 0.0f);
        }
        __syncwarp();
        if (lane < 10) {
            float t = bo[lane];
#pragma unroll
            for (int k = 0; k < 16; k++) t = fmaf(t16[warp][k], wo[k * 10 + lane], t);
            float yp = __fdividef(1.0f, 1.0f + __expf(-t));
            atomicAdd(&sums[batch[row] * 10 + lane], yp);
        }
        __syncwarp();
    }
}

__global__ void pool_finalize_kernel(const float* __restrict__ sums, const float* __restrict__ cnt,
                                     const float* __restrict__ y,
                                     float* __restrict__ out_pred, float* __restrict__ out_y) {
    int i = blockIdx.x * blockDim.x + threadIdx.x;
    if (i < GG * DOUT_) {
        out_pred[i] = sums[i] / fmaxf(cnt[i / DOUT_], 1.0f);
        out_y[i]    = y[i];
    }
}

// ---------------- launch ----------------
extern "C" void kernel_launch(void* const* d_in, const int* in_sizes, int n_in,
                              void* d_out, int out_size) {
    const float* x     = (const float*)d_in[0];
    const int*   ei    = (const int*)  d_in[1];
    const int*   batch = (const int*)  d_in[2];
    const float* y     = (const float*)d_in[3];
    const float* eps   = (const float*)d_in[4];
    const float* W_in  = (const float*)d_in[5];
    const float* b_in  = (const float*)d_in[6];
    const float* W_gcn = (const float*)d_in[7];
    const float* b_gcn = (const float*)d_in[8];
    const float* W_enc = (const float*)d_in[9];
    const float* b_enc = (const float*)d_in[10];
    const float* W_mu  = (const float*)d_in[11];
    const float* b_mu  = (const float*)d_in[12];
    const float* W_std = (const float*)d_in[13];
    const float* b_std = (const float*)d_in[14];
    const float* Wd0 = (const float*)d_in[15]; const float* bd0 = (const float*)d_in[16];
    const float* Wd1 = (const float*)d_in[17]; const float* bd1 = (const float*)d_in[18];
    const float* Wd2 = (const float*)d_in[19]; const float* bd2 = (const float*)d_in[20];
    const float* Wd3 = (const float*)d_in[21]; const float* bd3 = (const float*)d_in[22];
    const float* Wd4 = (const float*)d_in[23]; const float* bd4 = (const float*)d_in[24];
    const float* Wo  = (const float*)d_in[25]; const float* bo  = (const float*)d_in[26];

    float *u, *dinv, *sums, *cnt;
    int *deg, *off, *cur, *csr;
    unsigned short *wh;
    cudaGetSymbolAddress((void**)&u,    g_u);
    cudaGetSymbolAddress((void**)&dinv, g_dinv);
    cudaGetSymbolAddress((void**)&deg,  g_deg);
    cudaGetSymbolAddress((void**)&off,  g_off);
    cudaGetSymbolAddress((void**)&cur,  g_cur);
    cudaGetSymbolAddress((void**)&csr,  g_csr);
    cudaGetSymbolAddress((void**)&sums, g_sums);
    cudaGetSymbolAddress((void**)&cnt,  g_cnt);
    cudaGetSymbolAddress((void**)&wh,   g_wh);

    float* out      = (float*)d_out;
    float* out_pred = out;
    float* out_mu   = out + GG * DOUT_;
    float* out_std  = out + GG * DOUT_ + (size_t)NN * DL_;
    float* out_y    = out + GG * DOUT_ + (size_t)2 * NN * DL_;

    const int* src = ei;
    const int* dst = ei + EE;

    cudaFuncSetAttribute(mega_kernel, cudaFuncAttributeMaxDynamicSharedMemorySize, MEGA_SMEM);

    WJobs jobs;
    int O[11];
    {
        int o = 0;
        auto set = [&](int i, const float* W, int elems) {
            jobs.j[i].W = W; jobs.j[i].elems = elems; jobs.j[i].off = o; O[i] = o; o += elems;
        };
        set(0, W_in, 32 * 128);
        set(1, W_gcn, 128 * 128);
        for (int j = 0; j < 5; j++) set(2 + j, W_enc + (size_t)j * DL_ * DL_, 128 * 128);
        set(7, W_mu, 128 * 128);
        set(8, W_std, 128 * 128);
        set(9, Wd0, 128 * 256);
        set(10, Wd1, 256 * 128);
    }
    const int GRID = (NN + 127) / 128;
    const __half* WH = (const __half*)wh;

    wsplit_kernel<<<dim3(32, 11), 256>>>(jobs, wh);
    cudaMemsetAsync(deg, 0, NN * sizeof(int));
    count_deg_kernel   <<<(EE + 255) / 256, 256>>>(dst, deg, EE);
    scan_offsets_kernel<<<1, 1024>>>(deg, off, cur, dinv, NN);
    mega_kernel<<<GRID, 512, MEGA_SMEM>>>(0, x, WH, O[0], b_in, O[1], O[2], b_enc,
                                          O[7], b_mu, O[8], b_std, O[9], bd0, O[10], bd1,
                                          dinv, nullptr, nullptr, nullptr, nullptr,
                                          u, out_mu, nullptr, NN);
    csr_fill_kernel    <<<(EE + 255) / 256, 256>>>(src, dst, cur, csr, EE);

    for (int it = 0; it < KK; it++) {
        int mode = (it == KK - 1) ? 2 : 1;
        mega_kernel<<<GRID, 512, MEGA_SMEM>>>(mode, u, WH, O[0], b_in, O[1], O[2], b_enc,
                                              O[7], b_mu, O[8], b_std, O[9], bd0, O[10], bd1,
                                              dinv, eps + (size_t)it * NN * DL_,
                                              off, csr, b_gcn,
                                              u, out_mu, out_std, NN);
    }

    cudaMemsetAsync(sums, 0, GG * DOUT_ * sizeof(float));
    cudaMemsetAsync(cnt,  0, GG * sizeof(float));
    count_nodes_kernel<<<(NN + 255) / 256, 256>>>(batch, cnt, NN);
    decoder_tail_kernel<<<592, 128>>>(u, Wd2, bd2, Wd3, bd3, Wd4, bd4, Wo, bo,
                                      batch, sums, NN);
    pool_finalize_kernel<<<(GG * DOUT_ + 255) / 256, 256>>>(sums, cnt, y, out_pred, out_y);

    (void)in_sizes; (void)n_in; (void)out_size;
}

// round 15
// speedup vs baseline: 3.9224x; 1.0281x over previous
#include <cuda_runtime.h>
#include <cuda_fp16.h>
#include <math.h>

#define NN   50000
#define EE   800000
#define DIN_ 32
#define DL_  128
#define DOUT_ 10
#define GG   256
#define KK   3

// ---------------- scratch (device globals) ----------------
__device__ __align__(16) unsigned short g_u16[NN * DL_];   // u as fp16
__device__ __align__(16) float g_dinv[NN];
__device__ __align__(16) int   g_deg [NN];
__device__ __align__(16) int   g_off [NN + 1];
__device__ __align__(16) int   g_cur [NN];
__device__ __align__(16) int   g_csr [EE];
__device__ __align__(16) float g_sums[GG * DOUT_];
__device__ __align__(16) float g_cnt [GG];
__device__ __align__(16) unsigned short g_wh[184320];

// ---------------- asm helpers ----------------
__device__ __forceinline__ unsigned smem_u32(const void* p) {
    unsigned a;
    asm("{ .reg .u64 t; cvta.to.shared.u64 t, %1; cvt.u32.u64 %0, t; }" : "=r"(a) : "l"(p));
    return a;
}
#define CP_ASYNC16(dst_u32, src) \
    asm volatile("cp.async.ca.shared.global [%0], [%1], 16;" :: "r"(dst_u32), "l"(src))
#define CP_COMMIT() asm volatile("cp.async.commit_group;")
#define CP_WAIT0()  asm volatile("cp.async.wait_group 0;")
#define LDSM_X4(r0, r1, r2, r3, addr) \
    asm volatile("ldmatrix.sync.aligned.m8n8.x4.shared.b16 {%0,%1,%2,%3}, [%4];" \
                 : "=r"(r0), "=r"(r1), "=r"(r2), "=r"(r3) : "r"(addr))
#define LDSM_X2T(r0, r1, addr) \
    asm volatile("ldmatrix.sync.aligned.m8n8.x2.trans.shared.b16 {%0,%1}, [%2];" \
                 : "=r"(r0), "=r"(r1) : "r"(addr))
#define MMAF16(c, a0, a1, a2, a3, b0, b1) \
    asm volatile("mma.sync.aligned.m16n8k16.row.col.f32.f16.f16.f32 " \
                 "{%0,%1,%2,%3}, {%4,%5,%6,%7}, {%8,%9}, {%0,%1,%2,%3};" \
                 : "+f"((c)[0]), "+f"((c)[1]), "+f"((c)[2]), "+f"((c)[3]) \
                 : "r"(a0), "r"(a1), "r"(a2), "r"(a3), "r"(b0), "r"(b1))
#define BAR_GROUP(id) asm volatile("bar.sync %0, 128;" :: "r"(id) : "memory")

__device__ __forceinline__ unsigned hpack2(float a, float b) {
    __half2 h = __floats2half2_rn(a, b);
    return *(unsigned*)&h;
}
__device__ __forceinline__ void hunpack2(unsigned u, float& a, float& b) {
    __half2 h = *(__half2*)&u;
    float2 f = __half22float2(h);
    a = f.x; b = f.y;
}

// ===== mega smem geometry: A tile + TWO W buffers (fp16) = 102 KB, 2 CTAs/SM =====
#define AST    272
#define MS_AH  0
#define MS_W0  34816
#define MS_W1  69632
#define MEGA_SMEM 104448

// ---------------- preprocessing ----------------
__global__ void count_deg_kernel(const int* __restrict__ dst, int* __restrict__ deg, int E) {
    int i = blockIdx.x * blockDim.x + threadIdx.x;
    if (i < E) atomicAdd(&deg[dst[i]], 1);
}
__global__ void count_nodes_kernel(const int* __restrict__ batch, float* __restrict__ cnt, int M) {
    int i = blockIdx.x * blockDim.x + threadIdx.x;
    if (i < M) atomicAdd(&cnt[batch[i]], 1.0f);
}
__global__ __launch_bounds__(1024)
void scan_offsets_kernel(const int* __restrict__ deg, int* __restrict__ off,
                         int* __restrict__ cursor, float* __restrict__ dinv, int M) {
    __shared__ int part[1024];
    int t = threadIdx.x;
    int chunk = (M + 1023) >> 10;
    int base = t * chunk;
    int s = 0;
    for (int i = 0; i < chunk; i++) { int j = base + i; if (j < M) s += deg[j]; }
    part[t] = s;
    __syncthreads();
    for (int d = 1; d < 1024; d <<= 1) {
        int add = (t >= d) ? part[t - d] : 0;
        __syncthreads();
        part[t] += add;
        __syncthreads();
    }
    int run = part[t] - s;
    for (int i = 0; i < chunk; i++) {
        int j = base + i;
        if (j < M) {
            int dj = deg[j];
            off[j] = run; cursor[j] = run; run += dj;
            dinv[j] = rsqrtf((float)dj + 1.0f);
        }
    }
    if (t == 1023) off[M] = part[1023];
}
__global__ void csr_fill_kernel(const int* __restrict__ src, const int* __restrict__ dst,
                                int* __restrict__ cursor, int* __restrict__ csr, int E) {
    int i = blockIdx.x * blockDim.x + threadIdx.x;
    if (i < E) {
        int p = atomicAdd(&cursor[dst[i]], 1);
        csr[p] = src[i];
    }
}

// ---------------- weight convert (fp16) ----------------
struct WJob { const float* W; int elems; int off; };
struct WJobs { WJob j[11]; };
__global__ void wsplit_kernel(WJobs jobs, unsigned short* __restrict__ wh) {
    WJob jb = jobs.j[blockIdx.y];
    for (int i = blockIdx.x * blockDim.x + threadIdx.x; i < jb.elems;
         i += gridDim.x * blockDim.x) {
        wh[jb.off + i] = __half_as_ushort(__float2half_rn(jb.W[i]));
    }
}

// ===== mega pieces (512 thr, warp 32x32, single fp16 product) =====
__device__ __forceinline__ void stage_w(unsigned sb, int woff, const __half* Wh,
                                        int nrows, int ldb, int tid) {
    int chunks = nrows * 16;
    for (int idx = tid; idx < chunks; idx += 512) {
        int rowb = idx >> 4, cc = idx & 15;
        CP_ASYNC16(sb + woff + rowb * AST + cc * 16,
                   (const char*)(Wh + (size_t)rowb * ldb) + cc * 16);
    }
    CP_COMMIT();
}

// acc (+)= A(sm @ abase) @ W(sm @ woff);  zero=1 clears acc first
__device__ __forceinline__ void layer_mma(unsigned sb, int abase, int woff,
                                          int warp_m, int warp_n, int lane,
                                          int nks, float acc[2][4][4], int zero) {
    if (zero) {
#pragma unroll
        for (int i = 0; i < 2; i++)
#pragma unroll
            for (int j = 0; j < 4; j++)
#pragma unroll
                for (int q = 0; q < 4; q++) acc[i][j][q] = 0.0f;
    }
    const int arow = (lane & 7) + ((lane >> 3) & 1) * 8;
    const int akq  = lane >> 4;
    const int lane16 = lane & 15;
#pragma unroll
    for (int ks = 0; ks < 8; ks++) {
        if (ks >= nks) break;
        unsigned aoff = sb + abase + (warp_m + arow) * AST + (ks * 16 + akq * 8) * 2;
        unsigned boff = sb + woff + (ks * 16 + lane16) * AST + warp_n * 2;
        unsigned Ah[2][4], Bf[4][2];
#pragma unroll
        for (int tm = 0; tm < 2; tm++)
            LDSM_X4(Ah[tm][0], Ah[tm][1], Ah[tm][2], Ah[tm][3], aoff + tm * 16 * AST);
#pragma unroll
        for (int tn = 0; tn < 4; tn++)
            LDSM_X2T(Bf[tn][0], Bf[tn][1], boff + tn * 16);
#pragma unroll
        for (int tm = 0; tm < 2; tm++)
#pragma unroll
            for (int tn = 0; tn < 4; tn++)
                MMAF16(acc[tm][tn], Ah[tm][0], Ah[tm][1], Ah[tm][2], Ah[tm][3],
                       Bf[tn][0], Bf[tn][1]);
    }
}

// act: 1 sigmoid, 2 relu; writes fp16 tile at smem base `tbase`
__device__ __forceinline__ void store_tile(char* smem, int tbase, float acc[2][4][4],
                                           const float* __restrict__ bias, int act,
                                           int warp_m, int warp_n, int lane) {
#pragma unroll
    for (int tn = 0; tn < 4; tn++) {
        int c = warp_n + tn * 8 + (lane & 3) * 2;
        float b0 = __ldg(bias + c), b1 = __ldg(bias + c + 1);
#pragma unroll
        for (int tm = 0; tm < 2; tm++)
#pragma unroll
            for (int half = 0; half < 2; half++) {
                int r = warp_m + tm * 16 + (lane >> 2) + half * 8;
                float v0 = acc[tm][tn][half * 2]     + b0;
                float v1 = acc[tm][tn][half * 2 + 1] + b1;
                if (act == 1) {
                    v0 = __fdividef(1.0f, 1.0f + __expf(-v0));
                    v1 = __fdividef(1.0f, 1.0f + __expf(-v1));
                } else {
                    v0 = fmaxf(v0, 0.0f);
                    v1 = fmaxf(v1, 0.0f);
                }
                *(unsigned*)(smem + tbase + r * AST + c * 2) = hpack2(v0, v1);
            }
    }
}

// mode 0 = input (x -> h -> u); 1 = hop (gather -> ... -> u);
// mode 2 = last hop (gather -> mu,std -> h -> fused decoder dec1,dec2 -> u)
__global__ __launch_bounds__(512, 2)
void mega_kernel(int mode, const float* __restrict__ Xin,
                 const unsigned short* __restrict__ Uin,
                 const __half* __restrict__ WH,
                 int o_first, const float* __restrict__ b_first,
                 int o_gcn, int o_enc0, const float* __restrict__ b_enc,
                 int o_mu, const float* __restrict__ b_mu,
                 int o_std, const float* __restrict__ b_std,
                 int o_wd0, const float* __restrict__ bd0,
                 int o_wd1, const float* __restrict__ bd1,
                 const float* __restrict__ dinv, const float* __restrict__ eps_it,
                 const int* __restrict__ off, const int* __restrict__ csr,
                 const float* __restrict__ bgcn,
                 unsigned short* __restrict__ u_out, float* __restrict__ mu_out,
                 float* __restrict__ std_out, int M) {
    extern __shared__ __align__(16) char smem[];
    const unsigned sb = smem_u32(smem);
    const int tid  = threadIdx.x;
    const int wid  = tid >> 5;
    const int lane = tid & 31;
    const int brow = blockIdx.x * 128;
    const int warp_m = (wid >> 2) * 32;
    const int warp_n = (wid & 3) * 32;
    const int gbar = 1 + (wid >> 2);

    // ---- first W -> W0 (issued before A staging for overlap) ----
    stage_w(sb, MS_W0, WH + ((mode == 0) ? o_first : o_enc0),
            (mode == 0) ? 32 : 128, 128, tid);

    if (mode == 0) {
        int row = tid >> 2;
        int c0 = (tid & 3) * 8;
        bool ok = (brow + row) < M;
        const float* Ar = Xin + (size_t)(brow + row) * DIN_ + c0;
        for (int i4 = 0; i4 < 2; i4++) {
            float4 v = ok ? *(const float4*)(Ar + i4 * 4) : make_float4(0.f, 0.f, 0.f, 0.f);
            int c = c0 + i4 * 4;
            *(uint2*)(smem + MS_AH + row * AST + c * 2) =
                make_uint2(hpack2(v.x, v.y), hpack2(v.z, v.w));
        }
    } else {
        // fused gather staging (u is fp16): A[r] = fp16( dinv*(u_self + sum u_nbr) + b_gcn )
        float4 bg = *(const float4*)(bgcn + lane * 4);
        for (int rr = wid; rr < 128; rr += 16) {
            int gr = brow + rr;
            float4 a4 = make_float4(0.f, 0.f, 0.f, 0.f);
            if (gr < M) {
                uint2 us = __ldg((const uint2*)(Uin + (size_t)gr * DL_) + lane);
                hunpack2(us.x, a4.x, a4.y);
                hunpack2(us.y, a4.z, a4.w);
                int e0 = off[gr], e1 = off[gr + 1];
                int deg = e1 - e0;
                for (int base = 0; base < deg; base += 32) {
                    int cnt = min(32, deg - base);
                    int idx = 0;
                    if (base + lane < deg) idx = __ldg(csr + e0 + base + lane);
                    int j = 0;
                    for (; j + 8 <= cnt; j += 8) {
                        uint2 v[8];
#pragma unroll
                        for (int q = 0; q < 8; q++) {
                            int s = __shfl_sync(0xffffffffu, idx, j + q);
                            v[q] = __ldg((const uint2*)(Uin + (size_t)s * DL_) + lane);
                        }
#pragma unroll
                        for (int q = 0; q < 8; q++) {
                            float f0, f1, f2, f3;
                            hunpack2(v[q].x, f0, f1);
                            hunpack2(v[q].y, f2, f3);
                            a4.x += f0; a4.y += f1; a4.z += f2; a4.w += f3;
                        }
                    }
                    for (; j < cnt; j++) {
                        int s = __shfl_sync(0xffffffffu, idx, j);
                        uint2 vv = __ldg((const uint2*)(Uin + (size_t)s * DL_) + lane);
                        float f0, f1, f2, f3;
                        hunpack2(vv.x, f0, f1);
                        hunpack2(vv.y, f2, f3);
                        a4.x += f0; a4.y += f1; a4.z += f2; a4.w += f3;
                    }
                }
                float dv = __ldg(dinv + gr);
                a4.x = fmaf(dv, a4.x, bg.x);
                a4.y = fmaf(dv, a4.y, bg.y);
                a4.z = fmaf(dv, a4.z, bg.z);
                a4.w = fmaf(dv, a4.w, bg.w);
            }
            *(uint2*)(smem + MS_AH + rr * AST + lane * 8) =
                make_uint2(hpack2(a4.x, a4.y), hpack2(a4.z, a4.w));
        }
    }
    CP_WAIT0();
    __syncthreads();

    float acc[2][4][4];

    if (mode == 0) {
        stage_w(sb, MS_W1, WH + o_gcn, 128, 128, tid);
        layer_mma(sb, MS_AH, MS_W0, warp_m, warp_n, lane, 2, acc, 1);
        BAR_GROUP(gbar);
        store_tile(smem, MS_AH, acc, b_first, 1, warp_m, warp_n, lane);
        CP_WAIT0();
        __syncthreads();
        layer_mma(sb, MS_AH, MS_W1, warp_m, warp_n, lane, 8, acc, 1);
#pragma unroll
        for (int tm = 0; tm < 2; tm++)
#pragma unroll
            for (int half = 0; half < 2; half++) {
                int r = brow + warp_m + tm * 16 + (lane >> 2) + half * 8;
                if (r >= M) continue;
                float rs = __ldg(dinv + r);
#pragma unroll
                for (int tn = 0; tn < 4; tn++) {
                    int c = warp_n + tn * 8 + (lane & 3) * 2;
                    *(unsigned*)(u_out + (size_t)r * DL_ + c) =
                        hpack2(acc[tm][tn][half * 2] * rs, acc[tm][tn][half * 2 + 1] * rs);
                }
            }
        return;
    }

    // ---- hop: enc x5 (ping-pong W; stage next during current mma) ----
    for (int j = 0; j < 5; j++) {
        int cb = (j & 1) ? MS_W1 : MS_W0;
        int nb = (j & 1) ? MS_W0 : MS_W1;
        int nxt = (j < 4) ? (o_enc0 + (j + 1) * 16384) : o_mu;
        stage_w(sb, nb, WH + nxt, 128, 128, tid);
        layer_mma(sb, MS_AH, cb, warp_m, warp_n, lane, 8, acc, 1);
        BAR_GROUP(gbar);
        store_tile(smem, MS_AH, acc, b_enc + j * DL_, 1, warp_m, warp_n, lane);
        CP_WAIT0();
        __syncthreads();
    }
    // ---- mu (W in W1); stage W_std -> W0 during mma ----
    stage_w(sb, MS_W0, WH + o_std, 128, 128, tid);
    layer_mma(sb, MS_AH, MS_W1, warp_m, warp_n, lane, 8, acc, 1);
#pragma unroll
    for (int tn = 0; tn < 4; tn++) {
        int c = warp_n + tn * 8 + (lane & 3) * 2;
        float b0 = __ldg(b_mu + c), b1 = __ldg(b_mu + c + 1);
#pragma unroll
        for (int tm = 0; tm < 2; tm++)
#pragma unroll
            for (int half = 0; half < 2; half++) {
                int r = brow + warp_m + tm * 16 + (lane >> 2) + half * 8;
                if (r >= M) continue;
                float2 v;
                v.x = acc[tm][tn][half * 2]     + b0;
                v.y = acc[tm][tn][half * 2 + 1] + b1;
                *(float2*)(mu_out + (size_t)r * DL_ + c) = v;
            }
    }
    CP_WAIT0();
    __syncthreads();
    // ---- std (W in W0); stage next (gcn | Wd0a) -> W1 during mma ----
    if (mode == 1) stage_w(sb, MS_W1, WH + o_gcn, 128, 128, tid);
    else           stage_w(sb, MS_W1, WH + o_wd0, 128, 256, tid);
    layer_mma(sb, MS_AH, MS_W0, warp_m, warp_n, lane, 8, acc, 1);
    BAR_GROUP(gbar);
    // combine: h = mu(global) + softplus(std)*eps -> resident A; std out if last hop
#pragma unroll
    for (int tn = 0; tn < 4; tn++) {
        int c = warp_n + tn * 8 + (lane & 3) * 2;
        float b0 = __ldg(b_std + c), b1 = __ldg(b_std + c + 1);
#pragma unroll
        for (int tm = 0; tm < 2; tm++)
#pragma unroll
            for (int half = 0; half < 2; half++) {
                int r = warp_m + tm * 16 + (lane >> 2) + half * 8;
                int gr = brow + r;
                float s0 = acc[tm][tn][half * 2]     + b0 - 5.0f;
                float s1 = acc[tm][tn][half * 2 + 1] + b1 - 5.0f;
                s0 = (s0 > 20.0f) ? s0 : log1pf(expf(s0));
                s1 = (s1 > 20.0f) ? s1 : log1pf(expf(s1));
                float2 m = make_float2(0.f, 0.f), e = make_float2(0.f, 0.f);
                if (gr < M) {
                    m = *(const float2*)(mu_out + (size_t)gr * DL_ + c);
                    e = *(const float2*)(eps_it + (size_t)gr * DL_ + c);
                }
                float h0 = fmaf(s0, e.x, m.x);
                float h1 = fmaf(s1, e.y, m.y);
                if (mode == 2 && gr < M) {
                    float2 so; so.x = s0; so.y = s1;
                    *(float2*)(std_out + (size_t)gr * DL_ + c) = so;
                }
                *(unsigned*)(smem + MS_AH + r * AST + c * 2) = hpack2(h0, h1);
            }
    }
    CP_WAIT0();
    __syncthreads();

    if (mode == 1) {
        // ---- gcn: u = h @ W_gcn * dinv ----
        layer_mma(sb, MS_AH, MS_W1, warp_m, warp_n, lane, 8, acc, 1);
#pragma unroll
        for (int tm = 0; tm < 2; tm++)
#pragma unroll
            for (int half = 0; half < 2; half++) {
                int r = brow + warp_m + tm * 16 + (lane >> 2) + half * 8;
                if (r >= M) continue;
                float rs = __ldg(dinv + r);
#pragma unroll
                for (int tn = 0; tn < 4; tn++) {
                    int c = warp_n + tn * 8 + (lane & 3) * 2;
                    *(unsigned*)(u_out + (size_t)r * DL_ + c) =
                        hpack2(acc[tm][tn][half * 2] * rs, acc[tm][tn][half * 2 + 1] * rs);
                }
            }
        return;
    }

    // ======== mode 2: fused decoder dec1 = relu(h@Wd0+bd0) [256], dec2 = relu(dec1@Wd1+bd1) ========
    stage_w(sb, MS_W0, WH + o_wd0 + 128, 128, 256, tid);
    layer_mma(sb, MS_AH, MS_W1, warp_m, warp_n, lane, 8, acc, 1);   // dec1a = h@Wd0a
    __syncthreads();
    store_tile(smem, MS_W1, acc, bd0, 2, warp_m, warp_n, lane);     // dec1a -> W1
    CP_WAIT0();
    __syncthreads();
    layer_mma(sb, MS_AH, MS_W0, warp_m, warp_n, lane, 8, acc, 1);   // dec1b = h@Wd0b
    __syncthreads();
    store_tile(smem, MS_AH, acc, bd0 + 128, 2, warp_m, warp_n, lane); // dec1b -> A-tile
    stage_w(sb, MS_W0, WH + o_wd1, 128, 128, tid);                  // Wd1a -> W0
    CP_WAIT0();
    __syncthreads();
    layer_mma(sb, MS_W1, MS_W0, warp_m, warp_n, lane, 8, acc, 1);   // acc = dec1a@Wd1a
    __syncthreads();
    stage_w(sb, MS_W0, WH + o_wd1 + 128 * 128, 128, 128, tid);      // Wd1b -> W0
    CP_WAIT0();
    __syncthreads();
    layer_mma(sb, MS_AH, MS_W0, warp_m, warp_n, lane, 8, acc, 0);   // acc += dec1b@Wd1b
    // epilogue: u = relu(acc + bd1) -> global (fp16)
#pragma unroll
    for (int tn = 0; tn < 4; tn++) {
        int c = warp_n + tn * 8 + (lane & 3) * 2;
        float b0 = __ldg(bd1 + c), b1 = __ldg(bd1 + c + 1);
#pragma unroll
        for (int tm = 0; tm < 2; tm++)
#pragma unroll
            for (int half = 0; half < 2; half++) {
                int r = brow + warp_m + tm * 16 + (lane >> 2) + half * 8;
                if (r >= M) continue;
                *(unsigned*)(u_out + (size_t)r * DL_ + c) =
                    hpack2(fmaxf(acc[tm][tn][half * 2] + b0, 0.0f),
                           fmaxf(acc[tm][tn][half * 2 + 1] + b1, 0.0f));
            }
    }
}

// ---------------- fused decoder tail: [N,128]fp16 -> 64 -> 32 -> 16 -> 10 -> sigmoid -> pool ------
__global__ __launch_bounds__(128)
void decoder_tail_kernel(const unsigned short* __restrict__ din,
                         const float* __restrict__ W2, const float* __restrict__ b2,
                         const float* __restrict__ W3, const float* __restrict__ b3,
                         const float* __restrict__ W4, const float* __restrict__ b4,
                         const float* __restrict__ Wo, const float* __restrict__ bo,
                         const int* __restrict__ batch, float* __restrict__ sums, int M) {
    __shared__ float w2[128 * 64];
    __shared__ float w3[64 * 32];
    __shared__ float w4[32 * 16];
    __shared__ float wo[160];
    __shared__ float xs [4][128];
    __shared__ float t64[4][64];
    __shared__ float t32[4][32];
    __shared__ float t16[4][16];
    for (int i = threadIdx.x; i < 128 * 64; i += 128) w2[i] = W2[i];
    for (int i = threadIdx.x; i < 64 * 32;  i += 128) w3[i] = W3[i];
    for (int i = threadIdx.x; i < 32 * 16;  i += 128) w4[i] = W4[i];
    for (int i = threadIdx.x; i < 160;      i += 128) wo[i] = Wo[i];
    __syncthreads();
    int warp = threadIdx.x >> 5;
    int lane = threadIdx.x & 31;
    int stride = gridDim.x * 4;
    for (int row = blockIdx.x * 4 + warp; row < M; row += stride) {
        uint2 uv = __ldg((const uint2*)(din + (size_t)row * 128) + lane);
        float f0, f1, f2, f3;
        hunpack2(uv.x, f0, f1);
        hunpack2(uv.y, f2, f3);
        xs[warp][lane * 4 + 0] = f0;
        xs[warp][lane * 4 + 1] = f1;
        xs[warp][lane * 4 + 2] = f2;
        xs[warp][lane * 4 + 3] = f3;
        __syncwarp();
        float s0 = b2[lane], s1 = b2[lane + 32];
#pragma unroll 8
        for (int k = 0; k < 128; k++) {
            float xv = xs[warp][k];
            s0 = fmaf(xv, w2[k * 64 + lane],      s0);
            s1 = fmaf(xv, w2[k * 64 + lane + 32], s1);
        }
        t64[warp][lane]      = fmaxf(s0, 0.0f);
        t64[warp][lane + 32] = fmaxf(s1, 0.0f);
        __syncwarp();
        float s = b3[lane];
#pragma unroll 8
        for (int k = 0; k < 64; k++) s = fmaf(t64[warp][k], w3[k * 32 + lane], s);
        t32[warp][lane] = fmaxf(s, 0.0f);
        __syncwarp();
        if (lane < 16) {
            float t = b4[lane];
#pragma unroll
            for (int k = 0; k < 32; k++) t = fmaf(t32[warp][k], w4[k * 16 + lane], t);
            t16[warp][lane] = fmaxf(t, 0.0f);
        }
        __syncwarp();
        if (lane < 10) {
            float t = bo[lane];
#pragma unroll
            for (int k = 0; k < 16; k++) t = fmaf(t16[warp][k], wo[k * 10 + lane], t);
            float yp = __fdividef(1.0f, 1.0f + __expf(-t));
            atomicAdd(&sums[batch[row] * 10 + lane], yp);
        }
        __syncwarp();
    }
}

__global__ void pool_finalize_kernel(const float* __restrict__ sums, const float* __restrict__ cnt,
                                     const float* __restrict__ y,
                                     float* __restrict__ out_pred, float* __restrict__ out_y) {
    int i = blockIdx.x * blockDim.x + threadIdx.x;
    if (i < GG * DOUT_) {
        out_pred[i] = sums[i] / fmaxf(cnt[i / DOUT_], 1.0f);
        out_y[i]    = y[i];
    }
}

// ---------------- launch ----------------
extern "C" void kernel_launch(void* const* d_in, const int* in_sizes, int n_in,
                              void* d_out, int out_size) {
    const float* x     = (const float*)d_in[0];
    const int*   ei    = (const int*)  d_in[1];
    const int*   batch = (const int*)  d_in[2];
    const float* y     = (const float*)d_in[3];
    const float* eps   = (const float*)d_in[4];
    const float* W_in  = (const float*)d_in[5];
    const float* b_in  = (const float*)d_in[6];
    const float* W_gcn = (const float*)d_in[7];
    const float* b_gcn = (const float*)d_in[8];
    const float* W_enc = (const float*)d_in[9];
    const float* b_enc = (const float*)d_in[10];
    const float* W_mu  = (const float*)d_in[11];
    const float* b_mu  = (const float*)d_in[12];
    const float* W_std = (const float*)d_in[13];
    const float* b_std = (const float*)d_in[14];
    const float* Wd0 = (const float*)d_in[15]; const float* bd0 = (const float*)d_in[16];
    const float* Wd1 = (const float*)d_in[17]; const float* bd1 = (const float*)d_in[18];
    const float* Wd2 = (const float*)d_in[19]; const float* bd2 = (const float*)d_in[20];
    const float* Wd3 = (const float*)d_in[21]; const float* bd3 = (const float*)d_in[22];
    const float* Wd4 = (const float*)d_in[23]; const float* bd4 = (const float*)d_in[24];
    const float* Wo  = (const float*)d_in[25]; const float* bo  = (const float*)d_in[26];

    float *dinv, *sums, *cnt;
    int *deg, *off, *cur, *csr;
    unsigned short *wh, *u16;
    cudaGetSymbolAddress((void**)&u16,  g_u16);
    cudaGetSymbolAddress((void**)&dinv, g_dinv);
    cudaGetSymbolAddress((void**)&deg,  g_deg);
    cudaGetSymbolAddress((void**)&off,  g_off);
    cudaGetSymbolAddress((void**)&cur,  g_cur);
    cudaGetSymbolAddress((void**)&csr,  g_csr);
    cudaGetSymbolAddress((void**)&sums, g_sums);
    cudaGetSymbolAddress((void**)&cnt,  g_cnt);
    cudaGetSymbolAddress((void**)&wh,   g_wh);

    float* out      = (float*)d_out;
    float* out_pred = out;
    float* out_mu   = out + GG * DOUT_;
    float* out_std  = out + GG * DOUT_ + (size_t)NN * DL_;
    float* out_y    = out + GG * DOUT_ + (size_t)2 * NN * DL_;

    const int* src = ei;
    const int* dst = ei + EE;

    cudaFuncSetAttribute(mega_kernel, cudaFuncAttributeMaxDynamicSharedMemorySize, MEGA_SMEM);

    WJobs jobs;
    int O[11];
    {
        int o = 0;
        auto set = [&](int i, const float* W, int elems) {
            jobs.j[i].W = W; jobs.j[i].elems = elems; jobs.j[i].off = o; O[i] = o; o += elems;
        };
        set(0, W_in, 32 * 128);
        set(1, W_gcn, 128 * 128);
        for (int j = 0; j < 5; j++) set(2 + j, W_enc + (size_t)j * DL_ * DL_, 128 * 128);
        set(7, W_mu, 128 * 128);
        set(8, W_std, 128 * 128);
        set(9, Wd0, 128 * 256);
        set(10, Wd1, 256 * 128);
    }
    const int GRID = (NN + 127) / 128;
    const __half* WH = (const __half*)wh;

    wsplit_kernel<<<dim3(32, 11), 256>>>(jobs, wh);
    cudaMemsetAsync(deg, 0, NN * sizeof(int));
    count_deg_kernel   <<<(EE + 255) / 256, 256>>>(dst, deg, EE);
    scan_offsets_kernel<<<1, 1024>>>(deg, off, cur, dinv, NN);
    mega_kernel<<<GRID, 512, MEGA_SMEM>>>(0, x, nullptr, WH, O[0], b_in, O[1], O[2], b_enc,
                                          O[7], b_mu, O[8], b_std, O[9], bd0, O[10], bd1,
                                          dinv, nullptr, nullptr, nullptr, nullptr,
                                          u16, out_mu, nullptr, NN);
    csr_fill_kernel    <<<(EE + 255) / 256, 256>>>(src, dst, cur, csr, EE);

    for (int it = 0; it < KK; it++) {
        int mode = (it == KK - 1) ? 2 : 1;
        mega_kernel<<<GRID, 512, MEGA_SMEM>>>(mode, nullptr, u16, WH, O[0], b_in, O[1], O[2],
                                              b_enc, O[7], b_mu, O[8], b_std, O[9], bd0,
                                              O[10], bd1,
                                              dinv, eps + (size_t)it * NN * DL_,
                                              off, csr, b_gcn,
                                              u16, out_mu, out_std, NN);
    }

    cudaMemsetAsync(sums, 0, GG * DOUT_ * sizeof(float));
    cudaMemsetAsync(cnt,  0, GG * sizeof(float));
    count_nodes_kernel<<<(NN + 255) / 256, 256>>>(batch, cnt, NN);
    decoder_tail_kernel<<<592, 128>>>(u16, Wd2, bd2, Wd3, bd3, Wd4, bd4, Wo, bo,
                                      batch, sums, NN);
    pool_finalize_kernel<<<(GG * DOUT_ + 255) / 256, 256>>>(sums, cnt, y, out_pred, out_y);

    (void)in_sizes; (void)n_in; (void)out_size;
}

// round 17
// speedup vs baseline: 4.0170x; 1.0241x over previous
#include <cuda_runtime.h>
#include <cuda_fp16.h>
#include <math.h>

#define NN   50000
#define EE   800000
#define DIN_ 32
#define DL_  128
#define DOUT_ 10
#define GG   256
#define KK   3

// ---------------- scratch (device globals) ----------------
__device__ __align__(16) unsigned short g_u16[NN * DL_];   // u as fp16
__device__ __align__(16) float g_dinv[NN];
__device__ __align__(16) int   g_deg [NN];
__device__ __align__(16) int   g_off [NN + 1];
__device__ __align__(16) int   g_cur [NN];
__device__ __align__(16) int   g_csr [EE];
__device__ __align__(16) float g_sums[GG * DOUT_];
__device__ __align__(16) float g_cnt [GG];
__device__ __align__(16) unsigned short g_wh[184320];

// ---------------- asm helpers ----------------
__device__ __forceinline__ unsigned smem_u32(const void* p) {
    unsigned a;
    asm("{ .reg .u64 t; cvta.to.shared.u64 t, %1; cvt.u32.u64 %0, t; }" : "=r"(a) : "l"(p));
    return a;
}
#define CP_ASYNC16(dst_u32, src) \
    asm volatile("cp.async.ca.shared.global [%0], [%1], 16;" :: "r"(dst_u32), "l"(src))
#define CP_COMMIT() asm volatile("cp.async.commit_group;")
#define CP_WAIT0()  asm volatile("cp.async.wait_group 0;")
#define LDSM_X4(r0, r1, r2, r3, addr) \
    asm volatile("ldmatrix.sync.aligned.m8n8.x4.shared.b16 {%0,%1,%2,%3}, [%4];" \
                 : "=r"(r0), "=r"(r1), "=r"(r2), "=r"(r3) : "r"(addr))
#define LDSM_X2T(r0, r1, addr) \
    asm volatile("ldmatrix.sync.aligned.m8n8.x2.trans.shared.b16 {%0,%1}, [%2];" \
                 : "=r"(r0), "=r"(r1) : "r"(addr))
#define MMAF16(c, a0, a1, a2, a3, b0, b1) \
    asm volatile("mma.sync.aligned.m16n8k16.row.col.f32.f16.f16.f32 " \
                 "{%0,%1,%2,%3}, {%4,%5,%6,%7}, {%8,%9}, {%0,%1,%2,%3};" \
                 : "+f"((c)[0]), "+f"((c)[1]), "+f"((c)[2]), "+f"((c)[3]) \
                 : "r"(a0), "r"(a1), "r"(a2), "r"(a3), "r"(b0), "r"(b1))
#define BAR_GROUP(id) asm volatile("bar.sync %0, 128;" :: "r"(id) : "memory")

__device__ __forceinline__ unsigned hpack2(float a, float b) {
    __half2 h = __floats2half2_rn(a, b);
    return *(unsigned*)&h;
}
__device__ __forceinline__ void hunpack2(unsigned u, float& a, float& b) {
    __half2 h = *(__half2*)&u;
    float2 f = __half22float2(h);
    a = f.x; b = f.y;
}

// ===== mega smem geometry: A tile + TWO W buffers (fp16) = 102 KB, 2 CTAs/SM =====
#define AST    272
#define MS_AH  0
#define MS_W0  34816
#define MS_W1  69632
#define MEGA_SMEM 104448

// ---------------- preprocessing ----------------
__global__ void prep_kernel(const int* __restrict__ dst, int* __restrict__ deg,
                            const int* __restrict__ batch, float* __restrict__ cnt,
                            int E, int M) {
    int i = blockIdx.x * blockDim.x + threadIdx.x;
    if (i < E) atomicAdd(&deg[dst[i]], 1);
    if (i < M) atomicAdd(&cnt[batch[i]], 1.0f);
}
__global__ __launch_bounds__(1024)
void scan_offsets_kernel(const int* __restrict__ deg, int* __restrict__ off,
                         int* __restrict__ cursor, float* __restrict__ dinv, int M) {
    __shared__ int part[1024];
    int t = threadIdx.x;
    int chunk = (M + 1023) >> 10;
    int base = t * chunk;
    int s = 0;
    for (int i = 0; i < chunk; i++) { int j = base + i; if (j < M) s += deg[j]; }
    part[t] = s;
    __syncthreads();
    for (int d = 1; d < 1024; d <<= 1) {
        int add = (t >= d) ? part[t - d] : 0;
        __syncthreads();
        part[t] += add;
        __syncthreads();
    }
    int run = part[t] - s;
    for (int i = 0; i < chunk; i++) {
        int j = base + i;
        if (j < M) {
            int dj = deg[j];
            off[j] = run; cursor[j] = run; run += dj;
            dinv[j] = rsqrtf((float)dj + 1.0f);
        }
    }
    if (t == 1023) off[M] = part[1023];
}
__global__ void csr_fill_kernel(const int* __restrict__ src, const int* __restrict__ dst,
                                int* __restrict__ cursor, int* __restrict__ csr, int E) {
    int i = blockIdx.x * blockDim.x + threadIdx.x;
    if (i < E) {
        int p = atomicAdd(&cursor[dst[i]], 1);
        csr[p] = src[i];
    }
}

// ---------------- weight convert (fp16) ----------------
struct WJob { const float* W; int elems; int off; };
struct WJobs { WJob j[11]; };
__global__ void wsplit_kernel(WJobs jobs, unsigned short* __restrict__ wh) {
    WJob jb = jobs.j[blockIdx.y];
    for (int i = blockIdx.x * blockDim.x + threadIdx.x; i < jb.elems;
         i += gridDim.x * blockDim.x) {
        wh[jb.off + i] = __half_as_ushort(__float2half_rn(jb.W[i]));
    }
}

// ===== mega pieces (512 thr, warp 32x32, single fp16 product) =====
__device__ __forceinline__ void stage_w(unsigned sb, int woff, const __half* Wh,
                                        int nrows, int ldb, int tid) {
    int chunks = nrows * 16;
    for (int idx = tid; idx < chunks; idx += 512) {
        int rowb = idx >> 4, cc = idx & 15;
        CP_ASYNC16(sb + woff + rowb * AST + cc * 16,
                   (const char*)(Wh + (size_t)rowb * ldb) + cc * 16);
    }
    CP_COMMIT();
}

// acc (+)= A(sm @ abase) @ W(sm @ woff);  zero=1 clears acc first
__device__ __forceinline__ void layer_mma(unsigned sb, int abase, int woff,
                                          int warp_m, int warp_n, int lane,
                                          int nks, float acc[2][4][4], int zero) {
    if (zero) {
#pragma unroll
        for (int i = 0; i < 2; i++)
#pragma unroll
            for (int j = 0; j < 4; j++)
#pragma unroll
                for (int q = 0; q < 4; q++) acc[i][j][q] = 0.0f;
    }
    const int arow = (lane & 7) + ((lane >> 3) & 1) * 8;
    const int akq  = lane >> 4;
    const int lane16 = lane & 15;
#pragma unroll
    for (int ks = 0; ks < 8; ks++) {
        if (ks >= nks) break;
        unsigned aoff = sb + abase + (warp_m + arow) * AST + (ks * 16 + akq * 8) * 2;
        unsigned boff = sb + woff + (ks * 16 + lane16) * AST + warp_n * 2;
        unsigned Ah[2][4], Bf[4][2];
#pragma unroll
        for (int tm = 0; tm < 2; tm++)
            LDSM_X4(Ah[tm][0], Ah[tm][1], Ah[tm][2], Ah[tm][3], aoff + tm * 16 * AST);
#pragma unroll
        for (int tn = 0; tn < 4; tn++)
            LDSM_X2T(Bf[tn][0], Bf[tn][1], boff + tn * 16);
#pragma unroll
        for (int tm = 0; tm < 2; tm++)
#pragma unroll
            for (int tn = 0; tn < 4; tn++)
                MMAF16(acc[tm][tn], Ah[tm][0], Ah[tm][1], Ah[tm][2], Ah[tm][3],
                       Bf[tn][0], Bf[tn][1]);
    }
}

// act: 0 none, 1 sigmoid, 2 relu; writes fp16 tile at smem base `tbase`
__device__ __forceinline__ void store_tile(char* smem, int tbase, float acc[2][4][4],
                                           const float* __restrict__ bias, int act,
                                           int warp_m, int warp_n, int lane) {
#pragma unroll
    for (int tn = 0; tn < 4; tn++) {
        int c = warp_n + tn * 8 + (lane & 3) * 2;
        float b0 = __ldg(bias + c), b1 = __ldg(bias + c + 1);
#pragma unroll
        for (int tm = 0; tm < 2; tm++)
#pragma unroll
            for (int half = 0; half < 2; half++) {
                int r = warp_m + tm * 16 + (lane >> 2) + half * 8;
                float v0 = acc[tm][tn][half * 2]     + b0;
                float v1 = acc[tm][tn][half * 2 + 1] + b1;
                if (act == 1) {
                    v0 = __fdividef(1.0f, 1.0f + __expf(-v0));
                    v1 = __fdividef(1.0f, 1.0f + __expf(-v1));
                } else if (act == 2) {
                    v0 = fmaxf(v0, 0.0f);
                    v1 = fmaxf(v1, 0.0f);
                }
                *(unsigned*)(smem + tbase + r * AST + c * 2) = hpack2(v0, v1);
            }
    }
}

// mode 0 = input (x -> h -> u); 1 = hop (gather -> ... -> u);
// mode 2 = last hop (gather -> mu,std -> h -> fused decoder dec1,dec2 -> u)
__global__ __launch_bounds__(512, 2)
void mega_kernel(int mode, const float* __restrict__ Xin,
                 const unsigned short* __restrict__ Uin,
                 const __half* __restrict__ WH,
                 int o_first, const float* __restrict__ b_first,
                 int o_gcn, int o_enc0, const float* __restrict__ b_enc,
                 int o_mu, const float* __restrict__ b_mu,
                 int o_std, const float* __restrict__ b_std,
                 int o_wd0, const float* __restrict__ bd0,
                 int o_wd1, const float* __restrict__ bd1,
                 const float* __restrict__ dinv, const float* __restrict__ eps_it,
                 const int* __restrict__ off, const int* __restrict__ csr,
                 const float* __restrict__ bgcn,
                 unsigned short* __restrict__ u_out, float* __restrict__ mu_out,
                 float* __restrict__ std_out, int M) {
    extern __shared__ __align__(16) char smem[];
    const unsigned sb = smem_u32(smem);
    const int tid  = threadIdx.x;
    const int wid  = tid >> 5;
    const int lane = tid & 31;
    const int brow = blockIdx.x * 128;
    const int warp_m = (wid >> 2) * 32;
    const int warp_n = (wid & 3) * 32;
    const int gbar = 1 + (wid >> 2);

    stage_w(sb, MS_W0, WH + ((mode == 0) ? o_first : o_enc0),
            (mode == 0) ? 32 : 128, 128, tid);

    if (mode == 0) {
        int row = tid >> 2;
        int c0 = (tid & 3) * 8;
        bool ok = (brow + row) < M;
        const float* Ar = Xin + (size_t)(brow + row) * DIN_ + c0;
        for (int i4 = 0; i4 < 2; i4++) {
            float4 v = ok ? *(const float4*)(Ar + i4 * 4) : make_float4(0.f, 0.f, 0.f, 0.f);
            int c = c0 + i4 * 4;
            *(uint2*)(smem + MS_AH + row * AST + c * 2) =
                make_uint2(hpack2(v.x, v.y), hpack2(v.z, v.w));
        }
    } else {
        // fused gather staging (u fp16): A[r] = fp16( dinv*(u_self + sum u_nbr) + b_gcn )
        float4 bg = *(const float4*)(bgcn + lane * 4);
        for (int rr = wid; rr < 128; rr += 16) {
            int gr = brow + rr;
            float4 a4 = make_float4(0.f, 0.f, 0.f, 0.f);
            if (gr < M) {
                uint2 us = __ldg((const uint2*)(Uin + (size_t)gr * DL_) + lane);
                hunpack2(us.x, a4.x, a4.y);
                hunpack2(us.y, a4.z, a4.w);
                int e0 = off[gr], e1 = off[gr + 1];
                int deg = e1 - e0;
                for (int base = 0; base < deg; base += 32) {
                    int cnt = min(32, deg - base);
                    int idx = 0;
                    if (base + lane < deg) idx = __ldg(csr + e0 + base + lane);
                    int j = 0;
                    for (; j + 8 <= cnt; j += 8) {
                        uint2 v[8];
#pragma unroll
                        for (int q = 0; q < 8; q++) {
                            int s = __shfl_sync(0xffffffffu, idx, j + q);
                            v[q] = __ldg((const uint2*)(Uin + (size_t)s * DL_) + lane);
                        }
#pragma unroll
                        for (int q = 0; q < 8; q++) {
                            float f0, f1, f2, f3;
                            hunpack2(v[q].x, f0, f1);
                            hunpack2(v[q].y, f2, f3);
                            a4.x += f0; a4.y += f1; a4.z += f2; a4.w += f3;
                        }
                    }
                    for (; j < cnt; j++) {
                        int s = __shfl_sync(0xffffffffu, idx, j);
                        uint2 vv = __ldg((const uint2*)(Uin + (size_t)s * DL_) + lane);
                        float f0, f1, f2, f3;
                        hunpack2(vv.x, f0, f1);
                        hunpack2(vv.y, f2, f3);
                        a4.x += f0; a4.y += f1; a4.z += f2; a4.w += f3;
                    }
                }
                float dv = __ldg(dinv + gr);
                a4.x = fmaf(dv, a4.x, bg.x);
                a4.y = fmaf(dv, a4.y, bg.y);
                a4.z = fmaf(dv, a4.z, bg.z);
                a4.w = fmaf(dv, a4.w, bg.w);
            }
            *(uint2*)(smem + MS_AH + rr * AST + lane * 8) =
                make_uint2(hpack2(a4.x, a4.y), hpack2(a4.z, a4.w));
        }
    }
    CP_WAIT0();
    __syncthreads();

    float acc[2][4][4];

    if (mode == 0) {
        stage_w(sb, MS_W1, WH + o_gcn, 128, 128, tid);
        layer_mma(sb, MS_AH, MS_W0, warp_m, warp_n, lane, 2, acc, 1);
        BAR_GROUP(gbar);
        store_tile(smem, MS_AH, acc, b_first, 1, warp_m, warp_n, lane);
        CP_WAIT0();
        __syncthreads();
        layer_mma(sb, MS_AH, MS_W1, warp_m, warp_n, lane, 8, acc, 1);
#pragma unroll
        for (int tm = 0; tm < 2; tm++)
#pragma unroll
            for (int half = 0; half < 2; half++) {
                int r = brow + warp_m + tm * 16 + (lane >> 2) + half * 8;
                if (r >= M) continue;
                float rs = __ldg(dinv + r);
#pragma unroll
                for (int tn = 0; tn < 4; tn++) {
                    int c = warp_n + tn * 8 + (lane & 3) * 2;
                    *(unsigned*)(u_out + (size_t)r * DL_ + c) =
                        hpack2(acc[tm][tn][half * 2] * rs, acc[tm][tn][half * 2 + 1] * rs);
                }
            }
        return;
    }

    // ---- hop: enc x5 (ping-pong W; stage next during current mma) ----
    for (int j = 0; j < 5; j++) {
        int cb = (j & 1) ? MS_W1 : MS_W0;
        int nb = (j & 1) ? MS_W0 : MS_W1;
        int nxt = (j < 4) ? (o_enc0 + (j + 1) * 16384) : o_mu;
        stage_w(sb, nb, WH + nxt, 128, 128, tid);
        layer_mma(sb, MS_AH, cb, warp_m, warp_n, lane, 8, acc, 1);
        BAR_GROUP(gbar);
        store_tile(smem, MS_AH, acc, b_enc + j * DL_, 1, warp_m, warp_n, lane);
        CP_WAIT0();
        __syncthreads();
    }
    // ---- mu (W_mu in W1); stage W_std -> W0 during mma ----
    stage_w(sb, MS_W0, WH + o_std, 128, 128, tid);
    layer_mma(sb, MS_AH, MS_W1, warp_m, warp_n, lane, 8, acc, 1);
    __syncthreads();                 // all readers of W1 (W_mu) done
    // park mu (+bias) fp16 in W1; mode2 additionally writes fp32 mu to global
    store_tile(smem, MS_W1, acc, b_mu, 0, warp_m, warp_n, lane);
    if (mode == 2) {
#pragma unroll
        for (int tn = 0; tn < 4; tn++) {
            int c = warp_n + tn * 8 + (lane & 3) * 2;
            float b0 = __ldg(b_mu + c), b1 = __ldg(b_mu + c + 1);
#pragma unroll
            for (int tm = 0; tm < 2; tm++)
#pragma unroll
                for (int half = 0; half < 2; half++) {
                    int r = brow + warp_m + tm * 16 + (lane >> 2) + half * 8;
                    if (r >= M) continue;
                    float2 v;
                    v.x = acc[tm][tn][half * 2]     + b0;
                    v.y = acc[tm][tn][half * 2 + 1] + b1;
                    *(float2*)(mu_out + (size_t)r * DL_ + c) = v;
                }
        }
    }
    CP_WAIT0();                      // W_std landed
    __syncthreads();
    // ---- std (W in W0) ----
    layer_mma(sb, MS_AH, MS_W0, warp_m, warp_n, lane, 8, acc, 1);
    __syncthreads();                 // all readers of W0 + A done
    // stage next (gcn | Wd0a) -> W0, overlapped with combine math
    if (mode == 1) stage_w(sb, MS_W0, WH + o_gcn, 128, 128, tid);
    else           stage_w(sb, MS_W0, WH + o_wd0, 128, 256, tid);
    // combine: h = mu(smem fp16) + softplus(std)*eps -> resident A; std out if mode2
#pragma unroll
    for (int tn = 0; tn < 4; tn++) {
        int c = warp_n + tn * 8 + (lane & 3) * 2;
        float b0 = __ldg(b_std + c), b1 = __ldg(b_std + c + 1);
#pragma unroll
        for (int tm = 0; tm < 2; tm++)
#pragma unroll
            for (int half = 0; half < 2; half++) {
                int r = warp_m + tm * 16 + (lane >> 2) + half * 8;
                int gr = brow + r;
                float s0 = acc[tm][tn][half * 2]     + b0 - 5.0f;
                float s1 = acc[tm][tn][half * 2 + 1] + b1 - 5.0f;
                s0 = (s0 > 20.0f) ? s0 : log1pf(expf(s0));
                s1 = (s1 > 20.0f) ? s1 : log1pf(expf(s1));
                float m0, m1;
                hunpack2(*(unsigned*)(smem + MS_W1 + r * AST + c * 2), m0, m1);
                float2 e = make_float2(0.f, 0.f);
                if (gr < M) e = *(const float2*)(eps_it + (size_t)gr * DL_ + c);
                float h0 = fmaf(s0, e.x, m0);
                float h1 = fmaf(s1, e.y, m1);
                if (mode == 2 && gr < M) {
                    float2 so; so.x = s0; so.y = s1;
                    *(float2*)(std_out + (size_t)gr * DL_ + c) = so;
                }
                *(unsigned*)(smem + MS_AH + r * AST + c * 2) = hpack2(h0, h1);
            }
    }
    CP_WAIT0();
    __syncthreads();

    if (mode == 1) {
        // ---- gcn: u = h @ W_gcn * dinv ----
        layer_mma(sb, MS_AH, MS_W0, warp_m, warp_n, lane, 8, acc, 1);
#pragma unroll
        for (int tm = 0; tm < 2; tm++)
#pragma unroll
            for (int half = 0; half < 2; half++) {
                int r = brow + warp_m + tm * 16 + (lane >> 2) + half * 8;
                if (r >= M) continue;
                float rs = __ldg(dinv + r);
#pragma unroll
                for (int tn = 0; tn < 4; tn++) {
                    int c = warp_n + tn * 8 + (lane & 3) * 2;
                    *(unsigned*)(u_out + (size_t)r * DL_ + c) =
                        hpack2(acc[tm][tn][half * 2] * rs, acc[tm][tn][half * 2 + 1] * rs);
                }
            }
        return;
    }

    // ======== mode 2 fused decoder (h in A, Wd0a in W0) ========
    stage_w(sb, MS_W1, WH + o_wd0 + 128, 128, 256, tid);            // Wd0b -> W1 (mu dead)
    layer_mma(sb, MS_AH, MS_W0, warp_m, warp_n, lane, 8, acc, 1);   // dec1a = h@Wd0a
    __syncthreads();                                                // W0 readers done
    store_tile(smem, MS_W0, acc, bd0, 2, warp_m, warp_n, lane);     // dec1a -> W0
    CP_WAIT0();                                                     // Wd0b landed
    __syncthreads();
    layer_mma(sb, MS_AH, MS_W1, warp_m, warp_n, lane, 8, acc, 1);   // dec1b = h@Wd0b
    __syncthreads();                                                // A + W1 readers done
    store_tile(smem, MS_AH, acc, bd0 + 128, 2, warp_m, warp_n, lane); // dec1b -> A
    stage_w(sb, MS_W1, WH + o_wd1, 128, 128, tid);                  // Wd1a -> W1
    CP_WAIT0();
    __syncthreads();
    layer_mma(sb, MS_W0, MS_W1, warp_m, warp_n, lane, 8, acc, 1);   // acc = dec1a@Wd1a
    __syncthreads();                                                // W1 readers done
    stage_w(sb, MS_W1, WH + o_wd1 + 128 * 128, 128, 128, tid);      // Wd1b -> W1
    CP_WAIT0();
    __syncthreads();
    layer_mma(sb, MS_AH, MS_W1, warp_m, warp_n, lane, 8, acc, 0);   // acc += dec1b@Wd1b
    // epilogue: u = relu(acc + bd1) -> global (fp16)
#pragma unroll
    for (int tn = 0; tn < 4; tn++) {
        int c = warp_n + tn * 8 + (lane & 3) * 2;
        float b0 = __ldg(bd1 + c), b1 = __ldg(bd1 + c + 1);
#pragma unroll
        for (int tm = 0; tm < 2; tm++)
#pragma unroll
            for (int half = 0; half < 2; half++) {
                int r = brow + warp_m + tm * 16 + (lane >> 2) + half * 8;
                if (r >= M) continue;
                *(unsigned*)(u_out + (size_t)r * DL_ + c) =
                    hpack2(fmaxf(acc[tm][tn][half * 2] + b0, 0.0f),
                           fmaxf(acc[tm][tn][half * 2 + 1] + b1, 0.0f));
            }
    }
}

// ---------------- fused decoder tail: [N,128]fp16 -> 64 -> 32 -> 16 -> 10 -> sigmoid -> pool ------
__global__ __launch_bounds__(128)
void decoder_tail_kernel(const unsigned short* __restrict__ din,
                         const float* __restrict__ W2, const float* __restrict__ b2,
                         const float* __restrict__ W3, const float* __restrict__ b3,
                         const float* __restrict__ W4, const float* __restrict__ b4,
                         const float* __restrict__ Wo, const float* __restrict__ bo,
                         const int* __restrict__ batch, float* __restrict__ sums, int M) {
    __shared__ float w2[128 * 64];
    __shared__ float w3[64 * 32];
    __shared__ float w4[32 * 16];
    __shared__ float wo[160];
    __shared__ float xs [4][128];
    __shared__ float t64[4][64];
    __shared__ float t32[4][32];
    __shared__ float t16[4][16];
    for (int i = threadIdx.x; i < 128 * 64; i += 128) w2[i] = W2[i];
    for (int i = threadIdx.x; i < 64 * 32;  i += 128) w3[i] = W3[i];
    for (int i = threadIdx.x; i < 32 * 16;  i += 128) w4[i] = W4[i];
    for (int i = threadIdx.x; i < 160;      i += 128) wo[i] = Wo[i];
    __syncthreads();
    int warp = threadIdx.x >> 5;
    int lane = threadIdx.x & 31;
    int stride = gridDim.x * 4;
    for (int row = blockIdx.x * 4 + warp; row < M; row += stride) {
        uint2 uv = __ldg((const uint2*)(din + (size_t)row * 128) + lane);
        float f0, f1, f2, f3;
        hunpack2(uv.x, f0, f1);
        hunpack2(uv.y, f2, f3);
        xs[warp][lane * 4 + 0] = f0;
        xs[warp][lane * 4 + 1] = f1;
        xs[warp][lane * 4 + 2] = f2;
        xs[warp][lane * 4 + 3] = f3;
        __syncwarp();
        float s0 = b2[lane], s1 = b2[lane + 32];
#pragma unroll 8
        for (int k = 0; k < 128; k++) {
            float xv = xs[warp][k];
            s0 = fmaf(xv, w2[k * 64 + lane],      s0);
            s1 = fmaf(xv, w2[k * 64 + lane + 32], s1);
        }
        t64[warp][lane]      = fmaxf(s0, 0.0f);
        t64[warp][lane + 32] = fmaxf(s1, 0.0f);
        __syncwarp();
        float s = b3[lane];
#pragma unroll 8
        for (int k = 0; k < 64; k++) s = fmaf(t64[warp][k], w3[k * 32 + lane], s);
        t32[warp][lane] = fmaxf(s, 0.0f);
        __syncwarp();
        if (lane < 16) {
            float t = b4[lane];
#pragma unroll
            for (int k = 0; k < 32; k++) t = fmaf(t32[warp][k], w4[k * 16 + lane], t);
            t16[warp][lane] = fmaxf(t, 0.0f);
        }
        __syncwarp();
        if (lane < 10) {
            float t = bo[lane];
#pragma unroll
            for (int k = 0; k < 16; k++) t = fmaf(t16[warp][k], wo[k * 10 + lane], t);
            float yp = __fdividef(1.0f, 1.0f + __expf(-t));
            atomicAdd(&sums[batch[row] * 10 + lane], yp);
        }
        __syncwarp();
    }
}

__global__ void pool_finalize_kernel(const float* __restrict__ sums, const float* __restrict__ cnt,
                                     const float* __restrict__ y,
                                     float* __restrict__ out_pred, float* __restrict__ out_y) {
    int i = blockIdx.x * blockDim.x + threadIdx.x;
    if (i < GG * DOUT_) {
        out_pred[i] = sums[i] / fmaxf(cnt[i / DOUT_], 1.0f);
        out_y[i]    = y[i];
    }
}

// ---------------- launch ----------------
extern "C" void kernel_launch(void* const* d_in, const int* in_sizes, int n_in,
                              void* d_out, int out_size) {
    const float* x     = (const float*)d_in[0];
    const int*   ei    = (const int*)  d_in[1];
    const int*   batch = (const int*)  d_in[2];
    const float* y     = (const float*)d_in[3];
    const float* eps   = (const float*)d_in[4];
    const float* W_in  = (const float*)d_in[5];
    const float* b_in  = (const float*)d_in[6];
    const float* W_gcn = (const float*)d_in[7];
    const float* b_gcn = (const float*)d_in[8];
    const float* W_enc = (const float*)d_in[9];
    const float* b_enc = (const float*)d_in[10];
    const float* W_mu  = (const float*)d_in[11];
    const float* b_mu  = (const float*)d_in[12];
    const float* W_std = (const float*)d_in[13];
    const float* b_std = (const float*)d_in[14];
    const float* Wd0 = (const float*)d_in[15]; const float* bd0 = (const float*)d_in[16];
    const float* Wd1 = (const float*)d_in[17]; const float* bd1 = (const float*)d_in[18];
    const float* Wd2 = (const float*)d_in[19]; const float* bd2 = (const float*)d_in[20];
    const float* Wd3 = (const float*)d_in[21]; const float* bd3 = (const float*)d_in[22];
    const float* Wd4 = (const float*)d_in[23]; const float* bd4 = (const float*)d_in[24];
    const float* Wo  = (const float*)d_in[25]; const float* bo  = (const float*)d_in[26];

    float *dinv, *sums, *cnt;
    int *deg, *off, *cur, *csr;
    unsigned short *wh, *u16;
    cudaGetSymbolAddress((void**)&u16,  g_u16);
    cudaGetSymbolAddress((void**)&dinv, g_dinv);
    cudaGetSymbolAddress((void**)&deg,  g_deg);
    cudaGetSymbolAddress((void**)&off,  g_off);
    cudaGetSymbolAddress((void**)&cur,  g_cur);
    cudaGetSymbolAddress((void**)&csr,  g_csr);
    cudaGetSymbolAddress((void**)&sums, g_sums);
    cudaGetSymbolAddress((void**)&cnt,  g_cnt);
    cudaGetSymbolAddress((void**)&wh,   g_wh);

    float* out      = (float*)d_out;
    float* out_pred = out;
    float* out_mu   = out + GG * DOUT_;
    float* out_std  = out + GG * DOUT_ + (size_t)NN * DL_;
    float* out_y    = out + GG * DOUT_ + (size_t)2 * NN * DL_;

    const int* src = ei;
    const int* dst = ei + EE;

    cudaFuncSetAttribute(mega_kernel, cudaFuncAttributeMaxDynamicSharedMemorySize, MEGA_SMEM);

    WJobs jobs;
    int O[11];
    {
        int o = 0;
        auto set = [&](int i, const float* W, int elems) {
            jobs.j[i].W = W; jobs.j[i].elems = elems; jobs.j[i].off = o; O[i] = o; o += elems;
        };
        set(0, W_in, 32 * 128);
        set(1, W_gcn, 128 * 128);
        for (int j = 0; j < 5; j++) set(2 + j, W_enc + (size_t)j * DL_ * DL_, 128 * 128);
        set(7, W_mu, 128 * 128);
        set(8, W_std, 128 * 128);
        set(9, Wd0, 128 * 256);
        set(10, Wd1, 256 * 128);
    }
    const int GRID = (NN + 127) / 128;
    const __half* WH = (const __half*)wh;

    cudaMemsetAsync(deg,  0, NN * sizeof(int));
    cudaMemsetAsync(sums, 0, GG * DOUT_ * sizeof(float));
    cudaMemsetAsync(cnt,  0, GG * sizeof(float));
    wsplit_kernel<<<dim3(32, 11), 256>>>(jobs, wh);
    prep_kernel  <<<(EE + 255) / 256, 256>>>(dst, deg, batch, cnt, EE, NN);
    scan_offsets_kernel<<<1, 1024>>>(deg, off, cur, dinv, NN);
    mega_kernel<<<GRID, 512, MEGA_SMEM>>>(0, x, nullptr, WH, O[0], b_in, O[1], O[2], b_enc,
                                          O[7], b_mu, O[8], b_std, O[9], bd0, O[10], bd1,
                                          dinv, nullptr, nullptr, nullptr, nullptr,
                                          u16, out_mu, nullptr, NN);
    csr_fill_kernel<<<(EE + 255) / 256, 256>>>(src, dst, cur, csr, EE);

    for (int it = 0; it < KK; it++) {
        int mode = (it == KK - 1) ? 2 : 1;
        mega_kernel<<<GRID, 512, MEGA_SMEM>>>(mode, nullptr, u16, WH, O[0], b_in, O[1], O[2],
                                              b_enc, O[7], b_mu, O[8], b_std, O[9], bd0,
                                              O[10], bd1,
                                              dinv, eps + (size_t)it * NN * DL_,
                                              off, csr, b_gcn,
                                              u16, out_mu, out_std, NN);
    }

    decoder_tail_kernel<<<592, 128>>>(u16, Wd2, bd2, Wd3, bd3, Wd4, bd4, Wo, bo,
                                      batch, sums, NN);
    pool_finalize_kernel<<<(GG * DOUT_ + 255) / 256, 256>>>(sums, cnt, y, out_pred, out_y);

    (void)in_sizes; (void)n_in; (void)out_size;
}